// round 4
// baseline (speedup 1.0000x reference)
#include <cuda_runtime.h>
#include <cuda_bf16.h>
#include <math.h>
#include <stdint.h>

// ---------------- problem constants ----------------
#define BATCH   8
#define CIN     64
#define CDIM    192
#define HDIM    112
#define WDIM    112
#define L       (HDIM*WDIM)          // 12544
#define TKN     (BATCH*L)            // 100352
#define WS      7
#define NWIN    49
#define NH      6
#define HD      32
#define NWTOT   2048
#define KCONV   576

typedef unsigned long long u64;

// ---------------- f32x2 helpers (attention uses FFMA2) ----------------
#define FMA2(d,a,b)    asm("fma.rn.f32x2 %0, %1, %2, %0;" : "+l"(d) : "l"(a), "l"(b))
#define PACK2(d,x)     asm("mov.b64 %0, {%1, %1};" : "=l"(d) : "f"(x))
#define PACK2XY(d,x,y) asm("mov.b64 %0, {%1, %2};" : "=l"(d) : "f"(x), "f"(y))
#define UNPACK2(x,y,d) asm("mov.b64 {%0, %1}, %2;" : "=f"(x), "=f"(y) : "l"(d))

__device__ __forceinline__ uint32_t smem_u32(const void* p) {
    uint32_t a;
    asm("{ .reg .u64 t; cvta.to.shared.u64 t, %1; cvt.u32.u64 %0, t; }" : "=r"(a) : "l"(p));
    return a;
}

// ---------------- warp-MMA primitives (base ISA, works on plain sm_103) ----------------
#define LDMX4(r, addr) \
    asm volatile("ldmatrix.sync.aligned.m8n8.x4.shared.b16 {%0,%1,%2,%3}, [%4];" \
        : "=r"((r)[0]), "=r"((r)[1]), "=r"((r)[2]), "=r"((r)[3]) : "r"(addr))

#define MMA16816(c, a, b0, b1) \
    asm volatile("mma.sync.aligned.m16n8k16.row.col.f32.bf16.bf16.f32 " \
        "{%0,%1,%2,%3}, {%4,%5,%6,%7}, {%8,%9}, {%0,%1,%2,%3};" \
        : "+f"((c)[0]), "+f"((c)[1]), "+f"((c)[2]), "+f"((c)[3]) \
        : "r"((a)[0]), "r"((a)[1]), "r"((a)[2]), "r"((a)[3]), "r"(b0), "r"(b1))

// ---------------- scratch (static device) ----------------
__device__ __nv_bfloat16 g_col[(size_t)TKN*2*KCONV];    // conv A2 [hi(576)|lo(576)]
__device__ __nv_bfloat16 g_ln [(size_t)TKN*2*CDIM];     // LN split [hi|lo]
__device__ __nv_bfloat16 g_ao [(size_t)TKN*2*CDIM];     // attention out split
__device__ __nv_bfloat16 g_m1 [(size_t)TKN*2*4*CDIM];   // fc1 out split
__device__ float g_xt [(size_t)TKN*CDIM];
__device__ float g_qkv[(size_t)TKN*3*CDIM];
__device__ float g_t1 [(size_t)TKN*CDIM];
__device__ float g_t2 [(size_t)TKN*CDIM];
__device__ float g_bias[NH*NWIN*NWIN];
// weight triples [hi|lo|hi], widths 3K
__device__ __nv_bfloat16 g_wconv[CDIM*3*KCONV];
__device__ __nv_bfloat16 g_wqkv [3*CDIM*3*CDIM];
__device__ __nv_bfloat16 g_wap  [CDIM*3*CDIM];
__device__ __nv_bfloat16 g_wfc1 [4*CDIM*3*CDIM];
__device__ __nv_bfloat16 g_wfc2 [CDIM*3*4*CDIM];

// ---------------- split-bf16 HMMA GEMM ----------------
// A2: [M, 2K] bf16 (hi|lo). B3: [N, 3K] bf16 (hi|lo|hi). Effective K chain = 3K.
// CTA tile 128x64, 8 warps (4x2), warp tile 32x32, BK=32, double-buffered smem.
// Smem row stride 40 bf16 (80B) -> ldmatrix conflict-free.
// EPI: 0 bias, 1 bias+residual, 2 bias+GELU.  OSPLIT: emit split-bf16 [hi|lo].
#define SSTRIDE 40
template<int EPI, int OSPLIT>
__global__ __launch_bounds__(256) void mma_gemm(
    const __nv_bfloat16* __restrict__ A2, const __nv_bfloat16* __restrict__ B3,
    const float* __restrict__ bias, const float* __restrict__ res,
    float* __restrict__ Cf, __nv_bfloat16* __restrict__ Cs,
    int N, int K)
{
    __shared__ __align__(16) __nv_bfloat16 As[2][128*SSTRIDE];
    __shared__ __align__(16) __nv_bfloat16 Bs[2][64*SSTRIDE];
    const int t = threadIdx.x, wid = t >> 5, lane = t & 31;
    const int n0 = blockIdx.x * 64, m0 = blockIdx.y * 128;
    const int wm = (wid >> 1) * 32, wn = (wid & 1) * 32;

    float acc[2][4][4];
    #pragma unroll
    for (int i = 0; i < 2; i++)
        #pragma unroll
        for (int j = 0; j < 4; j++)
            #pragma unroll
            for (int l = 0; l < 4; l++) acc[i][j][l] = 0.f;

    const int kc = K >> 5, nc = 3*kc;
    const size_t lda = 2*(size_t)K, ldb = 3*(size_t)K;
    const int lrow = t >> 2, lseg = t & 3;   // loader: 64 rows per pass, 4x16B segs

    // chunk c -> A source column (hi, hi, lo) ; B column = c*32
    auto acol = [&](int c) {
        return (c < kc) ? (c << 5) : (c < 2*kc) ? ((c - kc) << 5) : (K + ((c - 2*kc) << 5));
    };

    // prologue: chunk 0 -> buf 0
    {
        const int ac = acol(0);
        uint4 ra0 = *(const uint4*)(A2 + (size_t)(m0 + lrow)*lda + ac + lseg*8);
        uint4 ra1 = *(const uint4*)(A2 + (size_t)(m0 + 64 + lrow)*lda + ac + lseg*8);
        uint4 rb  = *(const uint4*)(B3 + (size_t)(n0 + lrow)*ldb + lseg*8);
        *(uint4*)&As[0][lrow*SSTRIDE + lseg*8]        = ra0;
        *(uint4*)&As[0][(64 + lrow)*SSTRIDE + lseg*8] = ra1;
        *(uint4*)&Bs[0][lrow*SSTRIDE + lseg*8]        = rb;
    }
    __syncthreads();

    const uint32_t aS0 = smem_u32(&As[0][0]), bS0 = smem_u32(&Bs[0][0]);
    const uint32_t aS1 = smem_u32(&As[1][0]), bS1 = smem_u32(&Bs[1][0]);

    for (int c = 0; c < nc; c++) {
        uint4 ra0, ra1, rb;
        if (c + 1 < nc) {
            const int ac = acol(c + 1), bc = (c + 1) << 5;
            ra0 = *(const uint4*)(A2 + (size_t)(m0 + lrow)*lda + ac + lseg*8);
            ra1 = *(const uint4*)(A2 + (size_t)(m0 + 64 + lrow)*lda + ac + lseg*8);
            rb  = *(const uint4*)(B3 + (size_t)(n0 + lrow)*ldb + bc + lseg*8);
        }
        const uint32_t aB = (c & 1) ? aS1 : aS0;
        const uint32_t bB = (c & 1) ? bS1 : bS0;
        #pragma unroll
        for (int ks = 0; ks < 2; ks++) {
            const int kb = ks * 32;   // byte offset of k16 group
            uint32_t afr[2][4], bfr[2][4];
            #pragma unroll
            for (int am = 0; am < 2; am++) {
                uint32_t addr = aB + (uint32_t)((wm + am*16 + (lane & 15)) * (SSTRIDE*2))
                              + kb + ((lane >> 4) << 4);
                LDMX4(afr[am], addr);
            }
            #pragma unroll
            for (int bn = 0; bn < 2; bn++) {
                int mat = lane >> 3, r = lane & 7;
                uint32_t addr = bB + (uint32_t)((wn + bn*16 + ((mat & 2) << 2) + r) * (SSTRIDE*2))
                              + kb + ((mat & 1) << 4);
                LDMX4(bfr[bn], addr);
            }
            #pragma unroll
            for (int am = 0; am < 2; am++)
                #pragma unroll
                for (int nf = 0; nf < 4; nf++)
                    MMA16816(acc[am][nf], afr[am], bfr[nf >> 1][(nf & 1)*2], bfr[nf >> 1][(nf & 1)*2 + 1]);
        }
        if (c + 1 < nc) {
            __nv_bfloat16* Ad = (c & 1) ? As[0] : As[1];
            __nv_bfloat16* Bd = (c & 1) ? Bs[0] : Bs[1];
            *(uint4*)&Ad[lrow*SSTRIDE + lseg*8]        = ra0;
            *(uint4*)&Ad[(64 + lrow)*SSTRIDE + lseg*8] = ra1;
            *(uint4*)&Bd[lrow*SSTRIDE + lseg*8]        = rb;
        }
        __syncthreads();
    }

    // epilogue: fragment layout c0,c1 @ (row, col), c2,c3 @ (row+8, col)
    #pragma unroll
    for (int am = 0; am < 2; am++) {
        #pragma unroll
        for (int nf = 0; nf < 4; nf++) {
            const int row = wm + am*16 + (lane >> 2);
            const int col = wn + nf*8 + ((lane & 3) << 1);
            const int nn = n0 + col;
            const float b0 = bias[nn], b1 = bias[nn + 1];
            #pragma unroll
            for (int h = 0; h < 2; h++) {
                const int m = m0 + row + h*8;
                float o0 = acc[am][nf][h*2]     + b0;
                float o1 = acc[am][nf][h*2 + 1] + b1;
                if (EPI == 1) {
                    float2 rr = *(const float2*)(res + (size_t)m*N + nn);
                    o0 += rr.x; o1 += rr.y;
                }
                if (EPI == 2) {
                    o0 = 0.5f*o0*(1.0f + erff(o0*0.70710678118654752f));
                    o1 = 0.5f*o1*(1.0f + erff(o1*0.70710678118654752f));
                }
                if (OSPLIT) {
                    __nv_bfloat16 h0 = __float2bfloat16(o0), h1 = __float2bfloat16(o1);
                    *(__nv_bfloat162*)(Cs + (size_t)m*(2*(size_t)N) + nn) =
                        __halves2bfloat162(h0, h1);
                    *(__nv_bfloat162*)(Cs + (size_t)m*(2*(size_t)N) + N + nn) =
                        __halves2bfloat162(__float2bfloat16(o0 - __bfloat162float(h0)),
                                           __float2bfloat16(o1 - __bfloat162float(h1)));
                } else {
                    *(float2*)(Cf + (size_t)m*N + nn) = make_float2(o0, o1);
                }
            }
        }
    }
}

// ---------------- weight split: W[N,K] fp32 -> B3[N,3K] = [hi|lo|hi] ----------------
__global__ void wsplit(const float* __restrict__ W, __nv_bfloat16* __restrict__ B3,
                       int N, int K)
{
    int i = blockIdx.x*256 + threadIdx.x;
    if (i >= N*K) return;
    int n = i / K, k = i - n*K;
    float v = W[i];
    __nv_bfloat16 h = __float2bfloat16(v);
    __nv_bfloat16 l = __float2bfloat16(v - __bfloat162float(h));
    size_t b = (size_t)n*3*K;
    B3[b + k] = h; B3[b + K + k] = l; B3[b + 2*K + k] = h;
}

// ---------------- im2col + split ----------------
__global__ void im2col_split(const float* __restrict__ x, __nv_bfloat16* __restrict__ col)
{
    size_t i4 = (size_t)blockIdx.x*256 + threadIdx.x;
    if (i4 >= (size_t)TKN*144) return;
    int m  = (int)(i4 / 144);
    int k0 = (int)(i4 % 144) * 4;
    int b = m / L, hw = m % L, h = hw / WDIM, w = hw % WDIM;
    __nv_bfloat16 hi[4], lo[4];
    #pragma unroll
    for (int u = 0; u < 4; u++) {
        int k = k0 + u, ci = k / 9, rr = k - ci*9, kh = rr / 3, kw = rr - kh*3;
        int ih = h + kh - 1, iw = w + kw - 1;
        float v = (ih >= 0 && ih < HDIM && iw >= 0 && iw < WDIM)
                ? x[((size_t)(b*CIN + ci)*HDIM + ih)*WDIM + iw] : 0.f;
        hi[u] = __float2bfloat16(v);
        lo[u] = __float2bfloat16(v - __bfloat162float(hi[u]));
    }
    __nv_bfloat16* base = col + (size_t)m*(2*KCONV);
    *(uint2*)(base + k0)         = *(uint2*)hi;
    *(uint2*)(base + KCONV + k0) = *(uint2*)lo;
}

// ---------------- rel-pos bias precompute ----------------
__global__ void bias_pre(const float* __restrict__ tab, const int* __restrict__ idx,
                         float* __restrict__ out)
{
    int i = blockIdx.x*256 + threadIdx.x;
    if (i < NH*NWIN*NWIN) {
        int h = i / (NWIN*NWIN), ij = i % (NWIN*NWIN);
        out[i] = tab[idx[ij]*NH + h];
    }
}

// ---------------- LayerNorm + split (warp per token) ----------------
__global__ __launch_bounds__(128) void ln_split(const float* __restrict__ in,
                                                const float* __restrict__ w,
                                                const float* __restrict__ b,
                                                __nv_bfloat16* __restrict__ out)
{
    int warp = (blockIdx.x * blockDim.x + threadIdx.x) >> 5;
    int lane = threadIdx.x & 31;
    if (warp >= TKN) return;
    const float* p = in + (size_t)warp*CDIM;
    float v[6];
    float s = 0.f;
    #pragma unroll
    for (int j = 0; j < 6; j++) { v[j] = p[lane + 32*j]; s += v[j]; }
    #pragma unroll
    for (int o = 16; o > 0; o >>= 1) s += __shfl_xor_sync(0xffffffffu, s, o);
    float mu = s * (1.f/CDIM);
    float q = 0.f;
    #pragma unroll
    for (int j = 0; j < 6; j++) { float dd = v[j]-mu; q += dd*dd; }
    #pragma unroll
    for (int o = 16; o > 0; o >>= 1) q += __shfl_xor_sync(0xffffffffu, q, o);
    float rs = rsqrtf(q * (1.f/CDIM) + 1e-5f);
    __nv_bfloat16* ph = out + (size_t)warp*(2*CDIM);
    __nv_bfloat16* pl = ph + CDIM;
    #pragma unroll
    for (int j = 0; j < 6; j++) {
        int c = lane + 32*j;
        float y = (v[j]-mu)*rs*w[c] + b[c];
        __nv_bfloat16 h = __float2bfloat16(y);
        ph[c] = h;
        pl[c] = __float2bfloat16(y - __bfloat162float(h));
    }
}

// ---------------- window attention (writes split-bf16 output) ----------------
__global__ __launch_bounds__(64) void attn_kernel(const float* __restrict__ qkv,
                                                  const float* __restrict__ biasg,
                                                  __nv_bfloat16* __restrict__ o)
{
    __shared__ float ks[NWIN*HD], vs[NWIN*HD];
    __shared__ float sc[NWIN*NWIN];
    __shared__ int toks[NWIN];
    const int t = threadIdx.x;
    const int wi = blockIdx.x, head = blockIdx.y;
    const int b = wi >> 8, r = wi & 255, wh = r >> 4, ww = r & 15;
    if (t < NWIN) toks[t] = b*L + (wh*WS + t/WS)*WDIM + (ww*WS + t%WS);
    __syncthreads();

    for (int idx = t; idx < NWIN*8; idx += 64) {
        int row = idx >> 3, seg = idx & 7;
        const float4* src = (const float4*)(qkv + (size_t)toks[row]*(3*CDIM) + head*HD);
        *(float4*)&ks[row*HD + seg*4] = src[seg + 48];
        *(float4*)&vs[row*HD + seg*4] = src[seg + 96];
    }
    u64 q2[16];
    if (t < NWIN) {
        const float4* src = (const float4*)(qkv + (size_t)toks[t]*(3*CDIM) + head*HD);
        const float s = 0.17677669529663687f;
        #pragma unroll
        for (int l = 0; l < 8; l++) {
            float4 f = src[l];
            PACK2XY(q2[2*l],   f.x*s, f.y*s);
            PACK2XY(q2[2*l+1], f.z*s, f.w*s);
        }
    }
    __syncthreads();

    if (t < NWIN) {
        u64 z2; { float z = 0.f; PACK2(z2, z); }
        const float* bs = biasg + head*(NWIN*NWIN) + t*NWIN;
        float* row = &sc[t*NWIN];
        for (int j = 0; j < NWIN; j++) {
            u64 a2 = z2;
            #pragma unroll
            for (int d = 0; d < 16; d++)
                FMA2(a2, q2[d], *(const u64*)&ks[j*HD + 2*d]);
            float lo, hi; UNPACK2(lo, hi, a2);
            row[j] = lo + hi + bs[j];
        }
        float mx = -1e30f;
        for (int j = 0; j < NWIN; j++) mx = fmaxf(mx, row[j]);
        float s = 0.f;
        for (int j = 0; j < NWIN; j++) { float e = expf(row[j]-mx); row[j] = e; s += e; }
        float inv = 1.f/s;
        u64 acc2[16];
        #pragma unroll
        for (int d = 0; d < 16; d++) acc2[d] = z2;
        for (int j = 0; j < NWIN; j++) {
            u64 p2; float p = row[j]*inv; PACK2(p2, p);
            #pragma unroll
            for (int d = 0; d < 16; d++)
                FMA2(acc2[d], p2, *(const u64*)&vs[j*HD + 2*d]);
        }
        __nv_bfloat162* ph = (__nv_bfloat162*)(o + (size_t)toks[t]*(2*CDIM) + head*HD);
        __nv_bfloat162* pl = (__nv_bfloat162*)(o + (size_t)toks[t]*(2*CDIM) + CDIM + head*HD);
        #pragma unroll
        for (int l = 0; l < 16; l++) {
            float x0, x1; UNPACK2(x0, x1, acc2[l]);
            __nv_bfloat16 h0 = __float2bfloat16(x0), h1 = __float2bfloat16(x1);
            ph[l] = __halves2bfloat162(h0, h1);
            pl[l] = __halves2bfloat162(__float2bfloat16(x0 - __bfloat162float(h0)),
                                       __float2bfloat16(x1 - __bfloat162float(h1)));
        }
    }
}

// ---------------- final: out[b,c,h,w] = t2[tok,c] + shortcut[tok,c] (transpose) --------
__global__ void out_add(const float* __restrict__ t2, const float* __restrict__ scut,
                        float* __restrict__ out)
{
    __shared__ float tile[32][33];
    const int b   = blockIdx.z;
    const int hw0 = blockIdx.x * 32;
    const int c0  = blockIdx.y * 32;
    const int tx  = threadIdx.x, ty = threadIdx.y;   // (32, 8)
    #pragma unroll
    for (int r = 0; r < 4; r++) {
        int i = r*8 + ty;
        size_t off = (size_t)(b*L + hw0 + i)*CDIM + c0 + tx;
        tile[i][tx] = t2[off] + scut[off];
    }
    __syncthreads();
    #pragma unroll
    for (int r = 0; r < 4; r++) {
        int cy = r*8 + ty;
        out[(size_t)(b*CDIM + c0 + cy)*L + hw0 + tx] = tile[tx][cy];
    }
}

// ---------------- launch ----------------
extern "C" void kernel_launch(void* const* d_in, const int* in_sizes, int n_in,
                              void* d_out, int out_size)
{
    const float* x        = (const float*)d_in[0];
    const float* proj_w   = (const float*)d_in[1];
    const float* proj_b   = (const float*)d_in[2];
    const float* ln1_w    = (const float*)d_in[3];
    const float* ln1_b    = (const float*)d_in[4];
    const float* qkv_w    = (const float*)d_in[5];
    const float* qkv_b    = (const float*)d_in[6];
    const float* rel_tab  = (const float*)d_in[7];
    const float* apw      = (const float*)d_in[8];
    const float* apb      = (const float*)d_in[9];
    const float* ln2_w    = (const float*)d_in[10];
    const float* ln2_b    = (const float*)d_in[11];
    const float* fc1_w    = (const float*)d_in[12];
    const float* fc1_b    = (const float*)d_in[13];
    const float* fc2_w    = (const float*)d_in[14];
    const float* fc2_b    = (const float*)d_in[15];
    const int*   rel_idx  = (const int*)d_in[16];
    float* out = (float*)d_out;

    __nv_bfloat16 *col2, *lnq, *ao2, *m12, *wconv, *wqkv, *wap, *wfc1, *wfc2;
    float *xt, *qkvb, *t1, *t2, *biasp;
    cudaGetSymbolAddress((void**)&col2,  g_col);
    cudaGetSymbolAddress((void**)&lnq,   g_ln);
    cudaGetSymbolAddress((void**)&ao2,   g_ao);
    cudaGetSymbolAddress((void**)&m12,   g_m1);
    cudaGetSymbolAddress((void**)&xt,    g_xt);
    cudaGetSymbolAddress((void**)&qkvb,  g_qkv);
    cudaGetSymbolAddress((void**)&t1,    g_t1);
    cudaGetSymbolAddress((void**)&t2,    g_t2);
    cudaGetSymbolAddress((void**)&biasp, g_bias);
    cudaGetSymbolAddress((void**)&wconv, g_wconv);
    cudaGetSymbolAddress((void**)&wqkv,  g_wqkv);
    cudaGetSymbolAddress((void**)&wap,   g_wap);
    cudaGetSymbolAddress((void**)&wfc1,  g_wfc1);
    cudaGetSymbolAddress((void**)&wfc2,  g_wfc2);

    const int MB = TKN/128;   // 784

    bias_pre<<<57, 256>>>(rel_tab, rel_idx, biasp);
    wsplit<<<(CDIM*KCONV + 255)/256, 256>>>(proj_w, wconv, CDIM, KCONV);
    wsplit<<<(3*CDIM*CDIM + 255)/256, 256>>>(qkv_w, wqkv, 3*CDIM, CDIM);
    wsplit<<<(CDIM*CDIM + 255)/256, 256>>>(apw, wap, CDIM, CDIM);
    wsplit<<<(4*CDIM*CDIM + 255)/256, 256>>>(fc1_w, wfc1, 4*CDIM, CDIM);
    wsplit<<<(CDIM*4*CDIM + 255)/256, 256>>>(fc2_w, wfc2, CDIM, 4*CDIM);

    im2col_split<<<(int)(((size_t)TKN*144 + 255)/256), 256>>>(x, col2);
    // conv: K=576
    mma_gemm<0,0><<<dim3(3, MB), 256>>>(col2, wconv, proj_b, nullptr, xt, nullptr, CDIM, KCONV);
    ln_split<<<TKN/4, 128>>>(xt, ln1_w, ln1_b, lnq);
    // qkv: K=192, N=576
    mma_gemm<0,0><<<dim3(9, MB), 256>>>(lnq, wqkv, qkv_b, nullptr, qkvb, nullptr, 3*CDIM, CDIM);
    attn_kernel<<<dim3(NWTOT, NH), 64>>>(qkvb, biasp, ao2);
    // attn proj + residual(xt): K=192, N=192
    mma_gemm<1,0><<<dim3(3, MB), 256>>>(ao2, wap, apb, xt, t1, nullptr, CDIM, CDIM);
    ln_split<<<TKN/4, 128>>>(t1, ln2_w, ln2_b, lnq);
    // fc1 + GELU -> split out: K=192, N=768
    mma_gemm<2,1><<<dim3(12, MB), 256>>>(lnq, wfc1, fc1_b, nullptr, nullptr, m12, 4*CDIM, CDIM);
    // fc2 + residual(t1): K=768, N=192
    mma_gemm<1,0><<<dim3(3, MB), 256>>>(m12, wfc2, fc2_b, t1, t2, nullptr, CDIM, 4*CDIM);
    out_add<<<dim3(L/32, CDIM/32, BATCH), dim3(32,8)>>>(t2, xt, out);
}

// round 5
// speedup vs baseline: 1.7538x; 1.7538x over previous
#include <cuda_runtime.h>
#include <cuda_bf16.h>
#include <math.h>
#include <stdint.h>

// ---------------- problem constants ----------------
#define BATCH   8
#define CIN     64
#define CDIM    192
#define HDIM    112
#define WDIM    112
#define L       (HDIM*WDIM)          // 12544
#define TKN     (BATCH*L)            // 100352
#define WS      7
#define NWIN    49
#define NH      6
#define HD      32
#define NWTOT   2048
#define KCONV   576

typedef unsigned long long u64;

// ---------------- f32x2 helpers (attention uses FFMA2) ----------------
#define FMA2(d,a,b)    asm("fma.rn.f32x2 %0, %1, %2, %0;" : "+l"(d) : "l"(a), "l"(b))
#define PACK2(d,x)     asm("mov.b64 %0, {%1, %1};" : "=l"(d) : "f"(x))
#define PACK2XY(d,x,y) asm("mov.b64 %0, {%1, %2};" : "=l"(d) : "f"(x), "f"(y))
#define UNPACK2(x,y,d) asm("mov.b64 {%0, %1}, %2;" : "=f"(x), "=f"(y) : "l"(d))

__device__ __forceinline__ uint32_t smem_u32(const void* p) {
    uint32_t a;
    asm("{ .reg .u64 t; cvta.to.shared.u64 t, %1; cvt.u32.u64 %0, t; }" : "=r"(a) : "l"(p));
    return a;
}

// ---------------- warp-MMA + cp.async primitives (base ISA on sm_103) ----------------
#define LDMX4(r, addr) \
    asm volatile("ldmatrix.sync.aligned.m8n8.x4.shared.b16 {%0,%1,%2,%3}, [%4];" \
        : "=r"((r)[0]), "=r"((r)[1]), "=r"((r)[2]), "=r"((r)[3]) : "r"(addr))

#define MMA16816(c, a, b0, b1) \
    asm volatile("mma.sync.aligned.m16n8k16.row.col.f32.bf16.bf16.f32 " \
        "{%0,%1,%2,%3}, {%4,%5,%6,%7}, {%8,%9}, {%0,%1,%2,%3};" \
        : "+f"((c)[0]), "+f"((c)[1]), "+f"((c)[2]), "+f"((c)[3]) \
        : "r"((a)[0]), "r"((a)[1]), "r"((a)[2]), "r"((a)[3]), "r"(b0), "r"(b1))

#define CPA16(dst, src) \
    asm volatile("cp.async.ca.shared.global [%0], [%1], 16;" :: "r"(dst), "l"(src))
#define CPCOMMIT() asm volatile("cp.async.commit_group;" ::: "memory")
#define CPWAIT(n)  asm volatile("cp.async.wait_group %0;" :: "n"(n) : "memory")

// ---------------- scratch (static device) ----------------
__device__ __nv_bfloat16 g_col[(size_t)TKN*2*KCONV];    // conv A2 [hi(576)|lo(576)]
__device__ __nv_bfloat16 g_ln [(size_t)TKN*2*CDIM];     // LN split [hi|lo]
__device__ __nv_bfloat16 g_ao [(size_t)TKN*2*CDIM];     // attention out split
__device__ __nv_bfloat16 g_m1 [(size_t)TKN*2*4*CDIM];   // fc1 out split
__device__ float g_xt [(size_t)TKN*CDIM];
__device__ float g_qkv[(size_t)TKN*3*CDIM];
__device__ float g_t1 [(size_t)TKN*CDIM];
__device__ float g_t2 [(size_t)TKN*CDIM];
__device__ float g_bias[NH*NWIN*NWIN];
// weight layout: per row n, [ (Whi_c | Wlo_c) chunk pairs, c=0..K/32 ) | Whi (K) ]  width 3K
__device__ __nv_bfloat16 g_wconv[CDIM*3*KCONV];
__device__ __nv_bfloat16 g_wqkv [3*CDIM*3*CDIM];
__device__ __nv_bfloat16 g_wap  [CDIM*3*CDIM];
__device__ __nv_bfloat16 g_wfc1 [4*CDIM*3*CDIM];
__device__ __nv_bfloat16 g_wfc2 [CDIM*3*4*CDIM];

// ---------------- split-bf16 HMMA GEMM, BM=128 BN=192 BK=32 ----------------
// A2: [M, 2K] bf16 (hi|lo). B3: interleaved layout above.
// Phase 1 (kc chunks): A-hi chunk × (Whi | Wlo) pair.  Phase 2: A-lo × Whi.
// 8 warps as 2(m) x 4(n); warp tile 64x48. Double-buffered smem via cp.async.
// smem: A buf 128 rows * 80B; B buf 192 rows * 144B.
#define AROWB 80
#define BROWB 144
#define SM_A0 0
#define SM_A1 10240
#define SM_B0 20480
#define SM_B1 48128
#define SMEM_GEMM 75776
template<int EPI, int OSPLIT>
__global__ __launch_bounds__(256) void mma_gemm(
    const __nv_bfloat16* __restrict__ A2, const __nv_bfloat16* __restrict__ B3,
    const float* __restrict__ bias, const float* __restrict__ res,
    float* __restrict__ Cf, __nv_bfloat16* __restrict__ Cs,
    int N, int K)
{
    extern __shared__ __align__(16) char dsm[];
    const uint32_t s0 = smem_u32(dsm);
    const uint32_t sA[2] = { s0 + SM_A0, s0 + SM_A1 };
    const uint32_t sB[2] = { s0 + SM_B0, s0 + SM_B1 };
    const int t = threadIdx.x, wid = t >> 5, lane = t & 31;
    const int n0 = blockIdx.x * 192, m0 = blockIdx.y * 128;
    const int wm = (wid >> 2) * 64, wn = (wid & 3) * 48;
    const int mat = lane >> 3, rr = lane & 7;
    const int kc = K >> 5, nc2 = 2*kc;
    const size_t lda = 2*(size_t)K, ldb = 3*(size_t)K;

    float acc[4][6][4];
    #pragma unroll
    for (int i = 0; i < 4; i++)
        #pragma unroll
        for (int j = 0; j < 6; j++)
            #pragma unroll
            for (int l = 0; l < 4; l++) acc[i][j][l] = 0.f;

    // async load of chunk c into buffer c&1
    auto issue = [&](int c) {
        const int buf = c & 1;
        const int ac = (c < kc) ? (c << 5) : (K + ((c - kc) << 5));
        {   // A: 128 rows x 64B, 2 x 16B per thread
            const int row = t >> 2, seg = t & 3;
            CPA16(sA[buf] + row*AROWB + seg*16,
                  A2 + (size_t)(m0 + row)*lda + ac + seg*8);
            CPA16(sA[buf] + (row + 64)*AROWB + seg*16,
                  A2 + (size_t)(m0 + row + 64)*lda + ac + seg*8);
        }
        if (c < kc) {   // B pair: 192 rows x 128B
            const int bc = c << 6;
            #pragma unroll
            for (int j = 0; j < 6; j++) {
                const int idx = t + 256*j, row = idx >> 3, seg = idx & 7;
                CPA16(sB[buf] + row*BROWB + seg*16,
                      B3 + (size_t)(n0 + row)*ldb + bc + seg*8);
            }
        } else {        // B hi only: 192 rows x 64B
            const int bc = 2*K + ((c - kc) << 5);
            #pragma unroll
            for (int j = 0; j < 3; j++) {
                const int idx = t + 256*j, row = idx >> 2, seg = idx & 3;
                CPA16(sB[buf] + row*BROWB + seg*16,
                      B3 + (size_t)(n0 + row)*ldb + bc + seg*8);
            }
        }
    };

    issue(0); CPCOMMIT();
    for (int c = 0; c < nc2; c++) {
        if (c + 1 < nc2) { issue(c + 1); CPCOMMIT(); CPWAIT(1); }
        else             { CPWAIT(0); }
        __syncthreads();
        const uint32_t aB = sA[c & 1], bB = sB[c & 1];
        const bool p1 = (c < kc);
        #pragma unroll
        for (int ks = 0; ks < 2; ks++) {
            const int kb = ks * 32;
            uint32_t afr[4][4];
            #pragma unroll
            for (int am = 0; am < 4; am++)
                LDMX4(afr[am], aB + (uint32_t)((wm + am*16 + (lane & 15))*AROWB)
                             + kb + ((lane >> 4) << 4));
            uint32_t bf[3][4];
            #pragma unroll
            for (int bn = 0; bn < 3; bn++)
                LDMX4(bf[bn], bB + (uint32_t)((wn + bn*16 + ((mat & 2) << 2) + rr)*BROWB)
                            + kb + ((mat & 1) << 4));
            #pragma unroll
            for (int am = 0; am < 4; am++)
                #pragma unroll
                for (int bn = 0; bn < 3; bn++) {
                    MMA16816(acc[am][bn*2],   afr[am], bf[bn][0], bf[bn][1]);
                    MMA16816(acc[am][bn*2+1], afr[am], bf[bn][2], bf[bn][3]);
                }
            if (p1) {   // Wlo half of the pair (col offset 32 elems = 64B)
                #pragma unroll
                for (int bn = 0; bn < 3; bn++)
                    LDMX4(bf[bn], bB + (uint32_t)((wn + bn*16 + ((mat & 2) << 2) + rr)*BROWB)
                                + 64 + kb + ((mat & 1) << 4));
                #pragma unroll
                for (int am = 0; am < 4; am++)
                    #pragma unroll
                    for (int bn = 0; bn < 3; bn++) {
                        MMA16816(acc[am][bn*2],   afr[am], bf[bn][0], bf[bn][1]);
                        MMA16816(acc[am][bn*2+1], afr[am], bf[bn][2], bf[bn][3]);
                    }
            }
        }
        __syncthreads();
    }

    // epilogue
    #pragma unroll
    for (int am = 0; am < 4; am++) {
        #pragma unroll
        for (int nf = 0; nf < 6; nf++) {
            const int col = wn + nf*8 + ((lane & 3) << 1);
            const int nn = n0 + col;
            const float b0 = bias[nn], b1 = bias[nn + 1];
            #pragma unroll
            for (int h = 0; h < 2; h++) {
                const int m = m0 + wm + am*16 + (lane >> 2) + h*8;
                float o0 = acc[am][nf][h*2]     + b0;
                float o1 = acc[am][nf][h*2 + 1] + b1;
                if (EPI == 1) {
                    float2 rv = *(const float2*)(res + (size_t)m*N + nn);
                    o0 += rv.x; o1 += rv.y;
                }
                if (EPI == 2) {
                    o0 = 0.5f*o0*(1.0f + erff(o0*0.70710678118654752f));
                    o1 = 0.5f*o1*(1.0f + erff(o1*0.70710678118654752f));
                }
                if (OSPLIT) {
                    __nv_bfloat16 h0 = __float2bfloat16(o0), h1 = __float2bfloat16(o1);
                    *(__nv_bfloat162*)(Cs + (size_t)m*(2*(size_t)N) + nn) =
                        __halves2bfloat162(h0, h1);
                    *(__nv_bfloat162*)(Cs + (size_t)m*(2*(size_t)N) + N + nn) =
                        __halves2bfloat162(__float2bfloat16(o0 - __bfloat162float(h0)),
                                           __float2bfloat16(o1 - __bfloat162float(h1)));
                } else {
                    *(float2*)(Cf + (size_t)m*N + nn) = make_float2(o0, o1);
                }
            }
        }
    }
}

// ---------------- weight split -> interleaved layout ----------------
// (n,k): hi -> n*3K + (k>>5)*64 + (k&31);  lo -> ... + 32;  hi -> n*3K + 2K + k
__global__ void wsplit(const float* __restrict__ W, __nv_bfloat16* __restrict__ B3,
                       int N, int K)
{
    int i = blockIdx.x*256 + threadIdx.x;
    if (i >= N*K) return;
    int n = i / K, k = i - n*K;
    float v = W[i];
    __nv_bfloat16 h = __float2bfloat16(v);
    __nv_bfloat16 l = __float2bfloat16(v - __bfloat162float(h));
    size_t b = (size_t)n*3*K;
    int c = k >> 5, p = k & 31;
    B3[b + c*64 + p]      = h;
    B3[b + c*64 + 32 + p] = l;
    B3[b + 2*K + k]       = h;
}

// ---------------- im2col + split ----------------
__global__ void im2col_split(const float* __restrict__ x, __nv_bfloat16* __restrict__ col)
{
    size_t i4 = (size_t)blockIdx.x*256 + threadIdx.x;
    if (i4 >= (size_t)TKN*144) return;
    int m  = (int)(i4 / 144);
    int k0 = (int)(i4 % 144) * 4;
    int b = m / L, hw = m % L, h = hw / WDIM, w = hw % WDIM;
    __nv_bfloat16 hi[4], lo[4];
    #pragma unroll
    for (int u = 0; u < 4; u++) {
        int k = k0 + u, ci = k / 9, rr = k - ci*9, kh = rr / 3, kw = rr - kh*3;
        int ih = h + kh - 1, iw = w + kw - 1;
        float v = (ih >= 0 && ih < HDIM && iw >= 0 && iw < WDIM)
                ? x[((size_t)(b*CIN + ci)*HDIM + ih)*WDIM + iw] : 0.f;
        hi[u] = __float2bfloat16(v);
        lo[u] = __float2bfloat16(v - __bfloat162float(hi[u]));
    }
    __nv_bfloat16* base = col + (size_t)m*(2*KCONV);
    *(uint2*)(base + k0)         = *(uint2*)hi;
    *(uint2*)(base + KCONV + k0) = *(uint2*)lo;
}

// ---------------- rel-pos bias precompute ----------------
__global__ void bias_pre(const float* __restrict__ tab, const int* __restrict__ idx,
                         float* __restrict__ out)
{
    int i = blockIdx.x*256 + threadIdx.x;
    if (i < NH*NWIN*NWIN) {
        int h = i / (NWIN*NWIN), ij = i % (NWIN*NWIN);
        out[i] = tab[idx[ij]*NH + h];
    }
}

// ---------------- LayerNorm + split (warp per token) ----------------
__global__ __launch_bounds__(128) void ln_split(const float* __restrict__ in,
                                                const float* __restrict__ w,
                                                const float* __restrict__ b,
                                                __nv_bfloat16* __restrict__ out)
{
    int warp = (blockIdx.x * blockDim.x + threadIdx.x) >> 5;
    int lane = threadIdx.x & 31;
    if (warp >= TKN) return;
    const float* p = in + (size_t)warp*CDIM;
    float v[6];
    float s = 0.f;
    #pragma unroll
    for (int j = 0; j < 6; j++) { v[j] = p[lane + 32*j]; s += v[j]; }
    #pragma unroll
    for (int o = 16; o > 0; o >>= 1) s += __shfl_xor_sync(0xffffffffu, s, o);
    float mu = s * (1.f/CDIM);
    float q = 0.f;
    #pragma unroll
    for (int j = 0; j < 6; j++) { float dd = v[j]-mu; q += dd*dd; }
    #pragma unroll
    for (int o = 16; o > 0; o >>= 1) q += __shfl_xor_sync(0xffffffffu, q, o);
    float rs = rsqrtf(q * (1.f/CDIM) + 1e-5f);
    __nv_bfloat16* ph = out + (size_t)warp*(2*CDIM);
    __nv_bfloat16* pl = ph + CDIM;
    #pragma unroll
    for (int j = 0; j < 6; j++) {
        int c = lane + 32*j;
        float y = (v[j]-mu)*rs*w[c] + b[c];
        __nv_bfloat16 h = __float2bfloat16(y);
        ph[c] = h;
        pl[c] = __float2bfloat16(y - __bfloat162float(h));
    }
}

// ---------------- window attention (writes split-bf16 output) ----------------
__global__ __launch_bounds__(64) void attn_kernel(const float* __restrict__ qkv,
                                                  const float* __restrict__ biasg,
                                                  __nv_bfloat16* __restrict__ o)
{
    __shared__ float ks[NWIN*HD], vs[NWIN*HD];
    __shared__ float sc[NWIN*NWIN];
    __shared__ int toks[NWIN];
    const int t = threadIdx.x;
    const int wi = blockIdx.x, head = blockIdx.y;
    const int b = wi >> 8, r = wi & 255, wh = r >> 4, ww = r & 15;
    if (t < NWIN) toks[t] = b*L + (wh*WS + t/WS)*WDIM + (ww*WS + t%WS);
    __syncthreads();

    for (int idx = t; idx < NWIN*8; idx += 64) {
        int row = idx >> 3, seg = idx & 7;
        const float4* src = (const float4*)(qkv + (size_t)toks[row]*(3*CDIM) + head*HD);
        *(float4*)&ks[row*HD + seg*4] = src[seg + 48];
        *(float4*)&vs[row*HD + seg*4] = src[seg + 96];
    }
    u64 q2[16];
    if (t < NWIN) {
        const float4* src = (const float4*)(qkv + (size_t)toks[t]*(3*CDIM) + head*HD);
        const float s = 0.17677669529663687f;
        #pragma unroll
        for (int l = 0; l < 8; l++) {
            float4 f = src[l];
            PACK2XY(q2[2*l],   f.x*s, f.y*s);
            PACK2XY(q2[2*l+1], f.z*s, f.w*s);
        }
    }
    __syncthreads();

    if (t < NWIN) {
        u64 z2; { float z = 0.f; PACK2(z2, z); }
        const float* bs = biasg + head*(NWIN*NWIN) + t*NWIN;
        float* row = &sc[t*NWIN];
        for (int j = 0; j < NWIN; j++) {
            u64 a2 = z2;
            #pragma unroll
            for (int d = 0; d < 16; d++)
                FMA2(a2, q2[d], *(const u64*)&ks[j*HD + 2*d]);
            float lo, hi; UNPACK2(lo, hi, a2);
            row[j] = lo + hi + bs[j];
        }
        float mx = -1e30f;
        for (int j = 0; j < NWIN; j++) mx = fmaxf(mx, row[j]);
        float s = 0.f;
        for (int j = 0; j < NWIN; j++) { float e = expf(row[j]-mx); row[j] = e; s += e; }
        float inv = 1.f/s;
        u64 acc2[16];
        #pragma unroll
        for (int d = 0; d < 16; d++) acc2[d] = z2;
        for (int j = 0; j < NWIN; j++) {
            u64 p2; float p = row[j]*inv; PACK2(p2, p);
            #pragma unroll
            for (int d = 0; d < 16; d++)
                FMA2(acc2[d], p2, *(const u64*)&vs[j*HD + 2*d]);
        }
        __nv_bfloat162* ph = (__nv_bfloat162*)(o + (size_t)toks[t]*(2*CDIM) + head*HD);
        __nv_bfloat162* pl = (__nv_bfloat162*)(o + (size_t)toks[t]*(2*CDIM) + CDIM + head*HD);
        #pragma unroll
        for (int l = 0; l < 16; l++) {
            float x0, x1; UNPACK2(x0, x1, acc2[l]);
            __nv_bfloat16 h0 = __float2bfloat16(x0), h1 = __float2bfloat16(x1);
            ph[l] = __halves2bfloat162(h0, h1);
            pl[l] = __halves2bfloat162(__float2bfloat16(x0 - __bfloat162float(h0)),
                                       __float2bfloat16(x1 - __bfloat162float(h1)));
        }
    }
}

// ---------------- final: out[b,c,h,w] = t2[tok,c] + shortcut[tok,c] (transpose) --------
__global__ void out_add(const float* __restrict__ t2, const float* __restrict__ scut,
                        float* __restrict__ out)
{
    __shared__ float tile[32][33];
    const int b   = blockIdx.z;
    const int hw0 = blockIdx.x * 32;
    const int c0  = blockIdx.y * 32;
    const int tx  = threadIdx.x, ty = threadIdx.y;   // (32, 8)
    #pragma unroll
    for (int r = 0; r < 4; r++) {
        int i = r*8 + ty;
        size_t off = (size_t)(b*L + hw0 + i)*CDIM + c0 + tx;
        tile[i][tx] = t2[off] + scut[off];
    }
    __syncthreads();
    #pragma unroll
    for (int r = 0; r < 4; r++) {
        int cy = r*8 + ty;
        out[(size_t)(b*CDIM + c0 + cy)*L + hw0 + tx] = tile[tx][cy];
    }
}

// ---------------- launch ----------------
extern "C" void kernel_launch(void* const* d_in, const int* in_sizes, int n_in,
                              void* d_out, int out_size)
{
    const float* x        = (const float*)d_in[0];
    const float* proj_w   = (const float*)d_in[1];
    const float* proj_b   = (const float*)d_in[2];
    const float* ln1_w    = (const float*)d_in[3];
    const float* ln1_b    = (const float*)d_in[4];
    const float* qkv_w    = (const float*)d_in[5];
    const float* qkv_b    = (const float*)d_in[6];
    const float* rel_tab  = (const float*)d_in[7];
    const float* apw      = (const float*)d_in[8];
    const float* apb      = (const float*)d_in[9];
    const float* ln2_w    = (const float*)d_in[10];
    const float* ln2_b    = (const float*)d_in[11];
    const float* fc1_w    = (const float*)d_in[12];
    const float* fc1_b    = (const float*)d_in[13];
    const float* fc2_w    = (const float*)d_in[14];
    const float* fc2_b    = (const float*)d_in[15];
    const int*   rel_idx  = (const int*)d_in[16];
    float* out = (float*)d_out;

    __nv_bfloat16 *col2, *lnq, *ao2, *m12, *wconv, *wqkv, *wap, *wfc1, *wfc2;
    float *xt, *qkvb, *t1, *t2, *biasp;
    cudaGetSymbolAddress((void**)&col2,  g_col);
    cudaGetSymbolAddress((void**)&lnq,   g_ln);
    cudaGetSymbolAddress((void**)&ao2,   g_ao);
    cudaGetSymbolAddress((void**)&m12,   g_m1);
    cudaGetSymbolAddress((void**)&xt,    g_xt);
    cudaGetSymbolAddress((void**)&qkvb,  g_qkv);
    cudaGetSymbolAddress((void**)&t1,    g_t1);
    cudaGetSymbolAddress((void**)&t2,    g_t2);
    cudaGetSymbolAddress((void**)&biasp, g_bias);
    cudaGetSymbolAddress((void**)&wconv, g_wconv);
    cudaGetSymbolAddress((void**)&wqkv,  g_wqkv);
    cudaGetSymbolAddress((void**)&wap,   g_wap);
    cudaGetSymbolAddress((void**)&wfc1,  g_wfc1);
    cudaGetSymbolAddress((void**)&wfc2,  g_wfc2);

    cudaFuncSetAttribute(mma_gemm<0,0>, cudaFuncAttributeMaxDynamicSharedMemorySize, SMEM_GEMM);
    cudaFuncSetAttribute(mma_gemm<1,0>, cudaFuncAttributeMaxDynamicSharedMemorySize, SMEM_GEMM);
    cudaFuncSetAttribute(mma_gemm<2,1>, cudaFuncAttributeMaxDynamicSharedMemorySize, SMEM_GEMM);

    const int MB = TKN/128;   // 784

    bias_pre<<<57, 256>>>(rel_tab, rel_idx, biasp);
    wsplit<<<(CDIM*KCONV + 255)/256, 256>>>(proj_w, wconv, CDIM, KCONV);
    wsplit<<<(3*CDIM*CDIM + 255)/256, 256>>>(qkv_w, wqkv, 3*CDIM, CDIM);
    wsplit<<<(CDIM*CDIM + 255)/256, 256>>>(apw, wap, CDIM, CDIM);
    wsplit<<<(4*CDIM*CDIM + 255)/256, 256>>>(fc1_w, wfc1, 4*CDIM, CDIM);
    wsplit<<<(CDIM*4*CDIM + 255)/256, 256>>>(fc2_w, wfc2, CDIM, 4*CDIM);

    im2col_split<<<(int)(((size_t)TKN*144 + 255)/256), 256>>>(x, col2);
    // conv: K=576, N=192 (1 col block)
    mma_gemm<0,0><<<dim3(1, MB), 256, SMEM_GEMM>>>(col2, wconv, proj_b, nullptr, xt, nullptr, CDIM, KCONV);
    ln_split<<<TKN/4, 128>>>(xt, ln1_w, ln1_b, lnq);
    // qkv: K=192, N=576 (3 col blocks)
    mma_gemm<0,0><<<dim3(3, MB), 256, SMEM_GEMM>>>(lnq, wqkv, qkv_b, nullptr, qkvb, nullptr, 3*CDIM, CDIM);
    attn_kernel<<<dim3(NWTOT, NH), 64>>>(qkvb, biasp, ao2);
    // attn proj + residual(xt): K=192, N=192
    mma_gemm<1,0><<<dim3(1, MB), 256, SMEM_GEMM>>>(ao2, wap, apb, xt, t1, nullptr, CDIM, CDIM);
    ln_split<<<TKN/4, 128>>>(t1, ln2_w, ln2_b, lnq);
    // fc1 + GELU -> split out: K=192, N=768 (4 col blocks)
    mma_gemm<2,1><<<dim3(4, MB), 256, SMEM_GEMM>>>(lnq, wfc1, fc1_b, nullptr, nullptr, m12, 4*CDIM, CDIM);
    // fc2 + residual(t1): K=768, N=192
    mma_gemm<1,0><<<dim3(1, MB), 256, SMEM_GEMM>>>(m12, wfc2, fc2_b, t1, t2, nullptr, CDIM, 4*CDIM);
    out_add<<<dim3(L/32, CDIM/32, BATCH), dim3(32,8)>>>(t2, xt, out);
}

// round 6
// speedup vs baseline: 1.9237x; 1.0969x over previous
#include <cuda_runtime.h>
#include <cuda_bf16.h>
#include <math.h>
#include <stdint.h>

// ---------------- problem constants ----------------
#define BATCH   8
#define CIN     64
#define CDIM    192
#define HDIM    112
#define WDIM    112
#define L       (HDIM*WDIM)          // 12544
#define TKN     (BATCH*L)            // 100352
#define WS      7
#define NWIN    49
#define NH      6
#define HD      32
#define NWTOT   2048
#define KCONV   576

typedef unsigned long long u64;

// ---------------- f32x2 helpers ----------------
#define FMA2(d,a,b)    asm("fma.rn.f32x2 %0, %1, %2, %0;" : "+l"(d) : "l"(a), "l"(b))
#define PACK2(d,x)     asm("mov.b64 %0, {%1, %1};" : "=l"(d) : "f"(x))
#define PACK2XY(d,x,y) asm("mov.b64 %0, {%1, %2};" : "=l"(d) : "f"(x), "f"(y))
#define UNPACK2(x,y,d) asm("mov.b64 {%0, %1}, %2;" : "=f"(x), "=f"(y) : "l"(d))

union F4U2 { float4 f; u64 u[2]; };

__device__ __forceinline__ uint32_t smem_u32(const void* p) {
    uint32_t a;
    asm("{ .reg .u64 t; cvta.to.shared.u64 t, %1; cvt.u32.u64 %0, t; }" : "=r"(a) : "l"(p));
    return a;
}

// ---------------- warp-MMA + cp.async primitives (base ISA) ----------------
#define LDMX4(r, addr) \
    asm volatile("ldmatrix.sync.aligned.m8n8.x4.shared.b16 {%0,%1,%2,%3}, [%4];" \
        : "=r"((r)[0]), "=r"((r)[1]), "=r"((r)[2]), "=r"((r)[3]) : "r"(addr))

#define MMA16816(c, a, b0, b1) \
    asm volatile("mma.sync.aligned.m16n8k16.row.col.f32.bf16.bf16.f32 " \
        "{%0,%1,%2,%3}, {%4,%5,%6,%7}, {%8,%9}, {%0,%1,%2,%3};" \
        : "+f"((c)[0]), "+f"((c)[1]), "+f"((c)[2]), "+f"((c)[3]) \
        : "r"((a)[0]), "r"((a)[1]), "r"((a)[2]), "r"((a)[3]), "r"(b0), "r"(b1))

#define CPA16(dst, src) \
    asm volatile("cp.async.ca.shared.global [%0], [%1], 16;" :: "r"(dst), "l"(src))
#define CPCOMMIT() asm volatile("cp.async.commit_group;" ::: "memory")
#define CPWAIT(n)  asm volatile("cp.async.wait_group %0;" :: "n"(n) : "memory")

// ---------------- scratch (static device) ----------------
__device__ __nv_bfloat16 g_col[(size_t)TKN*2*KCONV];
__device__ __nv_bfloat16 g_ln [(size_t)TKN*2*CDIM];
__device__ __nv_bfloat16 g_ao [(size_t)TKN*2*CDIM];
__device__ __nv_bfloat16 g_m1 [(size_t)TKN*2*4*CDIM];
__device__ float g_xt [(size_t)TKN*CDIM];
__device__ float g_qkv[(size_t)TKN*3*CDIM];
__device__ float g_t1 [(size_t)TKN*CDIM];
__device__ float g_t2 [(size_t)TKN*CDIM];
__device__ float g_bias[NH*NWIN*NWIN];
__device__ __nv_bfloat16 g_wconv[CDIM*3*KCONV];
__device__ __nv_bfloat16 g_wqkv [3*CDIM*3*CDIM];
__device__ __nv_bfloat16 g_wap  [CDIM*3*CDIM];
__device__ __nv_bfloat16 g_wfc1 [4*CDIM*3*CDIM];
__device__ __nv_bfloat16 g_wfc2 [CDIM*3*4*CDIM];

// ---------------- split-bf16 HMMA GEMM, BM=128 BN=192 BK=32, 3-stage cp.async ------
// A2: [M,2K] bf16 hi|lo. B3 row: [(Whi_c|Wlo_c) pairs (2K)] [Whi (K)].
// Phase1: A-hi x (Whi|Wlo). Phase2: A-lo x Whi.
// EPI: 0 bias->Cf | 2 bias+GELU->split Cs | 3 bias->Cf + LN->split Cs
//      4 bias+res->Cf + LN->split Cs      | 5 bias+res+res2->Cf
#define AROWB  80
#define BROWB  144
#define ASTAGE 10240
#define BSTAGE 27648
#define STG    3
#define SMEM_GEMM (STG*(ASTAGE+BSTAGE))   // 113664
template<int EPI>
__global__ __launch_bounds__(256) void mma_gemm(
    const __nv_bfloat16* __restrict__ A2, const __nv_bfloat16* __restrict__ B3,
    const float* __restrict__ bias, const float* __restrict__ res,
    const float* __restrict__ res2, const float* __restrict__ lnw,
    const float* __restrict__ lnb,
    float* __restrict__ Cf, __nv_bfloat16* __restrict__ Cs,
    int N, int K)
{
    extern __shared__ __align__(16) char dsm[];
    const uint32_t s0 = smem_u32(dsm);
    const int t = threadIdx.x, wid = t >> 5, lane = t & 31;
    const int n0 = blockIdx.x * 192, m0 = blockIdx.y * 128;
    const int wm = (wid >> 2) * 64, wn = (wid & 3) * 48;
    const int mat = lane >> 3, rr = lane & 7;
    const int kc = K >> 5, nc2 = 2*kc;
    const size_t lda = 2*(size_t)K, ldb = 3*(size_t)K;

    float acc[4][6][4];
    #pragma unroll
    for (int i = 0; i < 4; i++)
        #pragma unroll
        for (int j = 0; j < 6; j++)
            #pragma unroll
            for (int l = 0; l < 4; l++) acc[i][j][l] = 0.f;

    auto issue = [&](int c) {
        const int buf = c % STG;
        const uint32_t aS = s0 + buf*ASTAGE;
        const uint32_t bS = s0 + STG*ASTAGE + buf*BSTAGE;
        const int ac = (c < kc) ? (c << 5) : (K + ((c - kc) << 5));
        {
            const int row = t >> 2, seg = t & 3;
            CPA16(aS + row*AROWB + seg*16,
                  A2 + (size_t)(m0 + row)*lda + ac + seg*8);
            CPA16(aS + (row + 64)*AROWB + seg*16,
                  A2 + (size_t)(m0 + row + 64)*lda + ac + seg*8);
        }
        if (c < kc) {
            const int bc = c << 6;
            #pragma unroll
            for (int j = 0; j < 6; j++) {
                const int idx = t + 256*j, row = idx >> 3, seg = idx & 7;
                CPA16(bS + row*BROWB + seg*16,
                      B3 + (size_t)(n0 + row)*ldb + bc + seg*8);
            }
        } else {
            const int bc = 2*K + ((c - kc) << 5);
            #pragma unroll
            for (int j = 0; j < 3; j++) {
                const int idx = t + 256*j, row = idx >> 2, seg = idx & 3;
                CPA16(bS + row*BROWB + seg*16,
                      B3 + (size_t)(n0 + row)*ldb + bc + seg*8);
            }
        }
    };

    issue(0); CPCOMMIT();
    issue(1); CPCOMMIT();
    for (int c = 0; c < nc2; c++) {
        CPWAIT(1);
        __syncthreads();
        if (c + 2 < nc2) issue(c + 2);
        CPCOMMIT();
        const int buf = c % STG;
        const uint32_t aB = s0 + buf*ASTAGE;
        const uint32_t bB = s0 + STG*ASTAGE + buf*BSTAGE;
        const bool p1 = (c < kc);
        #pragma unroll
        for (int ks = 0; ks < 2; ks++) {
            const int kb = ks * 32;
            uint32_t afr[4][4];
            #pragma unroll
            for (int am = 0; am < 4; am++)
                LDMX4(afr[am], aB + (uint32_t)((wm + am*16 + (lane & 15))*AROWB)
                             + kb + ((lane >> 4) << 4));
            uint32_t bf[3][4];
            #pragma unroll
            for (int bn = 0; bn < 3; bn++)
                LDMX4(bf[bn], bB + (uint32_t)((wn + bn*16 + ((mat & 2) << 2) + rr)*BROWB)
                            + kb + ((mat & 1) << 4));
            #pragma unroll
            for (int am = 0; am < 4; am++)
                #pragma unroll
                for (int bn = 0; bn < 3; bn++) {
                    MMA16816(acc[am][bn*2],   afr[am], bf[bn][0], bf[bn][1]);
                    MMA16816(acc[am][bn*2+1], afr[am], bf[bn][2], bf[bn][3]);
                }
            if (p1) {
                #pragma unroll
                for (int bn = 0; bn < 3; bn++)
                    LDMX4(bf[bn], bB + (uint32_t)((wn + bn*16 + ((mat & 2) << 2) + rr)*BROWB)
                                + 64 + kb + ((mat & 1) << 4));
                #pragma unroll
                for (int am = 0; am < 4; am++)
                    #pragma unroll
                    for (int bn = 0; bn < 3; bn++) {
                        MMA16816(acc[am][bn*2],   afr[am], bf[bn][0], bf[bn][1]);
                        MMA16816(acc[am][bn*2+1], afr[am], bf[bn][2], bf[bn][3]);
                    }
            }
        }
    }
    __syncthreads();

    // ---- epilogue pass 1: bias (+residuals), back into acc ----
    float lsum[4][2], lsq[4][2];
    #pragma unroll
    for (int am = 0; am < 4; am++)
        #pragma unroll
        for (int h = 0; h < 2; h++) { lsum[am][h] = 0.f; lsq[am][h] = 0.f; }
    #pragma unroll
    for (int am = 0; am < 4; am++) {
        #pragma unroll
        for (int nf = 0; nf < 6; nf++) {
            const int nn = n0 + wn + nf*8 + ((lane & 3) << 1);
            const float b0 = bias[nn], b1 = bias[nn + 1];
            #pragma unroll
            for (int h = 0; h < 2; h++) {
                const int m = m0 + wm + am*16 + (lane >> 2) + h*8;
                float o0 = acc[am][nf][h*2]     + b0;
                float o1 = acc[am][nf][h*2 + 1] + b1;
                if (EPI == 4 || EPI == 5) {
                    float2 rv = *(const float2*)(res + (size_t)m*N + nn);
                    o0 += rv.x; o1 += rv.y;
                }
                if (EPI == 5) {
                    float2 rv = *(const float2*)(res2 + (size_t)m*N + nn);
                    o0 += rv.x; o1 += rv.y;
                }
                if (EPI == 2) {
                    o0 = 0.5f*o0*(1.0f + erff(o0*0.70710678118654752f));
                    o1 = 0.5f*o1*(1.0f + erff(o1*0.70710678118654752f));
                }
                acc[am][nf][h*2]     = o0;
                acc[am][nf][h*2 + 1] = o1;
                if (EPI == 3 || EPI == 4) {
                    lsum[am][h] += o0 + o1;
                    lsq[am][h]  += o0*o0 + o1*o1;
                }
            }
        }
    }

    float mu[4][2], rs[4][2];
    if (EPI == 3 || EPI == 4) {   // row LayerNorm stats (N==192, full row in CTA)
        float2* red = (float2*)dsm;   // [128][4]
        #pragma unroll
        for (int am = 0; am < 4; am++)
            #pragma unroll
            for (int h = 0; h < 2; h++) {
                #pragma unroll
                for (int ox = 1; ox < 4; ox <<= 1) {
                    lsum[am][h] += __shfl_xor_sync(0xffffffffu, lsum[am][h], ox);
                    lsq[am][h]  += __shfl_xor_sync(0xffffffffu, lsq[am][h], ox);
                }
            }
        if ((lane & 3) == 0) {
            #pragma unroll
            for (int am = 0; am < 4; am++)
                #pragma unroll
                for (int h = 0; h < 2; h++) {
                    int row = wm + am*16 + (lane >> 2) + h*8;
                    red[row*4 + (wid & 3)] = make_float2(lsum[am][h], lsq[am][h]);
                }
        }
        __syncthreads();
        #pragma unroll
        for (int am = 0; am < 4; am++)
            #pragma unroll
            for (int h = 0; h < 2; h++) {
                int row = wm + am*16 + (lane >> 2) + h*8;
                float s = 0.f, q = 0.f;
                #pragma unroll
                for (int w = 0; w < 4; w++) {
                    float2 v = red[row*4 + w];
                    s += v.x; q += v.y;
                }
                float m_ = s * (1.f/192.f);
                float var = q * (1.f/192.f) - m_*m_;
                mu[am][h] = m_;
                rs[am][h] = rsqrtf(var + 1e-5f);
            }
    }

    // ---- epilogue pass 2: writes ----
    #pragma unroll
    for (int am = 0; am < 4; am++) {
        #pragma unroll
        for (int nf = 0; nf < 6; nf++) {
            const int nn = n0 + wn + nf*8 + ((lane & 3) << 1);
            #pragma unroll
            for (int h = 0; h < 2; h++) {
                const int m = m0 + wm + am*16 + (lane >> 2) + h*8;
                const float o0 = acc[am][nf][h*2], o1 = acc[am][nf][h*2 + 1];
                if (EPI == 0 || EPI == 5) {
                    *(float2*)(Cf + (size_t)m*N + nn) = make_float2(o0, o1);
                } else if (EPI == 2) {
                    __nv_bfloat16 h0 = __float2bfloat16(o0), h1 = __float2bfloat16(o1);
                    *(__nv_bfloat162*)(Cs + (size_t)m*(2*(size_t)N) + nn) =
                        __halves2bfloat162(h0, h1);
                    *(__nv_bfloat162*)(Cs + (size_t)m*(2*(size_t)N) + N + nn) =
                        __halves2bfloat162(__float2bfloat16(o0 - __bfloat162float(h0)),
                                           __float2bfloat16(o1 - __bfloat162float(h1)));
                } else {   // EPI 3/4: raw -> Cf, LN-split -> Cs
                    *(float2*)(Cf + (size_t)m*N + nn) = make_float2(o0, o1);
                    float y0 = (o0 - mu[am][h])*rs[am][h]*lnw[nn]     + lnb[nn];
                    float y1 = (o1 - mu[am][h])*rs[am][h]*lnw[nn + 1] + lnb[nn + 1];
                    __nv_bfloat16 h0 = __float2bfloat16(y0), h1 = __float2bfloat16(y1);
                    *(__nv_bfloat162*)(Cs + (size_t)m*(2*(size_t)N) + nn) =
                        __halves2bfloat162(h0, h1);
                    *(__nv_bfloat162*)(Cs + (size_t)m*(2*(size_t)N) + N + nn) =
                        __halves2bfloat162(__float2bfloat16(y0 - __bfloat162float(h0)),
                                           __float2bfloat16(y1 - __bfloat162float(h1)));
                }
            }
        }
    }
}

// ---------------- weight split -> interleaved layout ----------------
__global__ void wsplit(const float* __restrict__ W, __nv_bfloat16* __restrict__ B3,
                       int N, int K)
{
    int i = blockIdx.x*256 + threadIdx.x;
    if (i >= N*K) return;
    int n = i / K, k = i - n*K;
    float v = W[i];
    __nv_bfloat16 h = __float2bfloat16(v);
    __nv_bfloat16 l = __float2bfloat16(v - __bfloat162float(h));
    size_t b = (size_t)n*3*K;
    int c = k >> 5, p = k & 31;
    B3[b + c*64 + p]      = h;
    B3[b + c*64 + 32 + p] = l;
    B3[b + 2*K + k]       = h;
}

// ---------------- im2col + split ----------------
__global__ void im2col_split(const float* __restrict__ x, __nv_bfloat16* __restrict__ col)
{
    size_t i4 = (size_t)blockIdx.x*256 + threadIdx.x;
    if (i4 >= (size_t)TKN*144) return;
    int m  = (int)(i4 / 144);
    int k0 = (int)(i4 % 144) * 4;
    int b = m / L, hw = m % L, h = hw / WDIM, w = hw % WDIM;
    __nv_bfloat16 hi[4], lo[4];
    #pragma unroll
    for (int u = 0; u < 4; u++) {
        int k = k0 + u, ci = k / 9, rq = k - ci*9, kh = rq / 3, kw = rq - kh*3;
        int ih = h + kh - 1, iw = w + kw - 1;
        float v = (ih >= 0 && ih < HDIM && iw >= 0 && iw < WDIM)
                ? x[((size_t)(b*CIN + ci)*HDIM + ih)*WDIM + iw] : 0.f;
        hi[u] = __float2bfloat16(v);
        lo[u] = __float2bfloat16(v - __bfloat162float(hi[u]));
    }
    __nv_bfloat16* base = col + (size_t)m*(2*KCONV);
    *(uint2*)(base + k0)         = *(uint2*)hi;
    *(uint2*)(base + KCONV + k0) = *(uint2*)lo;
}

// ---------------- rel-pos bias precompute ----------------
__global__ void bias_pre(const float* __restrict__ tab, const int* __restrict__ idx,
                         float* __restrict__ out)
{
    int i = blockIdx.x*256 + threadIdx.x;
    if (i < NH*NWIN*NWIN) {
        int h = i / (NWIN*NWIN), ij = i % (NWIN*NWIN);
        out[i] = tab[idx[ij]*NH + h];
    }
}

// ---------------- window attention (LDS.128 inner loops, split-bf16 out) ----------
__global__ __launch_bounds__(64) void attn_kernel(const float* __restrict__ qkv,
                                                  const float* __restrict__ biasg,
                                                  __nv_bfloat16* __restrict__ o)
{
    __shared__ float ks[NWIN*HD], vs[NWIN*HD];
    __shared__ float sc[NWIN*NWIN];
    __shared__ int toks[NWIN];
    const int t = threadIdx.x;
    const int wi = blockIdx.x, head = blockIdx.y;
    const int b = wi >> 8, r = wi & 255, wh = r >> 4, ww = r & 15;
    if (t < NWIN) toks[t] = b*L + (wh*WS + t/WS)*WDIM + (ww*WS + t%WS);
    __syncthreads();

    for (int idx = t; idx < NWIN*8; idx += 64) {
        int row = idx >> 3, seg = idx & 7;
        const float4* src = (const float4*)(qkv + (size_t)toks[row]*(3*CDIM) + head*HD);
        *(float4*)&ks[row*HD + seg*4] = src[seg + 48];
        *(float4*)&vs[row*HD + seg*4] = src[seg + 96];
    }
    u64 q2[16];
    if (t < NWIN) {
        const float4* src = (const float4*)(qkv + (size_t)toks[t]*(3*CDIM) + head*HD);
        const float s = 0.17677669529663687f;
        #pragma unroll
        for (int l = 0; l < 8; l++) {
            float4 f = src[l];
            PACK2XY(q2[2*l],   f.x*s, f.y*s);
            PACK2XY(q2[2*l+1], f.z*s, f.w*s);
        }
    }
    __syncthreads();

    if (t < NWIN) {
        u64 z2; { float z = 0.f; PACK2(z2, z); }
        const float* bs = biasg + head*(NWIN*NWIN) + t*NWIN;
        float* row = &sc[t*NWIN];
        for (int j = 0; j < NWIN; j++) {
            const float4* kp = (const float4*)&ks[j*HD];
            u64 a2 = z2;
            #pragma unroll
            for (int d8 = 0; d8 < 8; d8++) {
                F4U2 kv; kv.f = kp[d8];
                FMA2(a2, q2[2*d8],     kv.u[0]);
                FMA2(a2, q2[2*d8 + 1], kv.u[1]);
            }
            float lo, hi; UNPACK2(lo, hi, a2);
            row[j] = lo + hi + bs[j];
        }
        float mx = -1e30f;
        for (int j = 0; j < NWIN; j++) mx = fmaxf(mx, row[j]);
        float s = 0.f;
        for (int j = 0; j < NWIN; j++) { float e = expf(row[j]-mx); row[j] = e; s += e; }
        float inv = 1.f/s;
        u64 acc2[16];
        #pragma unroll
        for (int d = 0; d < 16; d++) acc2[d] = z2;
        for (int j = 0; j < NWIN; j++) {
            const float4* vp = (const float4*)&vs[j*HD];
            u64 p2; float p = row[j]*inv; PACK2(p2, p);
            #pragma unroll
            for (int d8 = 0; d8 < 8; d8++) {
                F4U2 vv; vv.f = vp[d8];
                FMA2(acc2[2*d8],     p2, vv.u[0]);
                FMA2(acc2[2*d8 + 1], p2, vv.u[1]);
            }
        }
        __nv_bfloat162* ph = (__nv_bfloat162*)(o + (size_t)toks[t]*(2*CDIM) + head*HD);
        __nv_bfloat162* pl = (__nv_bfloat162*)(o + (size_t)toks[t]*(2*CDIM) + CDIM + head*HD);
        #pragma unroll
        for (int l = 0; l < 16; l++) {
            float x0, x1; UNPACK2(x0, x1, acc2[l]);
            __nv_bfloat16 h0 = __float2bfloat16(x0), h1 = __float2bfloat16(x1);
            ph[l] = __halves2bfloat162(h0, h1);
            pl[l] = __halves2bfloat162(__float2bfloat16(x0 - __bfloat162float(h0)),
                                       __float2bfloat16(x1 - __bfloat162float(h1)));
        }
    }
}

// ---------------- final transpose: out[b,c,hw] = t2[tok,c] ----------------
__global__ void out_tr(const float* __restrict__ t2, float* __restrict__ out)
{
    __shared__ float tile[32][33];
    const int b   = blockIdx.z;
    const int hw0 = blockIdx.x * 32;
    const int c0  = blockIdx.y * 32;
    const int tx  = threadIdx.x, ty = threadIdx.y;   // (32, 8)
    #pragma unroll
    for (int r = 0; r < 4; r++) {
        int i = r*8 + ty;
        tile[i][tx] = t2[(size_t)(b*L + hw0 + i)*CDIM + c0 + tx];
    }
    __syncthreads();
    #pragma unroll
    for (int r = 0; r < 4; r++) {
        int cy = r*8 + ty;
        out[(size_t)(b*CDIM + c0 + cy)*L + hw0 + tx] = tile[tx][cy];
    }
}

// ---------------- launch ----------------
extern "C" void kernel_launch(void* const* d_in, const int* in_sizes, int n_in,
                              void* d_out, int out_size)
{
    const float* x        = (const float*)d_in[0];
    const float* proj_w   = (const float*)d_in[1];
    const float* proj_b   = (const float*)d_in[2];
    const float* ln1_w    = (const float*)d_in[3];
    const float* ln1_b    = (const float*)d_in[4];
    const float* qkv_w    = (const float*)d_in[5];
    const float* qkv_b    = (const float*)d_in[6];
    const float* rel_tab  = (const float*)d_in[7];
    const float* apw      = (const float*)d_in[8];
    const float* apb      = (const float*)d_in[9];
    const float* ln2_w    = (const float*)d_in[10];
    const float* ln2_b    = (const float*)d_in[11];
    const float* fc1_w    = (const float*)d_in[12];
    const float* fc1_b    = (const float*)d_in[13];
    const float* fc2_w    = (const float*)d_in[14];
    const float* fc2_b    = (const float*)d_in[15];
    const int*   rel_idx  = (const int*)d_in[16];
    float* out = (float*)d_out;

    __nv_bfloat16 *col2, *lnq, *ao2, *m12, *wconv, *wqkv, *wap, *wfc1, *wfc2;
    float *xt, *qkvb, *t1, *t2, *biasp;
    cudaGetSymbolAddress((void**)&col2,  g_col);
    cudaGetSymbolAddress((void**)&lnq,   g_ln);
    cudaGetSymbolAddress((void**)&ao2,   g_ao);
    cudaGetSymbolAddress((void**)&m12,   g_m1);
    cudaGetSymbolAddress((void**)&xt,    g_xt);
    cudaGetSymbolAddress((void**)&qkvb,  g_qkv);
    cudaGetSymbolAddress((void**)&t1,    g_t1);
    cudaGetSymbolAddress((void**)&t2,    g_t2);
    cudaGetSymbolAddress((void**)&biasp, g_bias);
    cudaGetSymbolAddress((void**)&wconv, g_wconv);
    cudaGetSymbolAddress((void**)&wqkv,  g_wqkv);
    cudaGetSymbolAddress((void**)&wap,   g_wap);
    cudaGetSymbolAddress((void**)&wfc1,  g_wfc1);
    cudaGetSymbolAddress((void**)&wfc2,  g_wfc2);

    cudaFuncSetAttribute(mma_gemm<0>, cudaFuncAttributeMaxDynamicSharedMemorySize, SMEM_GEMM);
    cudaFuncSetAttribute(mma_gemm<2>, cudaFuncAttributeMaxDynamicSharedMemorySize, SMEM_GEMM);
    cudaFuncSetAttribute(mma_gemm<3>, cudaFuncAttributeMaxDynamicSharedMemorySize, SMEM_GEMM);
    cudaFuncSetAttribute(mma_gemm<4>, cudaFuncAttributeMaxDynamicSharedMemorySize, SMEM_GEMM);
    cudaFuncSetAttribute(mma_gemm<5>, cudaFuncAttributeMaxDynamicSharedMemorySize, SMEM_GEMM);

    const int MB = TKN/128;   // 784

    bias_pre<<<57, 256>>>(rel_tab, rel_idx, biasp);
    wsplit<<<(CDIM*KCONV + 255)/256, 256>>>(proj_w, wconv, CDIM, KCONV);
    wsplit<<<(3*CDIM*CDIM + 255)/256, 256>>>(qkv_w, wqkv, 3*CDIM, CDIM);
    wsplit<<<(CDIM*CDIM + 255)/256, 256>>>(apw, wap, CDIM, CDIM);
    wsplit<<<(4*CDIM*CDIM + 255)/256, 256>>>(fc1_w, wfc1, 4*CDIM, CDIM);
    wsplit<<<(CDIM*4*CDIM + 255)/256, 256>>>(fc2_w, wfc2, CDIM, 4*CDIM);

    im2col_split<<<(int)(((size_t)TKN*144 + 255)/256), 256>>>(x, col2);
    // conv + fused LN1: writes xt (fp32) + lnq (split)
    mma_gemm<3><<<dim3(1, MB), 256, SMEM_GEMM>>>(col2, wconv, proj_b, nullptr, nullptr,
                                                 ln1_w, ln1_b, xt, lnq, CDIM, KCONV);
    // qkv
    mma_gemm<0><<<dim3(3, MB), 256, SMEM_GEMM>>>(lnq, wqkv, qkv_b, nullptr, nullptr,
                                                 nullptr, nullptr, qkvb, nullptr, 3*CDIM, CDIM);
    attn_kernel<<<dim3(NWTOT, NH), 64>>>(qkvb, biasp, ao2);
    // attn-proj + residual(xt) + fused LN2: writes t1 + lnq
    mma_gemm<4><<<dim3(1, MB), 256, SMEM_GEMM>>>(ao2, wap, apb, xt, nullptr,
                                                 ln2_w, ln2_b, t1, lnq, CDIM, CDIM);
    // fc1 + GELU -> split
    mma_gemm<2><<<dim3(4, MB), 256, SMEM_GEMM>>>(lnq, wfc1, fc1_b, nullptr, nullptr,
                                                 nullptr, nullptr, nullptr, m12, 4*CDIM, CDIM);
    // fc2 + residual(t1) + shortcut(xt) -> t2
    mma_gemm<5><<<dim3(1, MB), 256, SMEM_GEMM>>>(m12, wfc2, fc2_b, t1, xt,
                                                 nullptr, nullptr, t2, nullptr, CDIM, 4*CDIM);
    out_tr<<<dim3(L/32, CDIM/32, BATCH), dim3(32,8)>>>(t2, out);
}

// round 7
// speedup vs baseline: 2.7061x; 1.4067x over previous
#include <cuda_runtime.h>
#include <cuda_fp16.h>
#include <math.h>
#include <stdint.h>

// ---------------- problem constants ----------------
#define BATCH   8
#define CIN     64
#define CDIM    192
#define HDIM    112
#define WDIM    112
#define L       (HDIM*WDIM)          // 12544
#define TKN     (BATCH*L)            // 100352
#define WS      7
#define NWIN    49
#define NH      6
#define HD      32
#define NWTOT   2048
#define KCONV   576

typedef unsigned long long u64;

// ---------------- f32x2 helpers ----------------
#define FMA2(d,a,b)    asm("fma.rn.f32x2 %0, %1, %2, %0;" : "+l"(d) : "l"(a), "l"(b))
#define PACK2(d,x)     asm("mov.b64 %0, {%1, %1};" : "=l"(d) : "f"(x))
#define PACK2XY(d,x,y) asm("mov.b64 %0, {%1, %2};" : "=l"(d) : "f"(x), "f"(y))
#define UNPACK2(x,y,d) asm("mov.b64 {%0, %1}, %2;" : "=f"(x), "=f"(y) : "l"(d))

union F4U2 { float4 f; u64 u[2]; };

__device__ __forceinline__ uint32_t smem_u32(const void* p) {
    uint32_t a;
    asm("{ .reg .u64 t; cvta.to.shared.u64 t, %1; cvt.u32.u64 %0, t; }" : "=r"(a) : "l"(p));
    return a;
}

// ---------------- warp-MMA + cp.async primitives (base ISA) ----------------
#define LDMX4(r, addr) \
    asm volatile("ldmatrix.sync.aligned.m8n8.x4.shared.b16 {%0,%1,%2,%3}, [%4];" \
        : "=r"((r)[0]), "=r"((r)[1]), "=r"((r)[2]), "=r"((r)[3]) : "r"(addr))

#define MMA16816(c, a, b0, b1) \
    asm volatile("mma.sync.aligned.m16n8k16.row.col.f32.f16.f16.f32 " \
        "{%0,%1,%2,%3}, {%4,%5,%6,%7}, {%8,%9}, {%0,%1,%2,%3};" \
        : "+f"((c)[0]), "+f"((c)[1]), "+f"((c)[2]), "+f"((c)[3]) \
        : "r"((a)[0]), "r"((a)[1]), "r"((a)[2]), "r"((a)[3]), "r"(b0), "r"(b1))

#define CPA16(dst, src) \
    asm volatile("cp.async.ca.shared.global [%0], [%1], 16;" :: "r"(dst), "l"(src))
#define CPCOMMIT() asm volatile("cp.async.commit_group;" ::: "memory")
#define CPWAIT(n)  asm volatile("cp.async.wait_group %0;" :: "n"(n) : "memory")

// ---------------- scratch (static device) ----------------
__device__ __half g_col[(size_t)TKN*KCONV];     // conv A, fp16
__device__ __half g_ln [(size_t)TKN*CDIM];      // LN output, fp16
__device__ __half g_ao [(size_t)TKN*CDIM];      // attention out, fp16
__device__ __half g_m1 [(size_t)TKN*4*CDIM];    // fc1+GELU out, fp16
__device__ float g_xt [(size_t)TKN*CDIM];
__device__ float g_qkv[(size_t)TKN*3*CDIM];
__device__ float g_t1 [(size_t)TKN*CDIM];
__device__ float g_t2 [(size_t)TKN*CDIM];
__device__ float g_bias[NH*NWIN*NWIN];
// weight pairs [ (Whi_c | Wlo_c), c = 0..K/32 ), width 2K fp16
__device__ __half g_wconv[CDIM*2*KCONV];
__device__ __half g_wqkv [3*CDIM*2*CDIM];
__device__ __half g_wap  [CDIM*2*CDIM];
__device__ __half g_wfc1 [4*CDIM*2*CDIM];
__device__ __half g_wfc2 [CDIM*2*4*CDIM];

// ---------------- 2-term split-fp16 HMMA GEMM, BM=128 BN=192 BK=32, 3-stage -------
// A: [M,K] fp16. B2 row: [(Whi_c|Wlo_c) pairs], width 2K.
// Per k32 chunk: acc += A*Whi + A*Wlo.
// EPI: 0 bias->Cf | 2 bias+GELU->Cs(h) | 3 bias->Cf + LN->Cs(h)
//      4 bias+res->Cf + LN->Cs(h)      | 5 bias+res+res2->Cf
#define AROWB  80
#define BROWB  144
#define ASTAGE 10240
#define BSTAGE 27648
#define STG    3
#define SMEM_GEMM (STG*(ASTAGE+BSTAGE))   // 113664
template<int EPI>
__global__ __launch_bounds__(256) void mma_gemm(
    const __half* __restrict__ A, const __half* __restrict__ B2,
    const float* __restrict__ bias, const float* __restrict__ res,
    const float* __restrict__ res2, const float* __restrict__ lnw,
    const float* __restrict__ lnb,
    float* __restrict__ Cf, __half* __restrict__ Cs,
    int N, int K)
{
    extern __shared__ __align__(16) char dsm[];
    const uint32_t s0 = smem_u32(dsm);
    const int t = threadIdx.x, wid = t >> 5, lane = t & 31;
    const int n0 = blockIdx.x * 192, m0 = blockIdx.y * 128;
    const int wm = (wid >> 2) * 64, wn = (wid & 3) * 48;
    const int mat = lane >> 3, rr = lane & 7;
    const int kc = K >> 5;
    const size_t ldb = 2*(size_t)K;

    float acc[4][6][4];
    #pragma unroll
    for (int i = 0; i < 4; i++)
        #pragma unroll
        for (int j = 0; j < 6; j++)
            #pragma unroll
            for (int l = 0; l < 4; l++) acc[i][j][l] = 0.f;

    auto issue = [&](int c) {
        const int buf = c % STG;
        const uint32_t aS = s0 + buf*ASTAGE;
        const uint32_t bS = s0 + STG*ASTAGE + buf*BSTAGE;
        const int ac = c << 5;
        {   // A: 128 rows x 64B
            const int row = t >> 2, seg = t & 3;
            CPA16(aS + row*AROWB + seg*16,
                  A + (size_t)(m0 + row)*K + ac + seg*8);
            CPA16(aS + (row + 64)*AROWB + seg*16,
                  A + (size_t)(m0 + row + 64)*K + ac + seg*8);
        }
        {   // B pair: 192 rows x 128B
            const int bc = c << 6;
            #pragma unroll
            for (int j = 0; j < 6; j++) {
                const int idx = t + 256*j, row = idx >> 3, seg = idx & 7;
                CPA16(bS + row*BROWB + seg*16,
                      B2 + (size_t)(n0 + row)*ldb + bc + seg*8);
            }
        }
    };

    issue(0); CPCOMMIT();
    if (kc > 1) { issue(1); CPCOMMIT(); } else { CPCOMMIT(); }
    for (int c = 0; c < kc; c++) {
        CPWAIT(1);
        __syncthreads();
        if (c + 2 < kc) issue(c + 2);
        CPCOMMIT();
        const int buf = c % STG;
        const uint32_t aB = s0 + buf*ASTAGE;
        const uint32_t bB = s0 + STG*ASTAGE + buf*BSTAGE;
        #pragma unroll
        for (int ks = 0; ks < 2; ks++) {
            const int kb = ks * 32;
            uint32_t afr[4][4];
            #pragma unroll
            for (int am = 0; am < 4; am++)
                LDMX4(afr[am], aB + (uint32_t)((wm + am*16 + (lane & 15))*AROWB)
                             + kb + ((lane >> 4) << 4));
            uint32_t bf[3][4];
            #pragma unroll
            for (int bn = 0; bn < 3; bn++)
                LDMX4(bf[bn], bB + (uint32_t)((wn + bn*16 + ((mat & 2) << 2) + rr)*BROWB)
                            + kb + ((mat & 1) << 4));
            #pragma unroll
            for (int am = 0; am < 4; am++)
                #pragma unroll
                for (int bn = 0; bn < 3; bn++) {
                    MMA16816(acc[am][bn*2],   afr[am], bf[bn][0], bf[bn][1]);
                    MMA16816(acc[am][bn*2+1], afr[am], bf[bn][2], bf[bn][3]);
                }
            // Wlo half of the pair (+64B)
            #pragma unroll
            for (int bn = 0; bn < 3; bn++)
                LDMX4(bf[bn], bB + (uint32_t)((wn + bn*16 + ((mat & 2) << 2) + rr)*BROWB)
                            + 64 + kb + ((mat & 1) << 4));
            #pragma unroll
            for (int am = 0; am < 4; am++)
                #pragma unroll
                for (int bn = 0; bn < 3; bn++) {
                    MMA16816(acc[am][bn*2],   afr[am], bf[bn][0], bf[bn][1]);
                    MMA16816(acc[am][bn*2+1], afr[am], bf[bn][2], bf[bn][3]);
                }
        }
    }
    __syncthreads();

    // ---- epilogue pass 1: bias (+residuals), back into acc ----
    float lsum[4][2], lsq[4][2];
    #pragma unroll
    for (int am = 0; am < 4; am++)
        #pragma unroll
        for (int h = 0; h < 2; h++) { lsum[am][h] = 0.f; lsq[am][h] = 0.f; }
    #pragma unroll
    for (int am = 0; am < 4; am++) {
        #pragma unroll
        for (int nf = 0; nf < 6; nf++) {
            const int nn = n0 + wn + nf*8 + ((lane & 3) << 1);
            const float b0 = bias[nn], b1 = bias[nn + 1];
            #pragma unroll
            for (int h = 0; h < 2; h++) {
                const int m = m0 + wm + am*16 + (lane >> 2) + h*8;
                float o0 = acc[am][nf][h*2]     + b0;
                float o1 = acc[am][nf][h*2 + 1] + b1;
                if (EPI == 4 || EPI == 5) {
                    float2 rv = *(const float2*)(res + (size_t)m*N + nn);
                    o0 += rv.x; o1 += rv.y;
                }
                if (EPI == 5) {
                    float2 rv = *(const float2*)(res2 + (size_t)m*N + nn);
                    o0 += rv.x; o1 += rv.y;
                }
                if (EPI == 2) {
                    o0 = 0.5f*o0*(1.0f + erff(o0*0.70710678118654752f));
                    o1 = 0.5f*o1*(1.0f + erff(o1*0.70710678118654752f));
                }
                acc[am][nf][h*2]     = o0;
                acc[am][nf][h*2 + 1] = o1;
                if (EPI == 3 || EPI == 4) {
                    lsum[am][h] += o0 + o1;
                    lsq[am][h]  += o0*o0 + o1*o1;
                }
            }
        }
    }

    float mu[4][2], rs[4][2];
    if (EPI == 3 || EPI == 4) {   // row LayerNorm stats (N==192, full row in CTA)
        float2* red = (float2*)dsm;
        #pragma unroll
        for (int am = 0; am < 4; am++)
            #pragma unroll
            for (int h = 0; h < 2; h++) {
                #pragma unroll
                for (int ox = 1; ox < 4; ox <<= 1) {
                    lsum[am][h] += __shfl_xor_sync(0xffffffffu, lsum[am][h], ox);
                    lsq[am][h]  += __shfl_xor_sync(0xffffffffu, lsq[am][h], ox);
                }
            }
        if ((lane & 3) == 0) {
            #pragma unroll
            for (int am = 0; am < 4; am++)
                #pragma unroll
                for (int h = 0; h < 2; h++) {
                    int row = wm + am*16 + (lane >> 2) + h*8;
                    red[row*4 + (wid & 3)] = make_float2(lsum[am][h], lsq[am][h]);
                }
        }
        __syncthreads();
        #pragma unroll
        for (int am = 0; am < 4; am++)
            #pragma unroll
            for (int h = 0; h < 2; h++) {
                int row = wm + am*16 + (lane >> 2) + h*8;
                float s = 0.f, q = 0.f;
                #pragma unroll
                for (int w = 0; w < 4; w++) {
                    float2 v = red[row*4 + w];
                    s += v.x; q += v.y;
                }
                float m_ = s * (1.f/192.f);
                float var = q * (1.f/192.f) - m_*m_;
                mu[am][h] = m_;
                rs[am][h] = rsqrtf(var + 1e-5f);
            }
    }

    // ---- epilogue pass 2: writes ----
    #pragma unroll
    for (int am = 0; am < 4; am++) {
        #pragma unroll
        for (int nf = 0; nf < 6; nf++) {
            const int nn = n0 + wn + nf*8 + ((lane & 3) << 1);
            #pragma unroll
            for (int h = 0; h < 2; h++) {
                const int m = m0 + wm + am*16 + (lane >> 2) + h*8;
                const float o0 = acc[am][nf][h*2], o1 = acc[am][nf][h*2 + 1];
                if (EPI == 0 || EPI == 5) {
                    *(float2*)(Cf + (size_t)m*N + nn) = make_float2(o0, o1);
                } else if (EPI == 2) {
                    *(__half2*)(Cs + (size_t)m*N + nn) =
                        __halves2half2(__float2half_rn(o0), __float2half_rn(o1));
                } else {   // EPI 3/4: raw -> Cf, LN -> Cs
                    *(float2*)(Cf + (size_t)m*N + nn) = make_float2(o0, o1);
                    float y0 = (o0 - mu[am][h])*rs[am][h]*lnw[nn]     + lnb[nn];
                    float y1 = (o1 - mu[am][h])*rs[am][h]*lnw[nn + 1] + lnb[nn + 1];
                    *(__half2*)(Cs + (size_t)m*N + nn) =
                        __halves2half2(__float2half_rn(y0), __float2half_rn(y1));
                }
            }
        }
    }
}

// ---------------- weight split: W[N,K] fp32 -> fp16 pairs, width 2K ----------------
__global__ void wsplit(const float* __restrict__ W, __half* __restrict__ B2,
                       int N, int K)
{
    int i = blockIdx.x*256 + threadIdx.x;
    if (i >= N*K) return;
    int n = i / K, k = i - n*K;
    float v = W[i];
    __half h = __float2half_rn(v);
    __half l = __float2half_rn(v - __half2float(h));
    size_t b = (size_t)n*2*K;
    int c = k >> 5, p = k & 31;
    B2[b + c*64 + p]      = h;
    B2[b + c*64 + 32 + p] = l;
}

// ---------------- im2col (fp16) ----------------
__global__ void im2col_h(const float* __restrict__ x, __half* __restrict__ col)
{
    size_t i4 = (size_t)blockIdx.x*256 + threadIdx.x;
    if (i4 >= (size_t)TKN*144) return;
    int m  = (int)(i4 / 144);
    int k0 = (int)(i4 % 144) * 4;
    int b = m / L, hw = m % L, h = hw / WDIM, w = hw % WDIM;
    __half v[4];
    #pragma unroll
    for (int u = 0; u < 4; u++) {
        int k = k0 + u, ci = k / 9, rq = k - ci*9, kh = rq / 3, kw = rq - kh*3;
        int ih = h + kh - 1, iw = w + kw - 1;
        float f = (ih >= 0 && ih < HDIM && iw >= 0 && iw < WDIM)
                ? x[((size_t)(b*CIN + ci)*HDIM + ih)*WDIM + iw] : 0.f;
        v[u] = __float2half_rn(f);
    }
    *(uint2*)&col[(size_t)m*KCONV + k0] = *(uint2*)v;
}

// ---------------- rel-pos bias precompute ----------------
__global__ void bias_pre(const float* __restrict__ tab, const int* __restrict__ idx,
                         float* __restrict__ out)
{
    int i = blockIdx.x*256 + threadIdx.x;
    if (i < NH*NWIN*NWIN) {
        int h = i / (NWIN*NWIN), ij = i % (NWIN*NWIN);
        out[i] = tab[idx[ij]*NH + h];
    }
}

// ---------------- window attention (fp32 compute, fp16 out) ----------------
__global__ __launch_bounds__(64) void attn_kernel(const float* __restrict__ qkv,
                                                  const float* __restrict__ biasg,
                                                  __half* __restrict__ o)
{
    __shared__ float ks[NWIN*HD], vs[NWIN*HD];
    __shared__ float sc[NWIN*NWIN];
    __shared__ int toks[NWIN];
    const int t = threadIdx.x;
    const int wi = blockIdx.x, head = blockIdx.y;
    const int b = wi >> 8, r = wi & 255, wh = r >> 4, ww = r & 15;
    if (t < NWIN) toks[t] = b*L + (wh*WS + t/WS)*WDIM + (ww*WS + t%WS);
    __syncthreads();

    for (int idx = t; idx < NWIN*8; idx += 64) {
        int row = idx >> 3, seg = idx & 7;
        const float4* src = (const float4*)(qkv + (size_t)toks[row]*(3*CDIM) + head*HD);
        *(float4*)&ks[row*HD + seg*4] = src[seg + 48];
        *(float4*)&vs[row*HD + seg*4] = src[seg + 96];
    }
    u64 q2[16];
    if (t < NWIN) {
        const float4* src = (const float4*)(qkv + (size_t)toks[t]*(3*CDIM) + head*HD);
        const float s = 0.17677669529663687f;
        #pragma unroll
        for (int l = 0; l < 8; l++) {
            float4 f = src[l];
            PACK2XY(q2[2*l],   f.x*s, f.y*s);
            PACK2XY(q2[2*l+1], f.z*s, f.w*s);
        }
    }
    __syncthreads();

    if (t < NWIN) {
        u64 z2; { float z = 0.f; PACK2(z2, z); }
        const float* bs = biasg + head*(NWIN*NWIN) + t*NWIN;
        float* row = &sc[t*NWIN];
        for (int j = 0; j < NWIN; j++) {
            const float4* kp = (const float4*)&ks[j*HD];
            u64 a2 = z2;
            #pragma unroll
            for (int d8 = 0; d8 < 8; d8++) {
                F4U2 kv; kv.f = kp[d8];
                FMA2(a2, q2[2*d8],     kv.u[0]);
                FMA2(a2, q2[2*d8 + 1], kv.u[1]);
            }
            float lo, hi; UNPACK2(lo, hi, a2);
            row[j] = lo + hi + bs[j];
        }
        float mx = -1e30f;
        for (int j = 0; j < NWIN; j++) mx = fmaxf(mx, row[j]);
        float s = 0.f;
        for (int j = 0; j < NWIN; j++) { float e = expf(row[j]-mx); row[j] = e; s += e; }
        float inv = 1.f/s;
        u64 acc2[16];
        #pragma unroll
        for (int d = 0; d < 16; d++) acc2[d] = z2;
        for (int j = 0; j < NWIN; j++) {
            const float4* vp = (const float4*)&vs[j*HD];
            u64 p2; float p = row[j]*inv; PACK2(p2, p);
            #pragma unroll
            for (int d8 = 0; d8 < 8; d8++) {
                F4U2 vv; vv.f = vp[d8];
                FMA2(acc2[2*d8],     p2, vv.u[0]);
                FMA2(acc2[2*d8 + 1], p2, vv.u[1]);
            }
        }
        __half2* ph = (__half2*)(o + (size_t)toks[t]*CDIM + head*HD);
        #pragma unroll
        for (int l = 0; l < 16; l++) {
            float x0, x1; UNPACK2(x0, x1, acc2[l]);
            ph[l] = __halves2half2(__float2half_rn(x0), __float2half_rn(x1));
        }
    }
}

// ---------------- final transpose: out[b,c,hw] = t2[tok,c] ----------------
__global__ void out_tr(const float* __restrict__ t2, float* __restrict__ out)
{
    __shared__ float tile[32][33];
    const int b   = blockIdx.z;
    const int hw0 = blockIdx.x * 32;
    const int c0  = blockIdx.y * 32;
    const int tx  = threadIdx.x, ty = threadIdx.y;   // (32, 8)
    #pragma unroll
    for (int r = 0; r < 4; r++) {
        int i = r*8 + ty;
        tile[i][tx] = t2[(size_t)(b*L + hw0 + i)*CDIM + c0 + tx];
    }
    __syncthreads();
    #pragma unroll
    for (int r = 0; r < 4; r++) {
        int cy = r*8 + ty;
        out[(size_t)(b*CDIM + c0 + cy)*L + hw0 + tx] = tile[tx][cy];
    }
}

// ---------------- launch ----------------
extern "C" void kernel_launch(void* const* d_in, const int* in_sizes, int n_in,
                              void* d_out, int out_size)
{
    const float* x        = (const float*)d_in[0];
    const float* proj_w   = (const float*)d_in[1];
    const float* proj_b   = (const float*)d_in[2];
    const float* ln1_w    = (const float*)d_in[3];
    const float* ln1_b    = (const float*)d_in[4];
    const float* qkv_w    = (const float*)d_in[5];
    const float* qkv_b    = (const float*)d_in[6];
    const float* rel_tab  = (const float*)d_in[7];
    const float* apw      = (const float*)d_in[8];
    const float* apb      = (const float*)d_in[9];
    const float* ln2_w    = (const float*)d_in[10];
    const float* ln2_b    = (const float*)d_in[11];
    const float* fc1_w    = (const float*)d_in[12];
    const float* fc1_b    = (const float*)d_in[13];
    const float* fc2_w    = (const float*)d_in[14];
    const float* fc2_b    = (const float*)d_in[15];
    const int*   rel_idx  = (const int*)d_in[16];
    float* out = (float*)d_out;

    __half *colh, *lnq, *aoh, *m1h, *wconv, *wqkv, *wap, *wfc1, *wfc2;
    float *xt, *qkvb, *t1, *t2, *biasp;
    cudaGetSymbolAddress((void**)&colh,  g_col);
    cudaGetSymbolAddress((void**)&lnq,   g_ln);
    cudaGetSymbolAddress((void**)&aoh,   g_ao);
    cudaGetSymbolAddress((void**)&m1h,   g_m1);
    cudaGetSymbolAddress((void**)&xt,    g_xt);
    cudaGetSymbolAddress((void**)&qkvb,  g_qkv);
    cudaGetSymbolAddress((void**)&t1,    g_t1);
    cudaGetSymbolAddress((void**)&t2,    g_t2);
    cudaGetSymbolAddress((void**)&biasp, g_bias);
    cudaGetSymbolAddress((void**)&wconv, g_wconv);
    cudaGetSymbolAddress((void**)&wqkv,  g_wqkv);
    cudaGetSymbolAddress((void**)&wap,   g_wap);
    cudaGetSymbolAddress((void**)&wfc1,  g_wfc1);
    cudaGetSymbolAddress((void**)&wfc2,  g_wfc2);

    cudaFuncSetAttribute(mma_gemm<0>, cudaFuncAttributeMaxDynamicSharedMemorySize, SMEM_GEMM);
    cudaFuncSetAttribute(mma_gemm<2>, cudaFuncAttributeMaxDynamicSharedMemorySize, SMEM_GEMM);
    cudaFuncSetAttribute(mma_gemm<3>, cudaFuncAttributeMaxDynamicSharedMemorySize, SMEM_GEMM);
    cudaFuncSetAttribute(mma_gemm<4>, cudaFuncAttributeMaxDynamicSharedMemorySize, SMEM_GEMM);
    cudaFuncSetAttribute(mma_gemm<5>, cudaFuncAttributeMaxDynamicSharedMemorySize, SMEM_GEMM);

    const int MB = TKN/128;   // 784

    bias_pre<<<57, 256>>>(rel_tab, rel_idx, biasp);
    wsplit<<<(CDIM*KCONV + 255)/256, 256>>>(proj_w, wconv, CDIM, KCONV);
    wsplit<<<(3*CDIM*CDIM + 255)/256, 256>>>(qkv_w, wqkv, 3*CDIM, CDIM);
    wsplit<<<(CDIM*CDIM + 255)/256, 256>>>(apw, wap, CDIM, CDIM);
    wsplit<<<(4*CDIM*CDIM + 255)/256, 256>>>(fc1_w, wfc1, 4*CDIM, CDIM);
    wsplit<<<(CDIM*4*CDIM + 255)/256, 256>>>(fc2_w, wfc2, CDIM, 4*CDIM);

    im2col_h<<<(int)(((size_t)TKN*144 + 255)/256), 256>>>(x, colh);
    // conv + fused LN1: writes xt (fp32) + lnq (fp16)
    mma_gemm<3><<<dim3(1, MB), 256, SMEM_GEMM>>>(colh, wconv, proj_b, nullptr, nullptr,
                                                 ln1_w, ln1_b, xt, lnq, CDIM, KCONV);
    // qkv (fp32 out)
    mma_gemm<0><<<dim3(3, MB), 256, SMEM_GEMM>>>(lnq, wqkv, qkv_b, nullptr, nullptr,
                                                 nullptr, nullptr, qkvb, nullptr, 3*CDIM, CDIM);
    attn_kernel<<<dim3(NWTOT, NH), 64>>>(qkvb, biasp, aoh);
    // attn-proj + residual(xt) + fused LN2: writes t1 + lnq
    mma_gemm<4><<<dim3(1, MB), 256, SMEM_GEMM>>>(aoh, wap, apb, xt, nullptr,
                                                 ln2_w, ln2_b, t1, lnq, CDIM, CDIM);
    // fc1 + GELU -> fp16
    mma_gemm<2><<<dim3(4, MB), 256, SMEM_GEMM>>>(lnq, wfc1, fc1_b, nullptr, nullptr,
                                                 nullptr, nullptr, nullptr, m1h, 4*CDIM, CDIM);
    // fc2 + residual(t1) + shortcut(xt) -> t2
    mma_gemm<5><<<dim3(1, MB), 256, SMEM_GEMM>>>(m1h, wfc2, fc2_b, t1, xt,
                                                 nullptr, nullptr, t2, nullptr, CDIM, 4*CDIM);
    out_tr<<<dim3(L/32, CDIM/32, BATCH), dim3(32,8)>>>(t2, out);
}

// round 8
// speedup vs baseline: 3.0534x; 1.1283x over previous
#include <cuda_runtime.h>
#include <cuda_fp16.h>
#include <math.h>
#include <stdint.h>

// ---------------- problem constants ----------------
#define BATCH   8
#define CIN     64
#define CDIM    192
#define HDIM    112
#define WDIM    112
#define L       (HDIM*WDIM)          // 12544
#define TKN     (BATCH*L)            // 100352
#define WS      7
#define NWIN    49
#define NH      6
#define HD      32
#define NWTOT   2048
#define KCONV   576

typedef unsigned long long u64;

// ---------------- f32x2 helpers ----------------
#define FMA2(d,a,b)    asm("fma.rn.f32x2 %0, %1, %2, %0;" : "+l"(d) : "l"(a), "l"(b))
#define PACK2(d,x)     asm("mov.b64 %0, {%1, %1};" : "=l"(d) : "f"(x))
#define PACK2XY(d,x,y) asm("mov.b64 %0, {%1, %2};" : "=l"(d) : "f"(x), "f"(y))
#define UNPACK2(x,y,d) asm("mov.b64 {%0, %1}, %2;" : "=f"(x), "=f"(y) : "l"(d))

union F4U2 { float4 f; u64 u[2]; };

__device__ __forceinline__ uint32_t smem_u32(const void* p) {
    uint32_t a;
    asm("{ .reg .u64 t; cvta.to.shared.u64 t, %1; cvt.u32.u64 %0, t; }" : "=r"(a) : "l"(p));
    return a;
}

// ---------------- warp-MMA + cp.async primitives (base ISA) ----------------
#define LDMX4(r, addr) \
    asm volatile("ldmatrix.sync.aligned.m8n8.x4.shared.b16 {%0,%1,%2,%3}, [%4];" \
        : "=r"((r)[0]), "=r"((r)[1]), "=r"((r)[2]), "=r"((r)[3]) : "r"(addr))

#define MMA16816(c, a, b0, b1) \
    asm volatile("mma.sync.aligned.m16n8k16.row.col.f32.f16.f16.f32 " \
        "{%0,%1,%2,%3}, {%4,%5,%6,%7}, {%8,%9}, {%0,%1,%2,%3};" \
        : "+f"((c)[0]), "+f"((c)[1]), "+f"((c)[2]), "+f"((c)[3]) \
        : "r"((a)[0]), "r"((a)[1]), "r"((a)[2]), "r"((a)[3]), "r"(b0), "r"(b1))

#define CPA16(dst, src) \
    asm volatile("cp.async.ca.shared.global [%0], [%1], 16;" :: "r"(dst), "l"(src))
#define CPCOMMIT() asm volatile("cp.async.commit_group;" ::: "memory")
#define CPWAIT(n)  asm volatile("cp.async.wait_group %0;" :: "n"(n) : "memory")

// ---------------- scratch (static device) ----------------
__device__ __half g_col[(size_t)TKN*KCONV];     // conv A, fp16
__device__ __half g_ln [(size_t)TKN*CDIM];      // LN output, fp16
__device__ __half g_ao [(size_t)TKN*CDIM];      // attention out, fp16
__device__ __half g_m1 [(size_t)TKN*4*CDIM];    // fc1+GELU out, fp16
__device__ __half g_qkv[(size_t)TKN*3*CDIM];    // qkv, fp16
__device__ float g_xt [(size_t)TKN*CDIM];
__device__ float g_t1 [(size_t)TKN*CDIM];
__device__ float g_t2 [(size_t)TKN*CDIM];
__device__ float g_bias[NH*NWIN*NWIN];
// plain fp16 weights [N,K]
__device__ __half g_wconv[CDIM*KCONV];
__device__ __half g_wqkv [3*CDIM*CDIM];
__device__ __half g_wap  [CDIM*CDIM];
__device__ __half g_wfc1 [4*CDIM*CDIM];
__device__ __half g_wfc2 [CDIM*4*CDIM];

// ---------------- fp16 HMMA GEMM, BM=128 BN=192 BK=32, 3-stage cp.async ----------
// A: [M,K] fp16. B: [N,K] fp16.
// EPI: 0 bias->Cs(h) | 2 bias+GELU->Cs(h) | 3 bias->Cf + LN->Cs(h)
//      4 bias+res->Cf + LN->Cs(h)        | 5 bias+res+res2->Cf
#define AROWB  80
#define BROWB  80
#define ASTAGE 10240
#define BSTAGE 15360
#define STG    3
#define SMEM_GEMM (STG*(ASTAGE+BSTAGE))   // 76800
template<int EPI>
__global__ __launch_bounds__(256) void mma_gemm(
    const __half* __restrict__ A, const __half* __restrict__ B,
    const float* __restrict__ bias, const float* __restrict__ res,
    const float* __restrict__ res2, const float* __restrict__ lnw,
    const float* __restrict__ lnb,
    float* __restrict__ Cf, __half* __restrict__ Cs,
    int N, int K)
{
    extern __shared__ __align__(16) char dsm[];
    const uint32_t s0 = smem_u32(dsm);
    const int t = threadIdx.x, wid = t >> 5, lane = t & 31;
    const int n0 = blockIdx.x * 192, m0 = blockIdx.y * 128;
    const int wm = (wid >> 2) * 64, wn = (wid & 3) * 48;
    const int mat = lane >> 3, rr = lane & 7;
    const int kc = K >> 5;

    float acc[4][6][4];
    #pragma unroll
    for (int i = 0; i < 4; i++)
        #pragma unroll
        for (int j = 0; j < 6; j++)
            #pragma unroll
            for (int l = 0; l < 4; l++) acc[i][j][l] = 0.f;

    auto issue = [&](int c) {
        const int buf = c % STG;
        const uint32_t aS = s0 + buf*ASTAGE;
        const uint32_t bS = s0 + STG*ASTAGE + buf*BSTAGE;
        const int ac = c << 5;
        {   // A: 128 rows x 64B
            const int row = t >> 2, seg = t & 3;
            CPA16(aS + row*AROWB + seg*16,
                  A + (size_t)(m0 + row)*K + ac + seg*8);
            CPA16(aS + (row + 64)*AROWB + seg*16,
                  A + (size_t)(m0 + row + 64)*K + ac + seg*8);
        }
        {   // B: 192 rows x 64B = 768 x 16B
            #pragma unroll
            for (int j = 0; j < 3; j++) {
                const int idx = t + 256*j, row = idx >> 2, seg = idx & 3;
                CPA16(bS + row*BROWB + seg*16,
                      B + (size_t)(n0 + row)*K + ac + seg*8);
            }
        }
    };

    issue(0); CPCOMMIT();
    issue(1); CPCOMMIT();
    for (int c = 0; c < kc; c++) {
        CPWAIT(1);
        __syncthreads();
        if (c + 2 < kc) issue(c + 2);
        CPCOMMIT();
        const int buf = c % STG;
        const uint32_t aB = s0 + buf*ASTAGE;
        const uint32_t bB = s0 + STG*ASTAGE + buf*BSTAGE;
        #pragma unroll
        for (int ks = 0; ks < 2; ks++) {
            const int kb = ks * 32;
            uint32_t afr[4][4];
            #pragma unroll
            for (int am = 0; am < 4; am++)
                LDMX4(afr[am], aB + (uint32_t)((wm + am*16 + (lane & 15))*AROWB)
                             + kb + ((lane >> 4) << 4));
            uint32_t bf[3][4];
            #pragma unroll
            for (int bn = 0; bn < 3; bn++)
                LDMX4(bf[bn], bB + (uint32_t)((wn + bn*16 + ((mat & 2) << 2) + rr)*BROWB)
                            + kb + ((mat & 1) << 4));
            #pragma unroll
            for (int am = 0; am < 4; am++)
                #pragma unroll
                for (int bn = 0; bn < 3; bn++) {
                    MMA16816(acc[am][bn*2],   afr[am], bf[bn][0], bf[bn][1]);
                    MMA16816(acc[am][bn*2+1], afr[am], bf[bn][2], bf[bn][3]);
                }
        }
    }
    __syncthreads();

    // ---- epilogue pass 1: bias (+residuals), back into acc ----
    float lsum[4][2], lsq[4][2];
    #pragma unroll
    for (int am = 0; am < 4; am++)
        #pragma unroll
        for (int h = 0; h < 2; h++) { lsum[am][h] = 0.f; lsq[am][h] = 0.f; }
    #pragma unroll
    for (int am = 0; am < 4; am++) {
        #pragma unroll
        for (int nf = 0; nf < 6; nf++) {
            const int nn = n0 + wn + nf*8 + ((lane & 3) << 1);
            const float b0 = bias[nn], b1 = bias[nn + 1];
            #pragma unroll
            for (int h = 0; h < 2; h++) {
                const int m = m0 + wm + am*16 + (lane >> 2) + h*8;
                float o0 = acc[am][nf][h*2]     + b0;
                float o1 = acc[am][nf][h*2 + 1] + b1;
                if (EPI == 4 || EPI == 5) {
                    float2 rv = *(const float2*)(res + (size_t)m*N + nn);
                    o0 += rv.x; o1 += rv.y;
                }
                if (EPI == 5) {
                    float2 rv = *(const float2*)(res2 + (size_t)m*N + nn);
                    o0 += rv.x; o1 += rv.y;
                }
                if (EPI == 2) {
                    o0 = 0.5f*o0*(1.0f + erff(o0*0.70710678118654752f));
                    o1 = 0.5f*o1*(1.0f + erff(o1*0.70710678118654752f));
                }
                acc[am][nf][h*2]     = o0;
                acc[am][nf][h*2 + 1] = o1;
                if (EPI == 3 || EPI == 4) {
                    lsum[am][h] += o0 + o1;
                    lsq[am][h]  += o0*o0 + o1*o1;
                }
            }
        }
    }

    float mu[4][2], rs[4][2];
    if (EPI == 3 || EPI == 4) {   // row LayerNorm (N==192: full row in CTA)
        float2* red = (float2*)dsm;
        #pragma unroll
        for (int am = 0; am < 4; am++)
            #pragma unroll
            for (int h = 0; h < 2; h++) {
                #pragma unroll
                for (int ox = 1; ox < 4; ox <<= 1) {
                    lsum[am][h] += __shfl_xor_sync(0xffffffffu, lsum[am][h], ox);
                    lsq[am][h]  += __shfl_xor_sync(0xffffffffu, lsq[am][h], ox);
                }
            }
        if ((lane & 3) == 0) {
            #pragma unroll
            for (int am = 0; am < 4; am++)
                #pragma unroll
                for (int h = 0; h < 2; h++) {
                    int row = wm + am*16 + (lane >> 2) + h*8;
                    red[row*4 + (wid & 3)] = make_float2(lsum[am][h], lsq[am][h]);
                }
        }
        __syncthreads();
        #pragma unroll
        for (int am = 0; am < 4; am++)
            #pragma unroll
            for (int h = 0; h < 2; h++) {
                int row = wm + am*16 + (lane >> 2) + h*8;
                float s = 0.f, q = 0.f;
                #pragma unroll
                for (int w = 0; w < 4; w++) {
                    float2 v = red[row*4 + w];
                    s += v.x; q += v.y;
                }
                float m_ = s * (1.f/192.f);
                float var = q * (1.f/192.f) - m_*m_;
                mu[am][h] = m_;
                rs[am][h] = rsqrtf(var + 1e-5f);
            }
    }

    // ---- epilogue pass 2: writes ----
    #pragma unroll
    for (int am = 0; am < 4; am++) {
        #pragma unroll
        for (int nf = 0; nf < 6; nf++) {
            const int nn = n0 + wn + nf*8 + ((lane & 3) << 1);
            #pragma unroll
            for (int h = 0; h < 2; h++) {
                const int m = m0 + wm + am*16 + (lane >> 2) + h*8;
                const float o0 = acc[am][nf][h*2], o1 = acc[am][nf][h*2 + 1];
                if (EPI == 5) {
                    *(float2*)(Cf + (size_t)m*N + nn) = make_float2(o0, o1);
                } else if (EPI == 0 || EPI == 2) {
                    *(__half2*)(Cs + (size_t)m*N + nn) =
                        __halves2half2(__float2half_rn(o0), __float2half_rn(o1));
                } else {   // EPI 3/4: raw -> Cf, LN -> Cs
                    *(float2*)(Cf + (size_t)m*N + nn) = make_float2(o0, o1);
                    float y0 = (o0 - mu[am][h])*rs[am][h]*lnw[nn]     + lnb[nn];
                    float y1 = (o1 - mu[am][h])*rs[am][h]*lnw[nn + 1] + lnb[nn + 1];
                    *(__half2*)(Cs + (size_t)m*N + nn) =
                        __halves2half2(__float2half_rn(y0), __float2half_rn(y1));
                }
            }
        }
    }
}

// ---------------- weight convert: fp32 -> fp16 ----------------
__global__ void wconv16(const float* __restrict__ W, __half* __restrict__ B,
                        int NK)
{
    int i = blockIdx.x*256 + threadIdx.x;
    if (i < NK) B[i] = __float2half_rn(W[i]);
}

// ---------------- im2col (fp16) ----------------
__global__ void im2col_h(const float* __restrict__ x, __half* __restrict__ col)
{
    size_t i4 = (size_t)blockIdx.x*256 + threadIdx.x;
    if (i4 >= (size_t)TKN*144) return;
    int m  = (int)(i4 / 144);
    int k0 = (int)(i4 % 144) * 4;
    int b = m / L, hw = m % L, h = hw / WDIM, w = hw % WDIM;
    __half v[4];
    #pragma unroll
    for (int u = 0; u < 4; u++) {
        int k = k0 + u, ci = k / 9, rq = k - ci*9, kh = rq / 3, kw = rq - kh*3;
        int ih = h + kh - 1, iw = w + kw - 1;
        float f = (ih >= 0 && ih < HDIM && iw >= 0 && iw < WDIM)
                ? x[((size_t)(b*CIN + ci)*HDIM + ih)*WDIM + iw] : 0.f;
        v[u] = __float2half_rn(f);
    }
    *(uint2*)&col[(size_t)m*KCONV + k0] = *(uint2*)v;
}

// ---------------- rel-pos bias precompute ----------------
__global__ void bias_pre(const float* __restrict__ tab, const int* __restrict__ idx,
                         float* __restrict__ out)
{
    int i = blockIdx.x*256 + threadIdx.x;
    if (i < NH*NWIN*NWIN) {
        int h = i / (NWIN*NWIN), ij = i % (NWIN*NWIN);
        out[i] = tab[idx[ij]*NH + h];
    }
}

// ---------------- window attention (fp16 qkv in, fp32 compute, fp16 out) ----------
__global__ __launch_bounds__(64) void attn_kernel(const __half* __restrict__ qkv,
                                                  const float* __restrict__ biasg,
                                                  __half* __restrict__ o)
{
    __shared__ float ks[NWIN*HD], vs[NWIN*HD];
    __shared__ float sc[NWIN*NWIN];
    __shared__ int toks[NWIN];
    const int t = threadIdx.x;
    const int wi = blockIdx.x, head = blockIdx.y;
    const int b = wi >> 8, r = wi & 255, wh = r >> 4, ww = r & 15;
    if (t < NWIN) toks[t] = b*L + (wh*WS + t/WS)*WDIM + (ww*WS + t%WS);
    __syncthreads();

    // K/V: per (row,seg): 8 halves = one uint4
    for (int idx = t; idx < NWIN*4; idx += 64) {
        int row = idx >> 2, seg = idx & 3;
        const __half2* kp = (const __half2*)(qkv + (size_t)toks[row]*(3*CDIM) + CDIM   + head*HD + seg*8);
        const __half2* vp = (const __half2*)(qkv + (size_t)toks[row]*(3*CDIM) + 2*CDIM + head*HD + seg*8);
        #pragma unroll
        for (int u = 0; u < 4; u++) {
            float2 kf = __half22float2(kp[u]);
            float2 vf = __half22float2(vp[u]);
            ks[row*HD + seg*8 + u*2]     = kf.x;
            ks[row*HD + seg*8 + u*2 + 1] = kf.y;
            vs[row*HD + seg*8 + u*2]     = vf.x;
            vs[row*HD + seg*8 + u*2 + 1] = vf.y;
        }
    }
    u64 q2[16];
    if (t < NWIN) {
        const __half2* qsrc = (const __half2*)(qkv + (size_t)toks[t]*(3*CDIM) + head*HD);
        const float s = 0.17677669529663687f;
        #pragma unroll
        for (int l = 0; l < 16; l++) {
            float2 f = __half22float2(qsrc[l]);
            PACK2XY(q2[l], f.x*s, f.y*s);
        }
    }
    __syncthreads();

    if (t < NWIN) {
        u64 z2; { float z = 0.f; PACK2(z2, z); }
        const float* bs = biasg + head*(NWIN*NWIN) + t*NWIN;
        float* row = &sc[t*NWIN];
        for (int j = 0; j < NWIN; j++) {
            const float4* kp = (const float4*)&ks[j*HD];
            u64 a2 = z2;
            #pragma unroll
            for (int d8 = 0; d8 < 8; d8++) {
                F4U2 kv; kv.f = kp[d8];
                FMA2(a2, q2[2*d8],     kv.u[0]);
                FMA2(a2, q2[2*d8 + 1], kv.u[1]);
            }
            float lo, hi; UNPACK2(lo, hi, a2);
            row[j] = lo + hi + bs[j];
        }
        float mx = -1e30f;
        for (int j = 0; j < NWIN; j++) mx = fmaxf(mx, row[j]);
        float s = 0.f;
        for (int j = 0; j < NWIN; j++) { float e = expf(row[j]-mx); row[j] = e; s += e; }
        float inv = 1.f/s;
        u64 acc2[16];
        #pragma unroll
        for (int d = 0; d < 16; d++) acc2[d] = z2;
        for (int j = 0; j < NWIN; j++) {
            const float4* vp = (const float4*)&vs[j*HD];
            u64 p2; float p = row[j]*inv; PACK2(p2, p);
            #pragma unroll
            for (int d8 = 0; d8 < 8; d8++) {
                F4U2 vv; vv.f = vp[d8];
                FMA2(acc2[2*d8],     p2, vv.u[0]);
                FMA2(acc2[2*d8 + 1], p2, vv.u[1]);
            }
        }
        __half2* ph = (__half2*)(o + (size_t)toks[t]*CDIM + head*HD);
        #pragma unroll
        for (int l = 0; l < 16; l++) {
            float x0, x1; UNPACK2(x0, x1, acc2[l]);
            ph[l] = __halves2half2(__float2half_rn(x0), __float2half_rn(x1));
        }
    }
}

// ---------------- final transpose: out[b,c,hw] = t2[tok,c] ----------------
__global__ void out_tr(const float* __restrict__ t2, float* __restrict__ out)
{
    __shared__ float tile[32][33];
    const int b   = blockIdx.z;
    const int hw0 = blockIdx.x * 32;
    const int c0  = blockIdx.y * 32;
    const int tx  = threadIdx.x, ty = threadIdx.y;   // (32, 8)
    #pragma unroll
    for (int r = 0; r < 4; r++) {
        int i = r*8 + ty;
        tile[i][tx] = t2[(size_t)(b*L + hw0 + i)*CDIM + c0 + tx];
    }
    __syncthreads();
    #pragma unroll
    for (int r = 0; r < 4; r++) {
        int cy = r*8 + ty;
        out[(size_t)(b*CDIM + c0 + cy)*L + hw0 + tx] = tile[tx][cy];
    }
}

// ---------------- launch ----------------
extern "C" void kernel_launch(void* const* d_in, const int* in_sizes, int n_in,
                              void* d_out, int out_size)
{
    const float* x        = (const float*)d_in[0];
    const float* proj_w   = (const float*)d_in[1];
    const float* proj_b   = (const float*)d_in[2];
    const float* ln1_w    = (const float*)d_in[3];
    const float* ln1_b    = (const float*)d_in[4];
    const float* qkv_w    = (const float*)d_in[5];
    const float* qkv_b    = (const float*)d_in[6];
    const float* rel_tab  = (const float*)d_in[7];
    const float* apw      = (const float*)d_in[8];
    const float* apb      = (const float*)d_in[9];
    const float* ln2_w    = (const float*)d_in[10];
    const float* ln2_b    = (const float*)d_in[11];
    const float* fc1_w    = (const float*)d_in[12];
    const float* fc1_b    = (const float*)d_in[13];
    const float* fc2_w    = (const float*)d_in[14];
    const float* fc2_b    = (const float*)d_in[15];
    const int*   rel_idx  = (const int*)d_in[16];
    float* out = (float*)d_out;

    __half *colh, *lnq, *aoh, *m1h, *qkvh, *wconv, *wqkv, *wap, *wfc1, *wfc2;
    float *xt, *t1, *t2, *biasp;
    cudaGetSymbolAddress((void**)&colh,  g_col);
    cudaGetSymbolAddress((void**)&lnq,   g_ln);
    cudaGetSymbolAddress((void**)&aoh,   g_ao);
    cudaGetSymbolAddress((void**)&m1h,   g_m1);
    cudaGetSymbolAddress((void**)&qkvh,  g_qkv);
    cudaGetSymbolAddress((void**)&xt,    g_xt);
    cudaGetSymbolAddress((void**)&t1,    g_t1);
    cudaGetSymbolAddress((void**)&t2,    g_t2);
    cudaGetSymbolAddress((void**)&biasp, g_bias);
    cudaGetSymbolAddress((void**)&wconv, g_wconv);
    cudaGetSymbolAddress((void**)&wqkv,  g_wqkv);
    cudaGetSymbolAddress((void**)&wap,   g_wap);
    cudaGetSymbolAddress((void**)&wfc1,  g_wfc1);
    cudaGetSymbolAddress((void**)&wfc2,  g_wfc2);

    cudaFuncSetAttribute(mma_gemm<0>, cudaFuncAttributeMaxDynamicSharedMemorySize, SMEM_GEMM);
    cudaFuncSetAttribute(mma_gemm<2>, cudaFuncAttributeMaxDynamicSharedMemorySize, SMEM_GEMM);
    cudaFuncSetAttribute(mma_gemm<3>, cudaFuncAttributeMaxDynamicSharedMemorySize, SMEM_GEMM);
    cudaFuncSetAttribute(mma_gemm<4>, cudaFuncAttributeMaxDynamicSharedMemorySize, SMEM_GEMM);
    cudaFuncSetAttribute(mma_gemm<5>, cudaFuncAttributeMaxDynamicSharedMemorySize, SMEM_GEMM);

    const int MB = TKN/128;   // 784

    bias_pre<<<57, 256>>>(rel_tab, rel_idx, biasp);
    wconv16<<<(CDIM*KCONV + 255)/256, 256>>>(proj_w, wconv, CDIM*KCONV);
    wconv16<<<(3*CDIM*CDIM + 255)/256, 256>>>(qkv_w, wqkv, 3*CDIM*CDIM);
    wconv16<<<(CDIM*CDIM + 255)/256, 256>>>(apw, wap, CDIM*CDIM);
    wconv16<<<(4*CDIM*CDIM + 255)/256, 256>>>(fc1_w, wfc1, 4*CDIM*CDIM);
    wconv16<<<(CDIM*4*CDIM + 255)/256, 256>>>(fc2_w, wfc2, CDIM*4*CDIM);

    im2col_h<<<(int)(((size_t)TKN*144 + 255)/256), 256>>>(x, colh);
    // conv + fused LN1: writes xt (fp32) + lnq (fp16)
    mma_gemm<3><<<dim3(1, MB), 256, SMEM_GEMM>>>(colh, wconv, proj_b, nullptr, nullptr,
                                                 ln1_w, ln1_b, xt, lnq, CDIM, KCONV);
    // qkv (fp16 out)
    mma_gemm<0><<<dim3(3, MB), 256, SMEM_GEMM>>>(lnq, wqkv, qkv_b, nullptr, nullptr,
                                                 nullptr, nullptr, nullptr, qkvh, 3*CDIM, CDIM);
    attn_kernel<<<dim3(NWTOT, NH), 64>>>(qkvh, biasp, aoh);
    // attn-proj + residual(xt) + fused LN2: writes t1 + lnq
    mma_gemm<4><<<dim3(1, MB), 256, SMEM_GEMM>>>(aoh, wap, apb, xt, nullptr,
                                                 ln2_w, ln2_b, t1, lnq, CDIM, CDIM);
    // fc1 + GELU -> fp16
    mma_gemm<2><<<dim3(4, MB), 256, SMEM_GEMM>>>(lnq, wfc1, fc1_b, nullptr, nullptr,
                                                 nullptr, nullptr, nullptr, m1h, 4*CDIM, CDIM);
    // fc2 + residual(t1) + shortcut(xt) -> t2
    mma_gemm<5><<<dim3(1, MB), 256, SMEM_GEMM>>>(m1h, wfc2, fc2_b, t1, xt,
                                                 nullptr, nullptr, t2, nullptr, CDIM, 4*CDIM);
    out_tr<<<dim3(L/32, CDIM/32, BATCH), dim3(32,8)>>>(t2, out);
}

// round 9
// speedup vs baseline: 3.1292x; 1.0248x over previous
#include <cuda_runtime.h>
#include <cuda_fp16.h>
#include <math.h>
#include <stdint.h>

// ---------------- problem constants ----------------
#define BATCH   8
#define CIN     64
#define CDIM    192
#define HDIM    112
#define WDIM    112
#define L       (HDIM*WDIM)          // 12544
#define TKN     (BATCH*L)            // 100352
#define WS      7
#define NWIN    49
#define NH      6
#define HD      32
#define NWTOT   2048
#define KCONV   576

typedef unsigned long long u64;

// ---------------- f32x2 helpers ----------------
#define FMA2(d,a,b)    asm("fma.rn.f32x2 %0, %1, %2, %0;" : "+l"(d) : "l"(a), "l"(b))
#define PACK2(d,x)     asm("mov.b64 %0, {%1, %1};" : "=l"(d) : "f"(x))
#define PACK2XY(d,x,y) asm("mov.b64 %0, {%1, %2};" : "=l"(d) : "f"(x), "f"(y))
#define UNPACK2(x,y,d) asm("mov.b64 {%0, %1}, %2;" : "=f"(x), "=f"(y) : "l"(d))

union F4U2 { float4 f; u64 u[2]; };

__device__ __forceinline__ uint32_t smem_u32(const void* p) {
    uint32_t a;
    asm("{ .reg .u64 t; cvta.to.shared.u64 t, %1; cvt.u32.u64 %0, t; }" : "=r"(a) : "l"(p));
    return a;
}

// ---------------- warp-MMA + cp.async primitives (base ISA) ----------------
#define LDMX4(r, addr) \
    asm volatile("ldmatrix.sync.aligned.m8n8.x4.shared.b16 {%0,%1,%2,%3}, [%4];" \
        : "=r"((r)[0]), "=r"((r)[1]), "=r"((r)[2]), "=r"((r)[3]) : "r"(addr))

#define MMA16816(c, a, b0, b1) \
    asm volatile("mma.sync.aligned.m16n8k16.row.col.f32.f16.f16.f32 " \
        "{%0,%1,%2,%3}, {%4,%5,%6,%7}, {%8,%9}, {%0,%1,%2,%3};" \
        : "+f"((c)[0]), "+f"((c)[1]), "+f"((c)[2]), "+f"((c)[3]) \
        : "r"((a)[0]), "r"((a)[1]), "r"((a)[2]), "r"((a)[3]), "r"(b0), "r"(b1))

#define CPA16(dst, src) \
    asm volatile("cp.async.ca.shared.global [%0], [%1], 16;" :: "r"(dst), "l"(src))
#define CPCOMMIT() asm volatile("cp.async.commit_group;" ::: "memory")
#define CPWAIT(n)  asm volatile("cp.async.wait_group %0;" :: "n"(n) : "memory")

// ---------------- scratch (static device) ----------------
__device__ __half g_col[(size_t)TKN*KCONV];     // conv A, fp16
__device__ __half g_ln [(size_t)TKN*CDIM];      // LN output, fp16
__device__ __half g_ao [(size_t)TKN*CDIM];      // attention out, fp16
__device__ __half g_m1 [(size_t)TKN*4*CDIM];    // fc1+GELU out, fp16
__device__ __half g_qkv[(size_t)TKN*3*CDIM];    // qkv, fp16
__device__ float g_xt [(size_t)TKN*CDIM];
__device__ float g_t1 [(size_t)TKN*CDIM];
__device__ float g_t2 [(size_t)TKN*CDIM];
__device__ float g_bias[NH*NWIN*NWIN];
// plain fp16 weights [N,K]
__device__ __half g_wconv[CDIM*KCONV];
__device__ __half g_wqkv [3*CDIM*CDIM];
__device__ __half g_wap  [CDIM*CDIM];
__device__ __half g_wfc1 [4*CDIM*CDIM];
__device__ __half g_wfc2 [CDIM*4*CDIM];

// ---------------- fp16 HMMA GEMM, BM=128 BN=192 BK=32, 4-stage cp.async ----------
// A: [M,K] fp16. B: [N,K] fp16.
// EPI: 0 bias->Cs(h) | 2 bias+GELU->Cs(h) | 3 bias->Cf + LN->Cs(h)
//      4 bias+res->Cf + LN->Cs(h)        | 5 bias+res+res2->Cf
#define AROWB  80
#define BROWB  80
#define ASTAGE 10240
#define BSTAGE 15360
#define STG    4
#define SMEM_GEMM (STG*(ASTAGE+BSTAGE))   // 102400
template<int EPI>
__global__ __launch_bounds__(256) void mma_gemm(
    const __half* __restrict__ A, const __half* __restrict__ B,
    const float* __restrict__ bias, const float* __restrict__ res,
    const float* __restrict__ res2, const float* __restrict__ lnw,
    const float* __restrict__ lnb,
    float* __restrict__ Cf, __half* __restrict__ Cs,
    int N, int K)
{
    extern __shared__ __align__(16) char dsm[];
    const uint32_t s0 = smem_u32(dsm);
    const int t = threadIdx.x, wid = t >> 5, lane = t & 31;
    const int n0 = blockIdx.x * 192, m0 = blockIdx.y * 128;
    const int wm = (wid >> 2) * 64, wn = (wid & 3) * 48;
    const int mat = lane >> 3, rr = lane & 7;
    const int kc = K >> 5;

    float acc[4][6][4];
    #pragma unroll
    for (int i = 0; i < 4; i++)
        #pragma unroll
        for (int j = 0; j < 6; j++)
            #pragma unroll
            for (int l = 0; l < 4; l++) acc[i][j][l] = 0.f;

    auto issue = [&](int c) {
        const int buf = c % STG;
        const uint32_t aS = s0 + buf*ASTAGE;
        const uint32_t bS = s0 + STG*ASTAGE + buf*BSTAGE;
        const int ac = c << 5;
        {   // A: 128 rows x 64B
            const int row = t >> 2, seg = t & 3;
            CPA16(aS + row*AROWB + seg*16,
                  A + (size_t)(m0 + row)*K + ac + seg*8);
            CPA16(aS + (row + 64)*AROWB + seg*16,
                  A + (size_t)(m0 + row + 64)*K + ac + seg*8);
        }
        {   // B: 192 rows x 64B = 768 x 16B
            #pragma unroll
            for (int j = 0; j < 3; j++) {
                const int idx = t + 256*j, row = idx >> 2, seg = idx & 3;
                CPA16(bS + row*BROWB + seg*16,
                      B + (size_t)(n0 + row)*K + ac + seg*8);
            }
        }
    };

    // prologue: 3 chunks ahead
    #pragma unroll
    for (int p = 0; p < 3; p++) {
        if (p < kc) issue(p);
        CPCOMMIT();
    }
    for (int c = 0; c < kc; c++) {
        CPWAIT(2);              // chunk c resident
        __syncthreads();        // all warps done with chunk c-1's buffer
        if (c + 3 < kc) issue(c + 3);
        CPCOMMIT();
        const int buf = c % STG;
        const uint32_t aB = s0 + buf*ASTAGE;
        const uint32_t bB = s0 + STG*ASTAGE + buf*BSTAGE;
        #pragma unroll
        for (int ks = 0; ks < 2; ks++) {
            const int kb = ks * 32;
            uint32_t afr[4][4];
            #pragma unroll
            for (int am = 0; am < 4; am++)
                LDMX4(afr[am], aB + (uint32_t)((wm + am*16 + (lane & 15))*AROWB)
                             + kb + ((lane >> 4) << 4));
            uint32_t bf[3][4];
            #pragma unroll
            for (int bn = 0; bn < 3; bn++)
                LDMX4(bf[bn], bB + (uint32_t)((wn + bn*16 + ((mat & 2) << 2) + rr)*BROWB)
                            + kb + ((mat & 1) << 4));
            #pragma unroll
            for (int am = 0; am < 4; am++)
                #pragma unroll
                for (int bn = 0; bn < 3; bn++) {
                    MMA16816(acc[am][bn*2],   afr[am], bf[bn][0], bf[bn][1]);
                    MMA16816(acc[am][bn*2+1], afr[am], bf[bn][2], bf[bn][3]);
                }
        }
    }
    __syncthreads();

    // ---- epilogue pass 1: bias (+residuals), back into acc ----
    float lsum[4][2], lsq[4][2];
    #pragma unroll
    for (int am = 0; am < 4; am++)
        #pragma unroll
        for (int h = 0; h < 2; h++) { lsum[am][h] = 0.f; lsq[am][h] = 0.f; }
    #pragma unroll
    for (int am = 0; am < 4; am++) {
        #pragma unroll
        for (int nf = 0; nf < 6; nf++) {
            const int nn = n0 + wn + nf*8 + ((lane & 3) << 1);
            const float b0 = bias[nn], b1 = bias[nn + 1];
            #pragma unroll
            for (int h = 0; h < 2; h++) {
                const int m = m0 + wm + am*16 + (lane >> 2) + h*8;
                float o0 = acc[am][nf][h*2]     + b0;
                float o1 = acc[am][nf][h*2 + 1] + b1;
                if (EPI == 4 || EPI == 5) {
                    float2 rv = *(const float2*)(res + (size_t)m*N + nn);
                    o0 += rv.x; o1 += rv.y;
                }
                if (EPI == 5) {
                    float2 rv = *(const float2*)(res2 + (size_t)m*N + nn);
                    o0 += rv.x; o1 += rv.y;
                }
                if (EPI == 2) {
                    o0 = 0.5f*o0*(1.0f + erff(o0*0.70710678118654752f));
                    o1 = 0.5f*o1*(1.0f + erff(o1*0.70710678118654752f));
                }
                acc[am][nf][h*2]     = o0;
                acc[am][nf][h*2 + 1] = o1;
                if (EPI == 3 || EPI == 4) {
                    lsum[am][h] += o0 + o1;
                    lsq[am][h]  += o0*o0 + o1*o1;
                }
            }
        }
    }

    float mu[4][2], rs[4][2];
    if (EPI == 3 || EPI == 4) {   // row LayerNorm (N==192: full row in CTA)
        float2* red = (float2*)dsm;
        #pragma unroll
        for (int am = 0; am < 4; am++)
            #pragma unroll
            for (int h = 0; h < 2; h++) {
                #pragma unroll
                for (int ox = 1; ox < 4; ox <<= 1) {
                    lsum[am][h] += __shfl_xor_sync(0xffffffffu, lsum[am][h], ox);
                    lsq[am][h]  += __shfl_xor_sync(0xffffffffu, lsq[am][h], ox);
                }
            }
        if ((lane & 3) == 0) {
            #pragma unroll
            for (int am = 0; am < 4; am++)
                #pragma unroll
                for (int h = 0; h < 2; h++) {
                    int row = wm + am*16 + (lane >> 2) + h*8;
                    red[row*4 + (wid & 3)] = make_float2(lsum[am][h], lsq[am][h]);
                }
        }
        __syncthreads();
        #pragma unroll
        for (int am = 0; am < 4; am++)
            #pragma unroll
            for (int h = 0; h < 2; h++) {
                int row = wm + am*16 + (lane >> 2) + h*8;
                float s = 0.f, q = 0.f;
                #pragma unroll
                for (int w = 0; w < 4; w++) {
                    float2 v = red[row*4 + w];
                    s += v.x; q += v.y;
                }
                float m_ = s * (1.f/192.f);
                float var = q * (1.f/192.f) - m_*m_;
                mu[am][h] = m_;
                rs[am][h] = rsqrtf(var + 1e-5f);
            }
    }

    // ---- epilogue pass 2: writes ----
    #pragma unroll
    for (int am = 0; am < 4; am++) {
        #pragma unroll
        for (int nf = 0; nf < 6; nf++) {
            const int nn = n0 + wn + nf*8 + ((lane & 3) << 1);
            #pragma unroll
            for (int h = 0; h < 2; h++) {
                const int m = m0 + wm + am*16 + (lane >> 2) + h*8;
                const float o0 = acc[am][nf][h*2], o1 = acc[am][nf][h*2 + 1];
                if (EPI == 5) {
                    *(float2*)(Cf + (size_t)m*N + nn) = make_float2(o0, o1);
                } else if (EPI == 0 || EPI == 2) {
                    *(__half2*)(Cs + (size_t)m*N + nn) =
                        __halves2half2(__float2half_rn(o0), __float2half_rn(o1));
                } else {   // EPI 3/4: raw -> Cf, LN -> Cs
                    *(float2*)(Cf + (size_t)m*N + nn) = make_float2(o0, o1);
                    float y0 = (o0 - mu[am][h])*rs[am][h]*lnw[nn]     + lnb[nn];
                    float y1 = (o1 - mu[am][h])*rs[am][h]*lnw[nn + 1] + lnb[nn + 1];
                    *(__half2*)(Cs + (size_t)m*N + nn) =
                        __halves2half2(__float2half_rn(y0), __float2half_rn(y1));
                }
            }
        }
    }
}

// ---------------- fused prep: im2col + 5x weight convert + rel-pos bias ----------
#define NB_IM 56448                     // TKN*144/256
#define W_C1 (CDIM*KCONV)               // 110592
#define W_C2 (W_C1 + 3*CDIM*CDIM)       // 221184
#define W_C3 (W_C2 + CDIM*CDIM)         // 258048
#define W_C4 (W_C3 + 4*CDIM*CDIM)       // 405504
#define W_C5 (W_C4 + CDIM*4*CDIM)       // 552960
#define NB_W 2160                       // 552960/256
#define NB_B 57
__global__ void prep_all(const float* __restrict__ x, __half* __restrict__ col,
                         const float* __restrict__ w0, __half* __restrict__ d0,
                         const float* __restrict__ w1, __half* __restrict__ d1,
                         const float* __restrict__ w2, __half* __restrict__ d2,
                         const float* __restrict__ w3, __half* __restrict__ d3,
                         const float* __restrict__ w4, __half* __restrict__ d4,
                         const float* __restrict__ tab, const int* __restrict__ idx,
                         float* __restrict__ biasout)
{
    const int bid = blockIdx.x;
    if (bid < NB_IM) {   // im2col (fp16)
        size_t i4 = (size_t)bid*256 + threadIdx.x;
        int m  = (int)(i4 / 144);
        int k0 = (int)(i4 % 144) * 4;
        int b = m / L, hw = m % L, h = hw / WDIM, w = hw % WDIM;
        __half v[4];
        #pragma unroll
        for (int u = 0; u < 4; u++) {
            int k = k0 + u, ci = k / 9, rq = k - ci*9, kh = rq / 3, kw = rq - kh*3;
            int ih = h + kh - 1, iw = w + kw - 1;
            float f = (ih >= 0 && ih < HDIM && iw >= 0 && iw < WDIM)
                    ? x[((size_t)(b*CIN + ci)*HDIM + ih)*WDIM + iw] : 0.f;
            v[u] = __float2half_rn(f);
        }
        *(uint2*)&col[(size_t)m*KCONV + k0] = *(uint2*)v;
    } else if (bid < NB_IM + NB_W) {   // weight converts
        int i = (bid - NB_IM)*256 + threadIdx.x;
        const float* s; __half* d; int off;
        if      (i < W_C1) { s = w0; d = d0; off = 0; }
        else if (i < W_C2) { s = w1; d = d1; off = W_C1; }
        else if (i < W_C3) { s = w2; d = d2; off = W_C2; }
        else if (i < W_C4) { s = w3; d = d3; off = W_C3; }
        else               { s = w4; d = d4; off = W_C4; }
        d[i - off] = __float2half_rn(s[i - off]);
    } else {   // rel-pos bias
        int i = (bid - NB_IM - NB_W)*256 + threadIdx.x;
        if (i < NH*NWIN*NWIN) {
            int h = i / (NWIN*NWIN), ij = i % (NWIN*NWIN);
            biasout[i] = tab[idx[ij]*NH + h];
        }
    }
}

// ---------------- window attention (fp16 qkv in, fp32 compute, fp16 out) ----------
__global__ __launch_bounds__(64) void attn_kernel(const __half* __restrict__ qkv,
                                                  const float* __restrict__ biasg,
                                                  __half* __restrict__ o)
{
    __shared__ float ks[NWIN*HD], vs[NWIN*HD];
    __shared__ float sc[NWIN*NWIN];
    __shared__ int toks[NWIN];
    const int t = threadIdx.x;
    const int wi = blockIdx.x, head = blockIdx.y;
    const int b = wi >> 8, r = wi & 255, wh = r >> 4, ww = r & 15;
    if (t < NWIN) toks[t] = b*L + (wh*WS + t/WS)*WDIM + (ww*WS + t%WS);
    __syncthreads();

    for (int idx = t; idx < NWIN*4; idx += 64) {
        int row = idx >> 2, seg = idx & 3;
        const __half2* kp = (const __half2*)(qkv + (size_t)toks[row]*(3*CDIM) + CDIM   + head*HD + seg*8);
        const __half2* vp = (const __half2*)(qkv + (size_t)toks[row]*(3*CDIM) + 2*CDIM + head*HD + seg*8);
        #pragma unroll
        for (int u = 0; u < 4; u++) {
            float2 kf = __half22float2(kp[u]);
            float2 vf = __half22float2(vp[u]);
            ks[row*HD + seg*8 + u*2]     = kf.x;
            ks[row*HD + seg*8 + u*2 + 1] = kf.y;
            vs[row*HD + seg*8 + u*2]     = vf.x;
            vs[row*HD + seg*8 + u*2 + 1] = vf.y;
        }
    }
    u64 q2[16];
    if (t < NWIN) {
        const __half2* qsrc = (const __half2*)(qkv + (size_t)toks[t]*(3*CDIM) + head*HD);
        const float s = 0.17677669529663687f;
        #pragma unroll
        for (int l = 0; l < 16; l++) {
            float2 f = __half22float2(qsrc[l]);
            PACK2XY(q2[l], f.x*s, f.y*s);
        }
    }
    __syncthreads();

    if (t < NWIN) {
        u64 z2; { float z = 0.f; PACK2(z2, z); }
        const float* bs = biasg + head*(NWIN*NWIN) + t*NWIN;
        float* row = &sc[t*NWIN];
        for (int j = 0; j < NWIN; j++) {
            const float4* kp = (const float4*)&ks[j*HD];
            u64 a2 = z2;
            #pragma unroll
            for (int d8 = 0; d8 < 8; d8++) {
                F4U2 kv; kv.f = kp[d8];
                FMA2(a2, q2[2*d8],     kv.u[0]);
                FMA2(a2, q2[2*d8 + 1], kv.u[1]);
            }
            float lo, hi; UNPACK2(lo, hi, a2);
            row[j] = lo + hi + bs[j];
        }
        float mx = -1e30f;
        for (int j = 0; j < NWIN; j++) mx = fmaxf(mx, row[j]);
        float s = 0.f;
        for (int j = 0; j < NWIN; j++) { float e = expf(row[j]-mx); row[j] = e; s += e; }
        float inv = 1.f/s;
        u64 acc2[16];
        #pragma unroll
        for (int d = 0; d < 16; d++) acc2[d] = z2;
        for (int j = 0; j < NWIN; j++) {
            const float4* vp = (const float4*)&vs[j*HD];
            u64 p2; float p = row[j]*inv; PACK2(p2, p);
            #pragma unroll
            for (int d8 = 0; d8 < 8; d8++) {
                F4U2 vv; vv.f = vp[d8];
                FMA2(acc2[2*d8],     p2, vv.u[0]);
                FMA2(acc2[2*d8 + 1], p2, vv.u[1]);
            }
        }
        __half2* ph = (__half2*)(o + (size_t)toks[t]*CDIM + head*HD);
        #pragma unroll
        for (int l = 0; l < 16; l++) {
            float x0, x1; UNPACK2(x0, x1, acc2[l]);
            ph[l] = __halves2half2(__float2half_rn(x0), __float2half_rn(x1));
        }
    }
}

// ---------------- final transpose: out[b,c,hw] = t2[tok,c] ----------------
__global__ void out_tr(const float* __restrict__ t2, float* __restrict__ out)
{
    __shared__ float tile[32][33];
    const int b   = blockIdx.z;
    const int hw0 = blockIdx.x * 32;
    const int c0  = blockIdx.y * 32;
    const int tx  = threadIdx.x, ty = threadIdx.y;   // (32, 8)
    #pragma unroll
    for (int r = 0; r < 4; r++) {
        int i = r*8 + ty;
        tile[i][tx] = t2[(size_t)(b*L + hw0 + i)*CDIM + c0 + tx];
    }
    __syncthreads();
    #pragma unroll
    for (int r = 0; r < 4; r++) {
        int cy = r*8 + ty;
        out[(size_t)(b*CDIM + c0 + cy)*L + hw0 + tx] = tile[tx][cy];
    }
}

// ---------------- launch ----------------
extern "C" void kernel_launch(void* const* d_in, const int* in_sizes, int n_in,
                              void* d_out, int out_size)
{
    const float* x        = (const float*)d_in[0];
    const float* proj_w   = (const float*)d_in[1];
    const float* proj_b   = (const float*)d_in[2];
    const float* ln1_w    = (const float*)d_in[3];
    const float* ln1_b    = (const float*)d_in[4];
    const float* qkv_w    = (const float*)d_in[5];
    const float* qkv_b    = (const float*)d_in[6];
    const float* rel_tab  = (const float*)d_in[7];
    const float* apw      = (const float*)d_in[8];
    const float* apb      = (const float*)d_in[9];
    const float* ln2_w    = (const float*)d_in[10];
    const float* ln2_b    = (const float*)d_in[11];
    const float* fc1_w    = (const float*)d_in[12];
    const float* fc1_b    = (const float*)d_in[13];
    const float* fc2_w    = (const float*)d_in[14];
    const float* fc2_b    = (const float*)d_in[15];
    const int*   rel_idx  = (const int*)d_in[16];
    float* out = (float*)d_out;

    __half *colh, *lnq, *aoh, *m1h, *qkvh, *wconv, *wqkv, *wap, *wfc1, *wfc2;
    float *xt, *t1, *t2, *biasp;
    cudaGetSymbolAddress((void**)&colh,  g_col);
    cudaGetSymbolAddress((void**)&lnq,   g_ln);
    cudaGetSymbolAddress((void**)&aoh,   g_ao);
    cudaGetSymbolAddress((void**)&m1h,   g_m1);
    cudaGetSymbolAddress((void**)&qkvh,  g_qkv);
    cudaGetSymbolAddress((void**)&xt,    g_xt);
    cudaGetSymbolAddress((void**)&t1,    g_t1);
    cudaGetSymbolAddress((void**)&t2,    g_t2);
    cudaGetSymbolAddress((void**)&biasp, g_bias);
    cudaGetSymbolAddress((void**)&wconv, g_wconv);
    cudaGetSymbolAddress((void**)&wqkv,  g_wqkv);
    cudaGetSymbolAddress((void**)&wap,   g_wap);
    cudaGetSymbolAddress((void**)&wfc1,  g_wfc1);
    cudaGetSymbolAddress((void**)&wfc2,  g_wfc2);

    cudaFuncSetAttribute(mma_gemm<0>, cudaFuncAttributeMaxDynamicSharedMemorySize, SMEM_GEMM);
    cudaFuncSetAttribute(mma_gemm<2>, cudaFuncAttributeMaxDynamicSharedMemorySize, SMEM_GEMM);
    cudaFuncSetAttribute(mma_gemm<3>, cudaFuncAttributeMaxDynamicSharedMemorySize, SMEM_GEMM);
    cudaFuncSetAttribute(mma_gemm<4>, cudaFuncAttributeMaxDynamicSharedMemorySize, SMEM_GEMM);
    cudaFuncSetAttribute(mma_gemm<5>, cudaFuncAttributeMaxDynamicSharedMemorySize, SMEM_GEMM);

    const int MB = TKN/128;   // 784

    // (0) all prep in one launch
    prep_all<<<NB_IM + NB_W + NB_B, 256>>>(x, colh,
                                           proj_w, wconv, qkv_w, wqkv, apw, wap,
                                           fc1_w, wfc1, fc2_w, wfc2,
                                           rel_tab, rel_idx, biasp);
    // (1) conv + fused LN1: writes xt (fp32) + lnq (fp16)
    mma_gemm<3><<<dim3(1, MB), 256, SMEM_GEMM>>>(colh, wconv, proj_b, nullptr, nullptr,
                                                 ln1_w, ln1_b, xt, lnq, CDIM, KCONV);
    // (2) qkv (fp16 out)
    mma_gemm<0><<<dim3(3, MB), 256, SMEM_GEMM>>>(lnq, wqkv, qkv_b, nullptr, nullptr,
                                                 nullptr, nullptr, nullptr, qkvh, 3*CDIM, CDIM);
    // (3) attention
    attn_kernel<<<dim3(NWTOT, NH), 64>>>(qkvh, biasp, aoh);
    // (4) attn-proj + residual(xt) + fused LN2: writes t1 + lnq
    mma_gemm<4><<<dim3(1, MB), 256, SMEM_GEMM>>>(aoh, wap, apb, xt, nullptr,
                                                 ln2_w, ln2_b, t1, lnq, CDIM, CDIM);
    // (5) fc1 + GELU -> fp16   <-- ncu -s 5 lands here
    mma_gemm<2><<<dim3(4, MB), 256, SMEM_GEMM>>>(lnq, wfc1, fc1_b, nullptr, nullptr,
                                                 nullptr, nullptr, nullptr, m1h, 4*CDIM, CDIM);
    // (6) fc2 + residual(t1) + shortcut(xt) -> t2
    mma_gemm<5><<<dim3(1, MB), 256, SMEM_GEMM>>>(m1h, wfc2, fc2_b, t1, xt,
                                                 nullptr, nullptr, t2, nullptr, CDIM, 4*CDIM);
    // (7) transpose
    out_tr<<<dim3(L/32, CDIM/32, BATCH), dim3(32,8)>>>(t2, out);
}

// round 10
// speedup vs baseline: 3.4218x; 1.0935x over previous
#include <cuda_runtime.h>
#include <cuda_fp16.h>
#include <math.h>
#include <stdint.h>

// ---------------- problem constants ----------------
#define BATCH   8
#define CIN     64
#define CDIM    192
#define HDIM    112
#define WDIM    112
#define L       (HDIM*WDIM)          // 12544
#define TKN     (BATCH*L)            // 100352
#define WS      7
#define NWIN    49
#define NH      6
#define HD      32
#define NWTOT   2048
#define KCONV   576

typedef unsigned long long u64;

__device__ __forceinline__ uint32_t smem_u32(const void* p) {
    uint32_t a;
    asm("{ .reg .u64 t; cvta.to.shared.u64 t, %1; cvt.u32.u64 %0, t; }" : "=r"(a) : "l"(p));
    return a;
}
__device__ __forceinline__ uint32_t packh2(float x, float y) {
    __half2 h = __floats2half2_rn(x, y);
    return *(uint32_t*)&h;
}

// ---------------- warp-MMA + cp.async primitives (base ISA) ----------------
#define LDMX4(r, addr) \
    asm volatile("ldmatrix.sync.aligned.m8n8.x4.shared.b16 {%0,%1,%2,%3}, [%4];" \
        : "=r"((r)[0]), "=r"((r)[1]), "=r"((r)[2]), "=r"((r)[3]) : "r"(addr))

#define MMA16816(c, a, b0, b1) \
    asm volatile("mma.sync.aligned.m16n8k16.row.col.f32.f16.f16.f32 " \
        "{%0,%1,%2,%3}, {%4,%5,%6,%7}, {%8,%9}, {%0,%1,%2,%3};" \
        : "+f"((c)[0]), "+f"((c)[1]), "+f"((c)[2]), "+f"((c)[3]) \
        : "r"((a)[0]), "r"((a)[1]), "r"((a)[2]), "r"((a)[3]), "r"(b0), "r"(b1))

#define MMA16816R(c, a0, a1, a2, a3, b0, b1) \
    asm volatile("mma.sync.aligned.m16n8k16.row.col.f32.f16.f16.f32 " \
        "{%0,%1,%2,%3}, {%4,%5,%6,%7}, {%8,%9}, {%0,%1,%2,%3};" \
        : "+f"((c)[0]), "+f"((c)[1]), "+f"((c)[2]), "+f"((c)[3]) \
        : "r"(a0), "r"(a1), "r"(a2), "r"(a3), "r"(b0), "r"(b1))

#define CPA16(dst, src) \
    asm volatile("cp.async.ca.shared.global [%0], [%1], 16;" :: "r"(dst), "l"(src))
#define CPCOMMIT() asm volatile("cp.async.commit_group;" ::: "memory")
#define CPWAIT(n)  asm volatile("cp.async.wait_group %0;" :: "n"(n) : "memory")

// ---------------- scratch (static device) ----------------
__device__ __half g_col[(size_t)TKN*KCONV];
__device__ __half g_ln [(size_t)TKN*CDIM];
__device__ __half g_ao [(size_t)TKN*CDIM];
__device__ __half g_m1 [(size_t)TKN*4*CDIM];
__device__ __half g_qkv[(size_t)TKN*3*CDIM];
__device__ float g_xt [(size_t)TKN*CDIM];
__device__ float g_t1 [(size_t)TKN*CDIM];
__device__ float g_t2 [(size_t)TKN*CDIM];
__device__ float g_bias[NH*64*56];              // padded: rows 64, cols 56 (-1e30 mask)
__device__ __half g_wconv[CDIM*KCONV];
__device__ __half g_wqkv [3*CDIM*CDIM];
__device__ __half g_wap  [CDIM*CDIM];
__device__ __half g_wfc1 [4*CDIM*CDIM];
__device__ __half g_wfc2 [CDIM*4*CDIM];

// ---------------- fp16 HMMA GEMM, BM=128 BN=192 BK=32, 4-stage cp.async ----------
#define AROWB  80
#define BROWB  80
#define ASTAGE 10240
#define BSTAGE 15360
#define STG    4
#define SMEM_GEMM (STG*(ASTAGE+BSTAGE))   // 102400
template<int EPI>
__global__ __launch_bounds__(256) void mma_gemm(
    const __half* __restrict__ A, const __half* __restrict__ B,
    const float* __restrict__ bias, const float* __restrict__ res,
    const float* __restrict__ res2, const float* __restrict__ lnw,
    const float* __restrict__ lnb,
    float* __restrict__ Cf, __half* __restrict__ Cs,
    int N, int K)
{
    extern __shared__ __align__(16) char dsm[];
    const uint32_t s0 = smem_u32(dsm);
    const int t = threadIdx.x, wid = t >> 5, lane = t & 31;
    const int n0 = blockIdx.x * 192, m0 = blockIdx.y * 128;
    const int wm = (wid >> 2) * 64, wn = (wid & 3) * 48;
    const int mat = lane >> 3, rr = lane & 7;
    const int kc = K >> 5;

    float acc[4][6][4];
    #pragma unroll
    for (int i = 0; i < 4; i++)
        #pragma unroll
        for (int j = 0; j < 6; j++)
            #pragma unroll
            for (int l = 0; l < 4; l++) acc[i][j][l] = 0.f;

    auto issue = [&](int c) {
        const int buf = c % STG;
        const uint32_t aS = s0 + buf*ASTAGE;
        const uint32_t bS = s0 + STG*ASTAGE + buf*BSTAGE;
        const int ac = c << 5;
        {
            const int row = t >> 2, seg = t & 3;
            CPA16(aS + row*AROWB + seg*16,
                  A + (size_t)(m0 + row)*K + ac + seg*8);
            CPA16(aS + (row + 64)*AROWB + seg*16,
                  A + (size_t)(m0 + row + 64)*K + ac + seg*8);
        }
        {
            #pragma unroll
            for (int j = 0; j < 3; j++) {
                const int idx = t + 256*j, row = idx >> 2, seg = idx & 3;
                CPA16(bS + row*BROWB + seg*16,
                      B + (size_t)(n0 + row)*K + ac + seg*8);
            }
        }
    };

    #pragma unroll
    for (int p = 0; p < 3; p++) {
        if (p < kc) issue(p);
        CPCOMMIT();
    }
    for (int c = 0; c < kc; c++) {
        CPWAIT(2);
        __syncthreads();
        if (c + 3 < kc) issue(c + 3);
        CPCOMMIT();
        const int buf = c % STG;
        const uint32_t aB = s0 + buf*ASTAGE;
        const uint32_t bB = s0 + STG*ASTAGE + buf*BSTAGE;
        #pragma unroll
        for (int ks = 0; ks < 2; ks++) {
            const int kb = ks * 32;
            uint32_t afr[4][4];
            #pragma unroll
            for (int am = 0; am < 4; am++)
                LDMX4(afr[am], aB + (uint32_t)((wm + am*16 + (lane & 15))*AROWB)
                             + kb + ((lane >> 4) << 4));
            uint32_t bf[3][4];
            #pragma unroll
            for (int bn = 0; bn < 3; bn++)
                LDMX4(bf[bn], bB + (uint32_t)((wn + bn*16 + ((mat & 2) << 2) + rr)*BROWB)
                            + kb + ((mat & 1) << 4));
            #pragma unroll
            for (int am = 0; am < 4; am++)
                #pragma unroll
                for (int bn = 0; bn < 3; bn++) {
                    MMA16816(acc[am][bn*2],   afr[am], bf[bn][0], bf[bn][1]);
                    MMA16816(acc[am][bn*2+1], afr[am], bf[bn][2], bf[bn][3]);
                }
        }
    }
    __syncthreads();

    float lsum[4][2], lsq[4][2];
    #pragma unroll
    for (int am = 0; am < 4; am++)
        #pragma unroll
        for (int h = 0; h < 2; h++) { lsum[am][h] = 0.f; lsq[am][h] = 0.f; }
    #pragma unroll
    for (int am = 0; am < 4; am++) {
        #pragma unroll
        for (int nf = 0; nf < 6; nf++) {
            const int nn = n0 + wn + nf*8 + ((lane & 3) << 1);
            const float b0 = bias[nn], b1 = bias[nn + 1];
            #pragma unroll
            for (int h = 0; h < 2; h++) {
                const int m = m0 + wm + am*16 + (lane >> 2) + h*8;
                float o0 = acc[am][nf][h*2]     + b0;
                float o1 = acc[am][nf][h*2 + 1] + b1;
                if (EPI == 4 || EPI == 5) {
                    float2 rv = *(const float2*)(res + (size_t)m*N + nn);
                    o0 += rv.x; o1 += rv.y;
                }
                if (EPI == 5) {
                    float2 rv = *(const float2*)(res2 + (size_t)m*N + nn);
                    o0 += rv.x; o1 += rv.y;
                }
                if (EPI == 2) {
                    o0 = 0.5f*o0*(1.0f + erff(o0*0.70710678118654752f));
                    o1 = 0.5f*o1*(1.0f + erff(o1*0.70710678118654752f));
                }
                acc[am][nf][h*2]     = o0;
                acc[am][nf][h*2 + 1] = o1;
                if (EPI == 3 || EPI == 4) {
                    lsum[am][h] += o0 + o1;
                    lsq[am][h]  += o0*o0 + o1*o1;
                }
            }
        }
    }

    float mu[4][2], rs[4][2];
    if (EPI == 3 || EPI == 4) {
        float2* red = (float2*)dsm;
        #pragma unroll
        for (int am = 0; am < 4; am++)
            #pragma unroll
            for (int h = 0; h < 2; h++) {
                #pragma unroll
                for (int ox = 1; ox < 4; ox <<= 1) {
                    lsum[am][h] += __shfl_xor_sync(0xffffffffu, lsum[am][h], ox);
                    lsq[am][h]  += __shfl_xor_sync(0xffffffffu, lsq[am][h], ox);
                }
            }
        if ((lane & 3) == 0) {
            #pragma unroll
            for (int am = 0; am < 4; am++)
                #pragma unroll
                for (int h = 0; h < 2; h++) {
                    int row = wm + am*16 + (lane >> 2) + h*8;
                    red[row*4 + (wid & 3)] = make_float2(lsum[am][h], lsq[am][h]);
                }
        }
        __syncthreads();
        #pragma unroll
        for (int am = 0; am < 4; am++)
            #pragma unroll
            for (int h = 0; h < 2; h++) {
                int row = wm + am*16 + (lane >> 2) + h*8;
                float s = 0.f, q = 0.f;
                #pragma unroll
                for (int w = 0; w < 4; w++) {
                    float2 v = red[row*4 + w];
                    s += v.x; q += v.y;
                }
                float m_ = s * (1.f/192.f);
                float var = q * (1.f/192.f) - m_*m_;
                mu[am][h] = m_;
                rs[am][h] = rsqrtf(var + 1e-5f);
            }
    }

    #pragma unroll
    for (int am = 0; am < 4; am++) {
        #pragma unroll
        for (int nf = 0; nf < 6; nf++) {
            const int nn = n0 + wn + nf*8 + ((lane & 3) << 1);
            #pragma unroll
            for (int h = 0; h < 2; h++) {
                const int m = m0 + wm + am*16 + (lane >> 2) + h*8;
                const float o0 = acc[am][nf][h*2], o1 = acc[am][nf][h*2 + 1];
                if (EPI == 5) {
                    *(float2*)(Cf + (size_t)m*N + nn) = make_float2(o0, o1);
                } else if (EPI == 0 || EPI == 2) {
                    *(__half2*)(Cs + (size_t)m*N + nn) =
                        __halves2half2(__float2half_rn(o0), __float2half_rn(o1));
                } else {
                    *(float2*)(Cf + (size_t)m*N + nn) = make_float2(o0, o1);
                    float y0 = (o0 - mu[am][h])*rs[am][h]*lnw[nn]     + lnb[nn];
                    float y1 = (o1 - mu[am][h])*rs[am][h]*lnw[nn + 1] + lnb[nn + 1];
                    *(__half2*)(Cs + (size_t)m*N + nn) =
                        __halves2half2(__float2half_rn(y0), __float2half_rn(y1));
                }
            }
        }
    }
}

// ---------------- fused prep: im2col + 5x weight convert + padded rel-pos bias ----
#define NB_IM 56448
#define W_C1 (CDIM*KCONV)
#define W_C2 (W_C1 + 3*CDIM*CDIM)
#define W_C3 (W_C2 + CDIM*CDIM)
#define W_C4 (W_C3 + 4*CDIM*CDIM)
#define W_C5 (W_C4 + CDIM*4*CDIM)       // 552960
#define NB_W 2160
#define NB_B 84                          // 6*64*56 = 21504 / 256
__global__ void prep_all(const float* __restrict__ x, __half* __restrict__ col,
                         const float* __restrict__ w0, __half* __restrict__ d0,
                         const float* __restrict__ w1, __half* __restrict__ d1,
                         const float* __restrict__ w2, __half* __restrict__ d2,
                         const float* __restrict__ w3, __half* __restrict__ d3,
                         const float* __restrict__ w4, __half* __restrict__ d4,
                         const float* __restrict__ tab, const int* __restrict__ idx,
                         float* __restrict__ biasout)
{
    const int bid = blockIdx.x;
    if (bid < NB_IM) {
        size_t i4 = (size_t)bid*256 + threadIdx.x;
        int m  = (int)(i4 / 144);
        int k0 = (int)(i4 % 144) * 4;
        int b = m / L, hw = m % L, h = hw / WDIM, w = hw % WDIM;
        __half v[4];
        #pragma unroll
        for (int u = 0; u < 4; u++) {
            int k = k0 + u, ci = k / 9, rq = k - ci*9, kh = rq / 3, kw = rq - kh*3;
            int ih = h + kh - 1, iw = w + kw - 1;
            float f = (ih >= 0 && ih < HDIM && iw >= 0 && iw < WDIM)
                    ? x[((size_t)(b*CIN + ci)*HDIM + ih)*WDIM + iw] : 0.f;
            v[u] = __float2half_rn(f);
        }
        *(uint2*)&col[(size_t)m*KCONV + k0] = *(uint2*)v;
    } else if (bid < NB_IM + NB_W) {
        int i = (bid - NB_IM)*256 + threadIdx.x;
        const float* s; __half* d; int off;
        if      (i < W_C1) { s = w0; d = d0; off = 0; }
        else if (i < W_C2) { s = w1; d = d1; off = W_C1; }
        else if (i < W_C3) { s = w2; d = d2; off = W_C2; }
        else if (i < W_C4) { s = w3; d = d3; off = W_C3; }
        else               { s = w4; d = d4; off = W_C4; }
        d[i - off] = __float2half_rn(s[i - off]);
    } else {
        int i = (bid - NB_IM - NB_W)*256 + threadIdx.x;
        if (i < NH*64*56) {
            int h = i / (64*56), rem = i % (64*56);
            int r = rem / 56, c = rem % 56;
            float v;
            if (c >= NWIN)      v = -1e30f;                 // col mask (softmax zero)
            else if (r >= NWIN) v = 0.f;                    // garbage rows, finite
            else                v = tab[idx[r*NWIN + c]*NH + h];
            biasout[i] = v;
        }
    }
}

// ---------------- HMMA window attention: 1 block/window, 12 warps ----------------
// Warp w: head = w>>1, row-half m0 = (w&1)*32.
// QS/KS: [64][200] halves (400B stride, ldmatrix conflict-free); VT: [192][72].
#define QROW 200
#define VROW 72
#define SM_QS  256
#define SM_KS  (SM_QS + 64*400)
#define SM_VT  (SM_KS + 64*400)
#define SMEM_ATT (SM_VT + 192*144)   // 79104
__global__ __launch_bounds__(384) void attn_mma(const __half* __restrict__ qkv,
                                                const float* __restrict__ biasp,
                                                __half* __restrict__ o)
{
    extern __shared__ __align__(16) char sm[];
    int* toks = (int*)sm;
    __half* QS = (__half*)(sm + SM_QS);
    __half* KS = (__half*)(sm + SM_KS);
    __half* VT = (__half*)(sm + SM_VT);
    const int t = threadIdx.x, wid = t >> 5, lane = t & 31;
    const int wi = blockIdx.x;
    const int b = wi >> 8, r_ = wi & 255, wh = r_ >> 4, ww = r_ & 15;
    if (t < NWIN) toks[t] = b*L + (wh*WS + t/WS)*WDIM + (ww*WS + t%WS);
    __syncthreads();

    // Q/K rows 0..48 (24 x 16B segments per row)
    for (int idx = t; idx < NWIN*24; idx += 384) {
        int p = idx / 24, seg = idx % 24;
        const uint4* src = (const uint4*)(qkv + (size_t)toks[p]*576);
        *(uint4*)(QS + p*QROW + seg*8) = src[seg];
        *(uint4*)(KS + p*QROW + seg*8) = src[seg + 24];
    }
    // V transposed: VT[d][p]
    for (int idx = t; idx < NWIN*96; idx += 384) {
        int p = idx / 96, cp = idx % 96;
        __half2 v = *(const __half2*)(qkv + (size_t)toks[p]*576 + 384 + cp*2);
        VT[(cp*2)*VROW + p]     = __low2half(v);
        VT[(cp*2 + 1)*VROW + p] = __high2half(v);
    }
    // zero pads: QS/KS rows 49..63; VT cols 49..63
    for (int idx = t; idx < 15*100; idx += 384) {
        int rr2 = idx / 100, c2 = idx % 100;
        *(uint32_t*)(QS + (NWIN + rr2)*QROW + c2*2) = 0;
        *(uint32_t*)(KS + (NWIN + rr2)*QROW + c2*2) = 0;
    }
    for (int idx = t; idx < 192*15; idx += 384) {
        int d = idx / 15, j = NWIN + idx % 15;
        VT[d*VROW + j] = __float2half(0.f);
    }
    __syncthreads();

    const int h = wid >> 1, m0 = (wid & 1)*32;
    const int mat = lane >> 3, rr = lane & 7;
    const uint32_t qsB = smem_u32(QS), ksB = smem_u32(KS), vtB = smem_u32(VT);

    // S = Q K^T  (2 m-frags x 7 n-frags)
    float accS[2][7][4];
    #pragma unroll
    for (int i = 0; i < 2; i++)
        #pragma unroll
        for (int j = 0; j < 7; j++)
            #pragma unroll
            for (int l = 0; l < 4; l++) accS[i][j][l] = 0.f;
    #pragma unroll
    for (int ks = 0; ks < 2; ks++) {
        const int kb = ks*32;
        uint32_t af[2][4];
        #pragma unroll
        for (int mf = 0; mf < 2; mf++)
            LDMX4(af[mf], qsB + (uint32_t)((m0 + mf*16 + (lane & 15))*400)
                        + h*64 + kb + ((lane >> 4) << 4));
        uint32_t bf[4][4];
        #pragma unroll
        for (int bn = 0; bn < 4; bn++)
            LDMX4(bf[bn], ksB + (uint32_t)((bn*16 + ((mat & 2) << 2) + rr)*400)
                        + h*64 + kb + ((mat & 1) << 4));
        #pragma unroll
        for (int mf = 0; mf < 2; mf++)
            #pragma unroll
            for (int nf = 0; nf < 7; nf++)
                MMA16816(accS[mf][nf], af[mf], bf[nf >> 1][(nf & 1)*2], bf[nf >> 1][(nf & 1)*2 + 1]);
    }

    // scale + bias + softmax on accumulator fragments
    const float scale = 0.17677669529663687f;
    #pragma unroll
    for (int mf = 0; mf < 2; mf++) {
        const int rl = m0 + mf*16 + (lane >> 2);
        const float* b0 = biasp + (h*64 + rl)*56;
        const float* b1 = biasp + (h*64 + rl + 8)*56;
        #pragma unroll
        for (int nf = 0; nf < 7; nf++) {
            const int c0 = nf*8 + (lane & 3)*2;
            float2 blo = *(const float2*)(b0 + c0);
            float2 bhi = *(const float2*)(b1 + c0);
            accS[mf][nf][0] = accS[mf][nf][0]*scale + blo.x;
            accS[mf][nf][1] = accS[mf][nf][1]*scale + blo.y;
            accS[mf][nf][2] = accS[mf][nf][2]*scale + bhi.x;
            accS[mf][nf][3] = accS[mf][nf][3]*scale + bhi.y;
        }
        float mlo = -1e30f, mhi = -1e30f;
        #pragma unroll
        for (int nf = 0; nf < 7; nf++) {
            mlo = fmaxf(mlo, fmaxf(accS[mf][nf][0], accS[mf][nf][1]));
            mhi = fmaxf(mhi, fmaxf(accS[mf][nf][2], accS[mf][nf][3]));
        }
        #pragma unroll
        for (int ox = 1; ox < 4; ox <<= 1) {
            mlo = fmaxf(mlo, __shfl_xor_sync(0xffffffffu, mlo, ox));
            mhi = fmaxf(mhi, __shfl_xor_sync(0xffffffffu, mhi, ox));
        }
        float slo = 0.f, shi = 0.f;
        #pragma unroll
        for (int nf = 0; nf < 7; nf++) {
            accS[mf][nf][0] = __expf(accS[mf][nf][0] - mlo);
            accS[mf][nf][1] = __expf(accS[mf][nf][1] - mlo);
            accS[mf][nf][2] = __expf(accS[mf][nf][2] - mhi);
            accS[mf][nf][3] = __expf(accS[mf][nf][3] - mhi);
            slo += accS[mf][nf][0] + accS[mf][nf][1];
            shi += accS[mf][nf][2] + accS[mf][nf][3];
        }
        #pragma unroll
        for (int ox = 1; ox < 4; ox <<= 1) {
            slo += __shfl_xor_sync(0xffffffffu, slo, ox);
            shi += __shfl_xor_sync(0xffffffffu, shi, ox);
        }
        const float ilo = 1.f/slo, ihi = 1.f/shi;
        #pragma unroll
        for (int nf = 0; nf < 7; nf++) {
            accS[mf][nf][0] *= ilo; accS[mf][nf][1] *= ilo;
            accS[mf][nf][2] *= ihi; accS[mf][nf][3] *= ihi;
        }
    }

    // O = P V  (P fragments reused directly as A operands)
    float accO[2][4][4];
    #pragma unroll
    for (int i = 0; i < 2; i++)
        #pragma unroll
        for (int j = 0; j < 4; j++)
            #pragma unroll
            for (int l = 0; l < 4; l++) accO[i][j][l] = 0.f;
    #pragma unroll
    for (int kt = 0; kt < 4; kt++) {
        uint32_t bf[2][4];
        #pragma unroll
        for (int bn = 0; bn < 2; bn++)
            LDMX4(bf[bn], vtB + (uint32_t)((h*32 + bn*16 + ((mat & 2) << 2) + rr)*144)
                        + kt*32 + ((mat & 1) << 4));
        #pragma unroll
        for (int mf = 0; mf < 2; mf++) {
            const int nf0 = 2*kt, nf1 = 2*kt + 1;
            uint32_t a0 = packh2(accS[mf][nf0][0], accS[mf][nf0][1]);
            uint32_t a1 = packh2(accS[mf][nf0][2], accS[mf][nf0][3]);
            uint32_t a2 = 0, a3 = 0;
            if (nf1 < 7) {
                a2 = packh2(accS[mf][nf1][0], accS[mf][nf1][1]);
                a3 = packh2(accS[mf][nf1][2], accS[mf][nf1][3]);
            }
            #pragma unroll
            for (int nf = 0; nf < 4; nf++)
                MMA16816R(accO[mf][nf], a0, a1, a2, a3,
                          bf[nf >> 1][(nf & 1)*2], bf[nf >> 1][(nf & 1)*2 + 1]);
        }
    }

    // store rows < 49
    #pragma unroll
    for (int mf = 0; mf < 2; mf++) {
        const int rl = m0 + mf*16 + (lane >> 2);
        #pragma unroll
        for (int nf = 0; nf < 4; nf++) {
            const int c = nf*8 + (lane & 3)*2;
            if (rl < NWIN)
                *(__half2*)(o + (size_t)toks[rl]*CDIM + h*HD + c) =
                    __halves2half2(__float2half_rn(accO[mf][nf][0]),
                                   __float2half_rn(accO[mf][nf][1]));
            if (rl + 8 < NWIN)
                *(__half2*)(o + (size_t)toks[rl + 8]*CDIM + h*HD + c) =
                    __halves2half2(__float2half_rn(accO[mf][nf][2]),
                                   __float2half_rn(accO[mf][nf][3]));
        }
    }
}

// ---------------- final transpose ----------------
__global__ void out_tr(const float* __restrict__ t2, float* __restrict__ out)
{
    __shared__ float tile[32][33];
    const int b   = blockIdx.z;
    const int hw0 = blockIdx.x * 32;
    const int c0  = blockIdx.y * 32;
    const int tx  = threadIdx.x, ty = threadIdx.y;
    #pragma unroll
    for (int r = 0; r < 4; r++) {
        int i = r*8 + ty;
        tile[i][tx] = t2[(size_t)(b*L + hw0 + i)*CDIM + c0 + tx];
    }
    __syncthreads();
    #pragma unroll
    for (int r = 0; r < 4; r++) {
        int cy = r*8 + ty;
        out[(size_t)(b*CDIM + c0 + cy)*L + hw0 + tx] = tile[tx][cy];
    }
}

// ---------------- launch ----------------
extern "C" void kernel_launch(void* const* d_in, const int* in_sizes, int n_in,
                              void* d_out, int out_size)
{
    const float* x        = (const float*)d_in[0];
    const float* proj_w   = (const float*)d_in[1];
    const float* proj_b   = (const float*)d_in[2];
    const float* ln1_w    = (const float*)d_in[3];
    const float* ln1_b    = (const float*)d_in[4];
    const float* qkv_w    = (const float*)d_in[5];
    const float* qkv_b    = (const float*)d_in[6];
    const float* rel_tab  = (const float*)d_in[7];
    const float* apw      = (const float*)d_in[8];
    const float* apb      = (const float*)d_in[9];
    const float* ln2_w    = (const float*)d_in[10];
    const float* ln2_b    = (const float*)d_in[11];
    const float* fc1_w    = (const float*)d_in[12];
    const float* fc1_b    = (const float*)d_in[13];
    const float* fc2_w    = (const float*)d_in[14];
    const float* fc2_b    = (const float*)d_in[15];
    const int*   rel_idx  = (const int*)d_in[16];
    float* out = (float*)d_out;

    __half *colh, *lnq, *aoh, *m1h, *qkvh, *wconv, *wqkv, *wap, *wfc1, *wfc2;
    float *xt, *t1, *t2, *biasp;
    cudaGetSymbolAddress((void**)&colh,  g_col);
    cudaGetSymbolAddress((void**)&lnq,   g_ln);
    cudaGetSymbolAddress((void**)&aoh,   g_ao);
    cudaGetSymbolAddress((void**)&m1h,   g_m1);
    cudaGetSymbolAddress((void**)&qkvh,  g_qkv);
    cudaGetSymbolAddress((void**)&xt,    g_xt);
    cudaGetSymbolAddress((void**)&t1,    g_t1);
    cudaGetSymbolAddress((void**)&t2,    g_t2);
    cudaGetSymbolAddress((void**)&biasp, g_bias);
    cudaGetSymbolAddress((void**)&wconv, g_wconv);
    cudaGetSymbolAddress((void**)&wqkv,  g_wqkv);
    cudaGetSymbolAddress((void**)&wap,   g_wap);
    cudaGetSymbolAddress((void**)&wfc1,  g_wfc1);
    cudaGetSymbolAddress((void**)&wfc2,  g_wfc2);

    cudaFuncSetAttribute(mma_gemm<0>, cudaFuncAttributeMaxDynamicSharedMemorySize, SMEM_GEMM);
    cudaFuncSetAttribute(mma_gemm<2>, cudaFuncAttributeMaxDynamicSharedMemorySize, SMEM_GEMM);
    cudaFuncSetAttribute(mma_gemm<3>, cudaFuncAttributeMaxDynamicSharedMemorySize, SMEM_GEMM);
    cudaFuncSetAttribute(mma_gemm<4>, cudaFuncAttributeMaxDynamicSharedMemorySize, SMEM_GEMM);
    cudaFuncSetAttribute(mma_gemm<5>, cudaFuncAttributeMaxDynamicSharedMemorySize, SMEM_GEMM);
    cudaFuncSetAttribute(attn_mma,    cudaFuncAttributeMaxDynamicSharedMemorySize, SMEM_ATT);

    const int MB = TKN/128;   // 784

    // (0) prep
    prep_all<<<NB_IM + NB_W + NB_B, 256>>>(x, colh,
                                           proj_w, wconv, qkv_w, wqkv, apw, wap,
                                           fc1_w, wfc1, fc2_w, wfc2,
                                           rel_tab, rel_idx, biasp);
    // (1) conv + fused LN1
    mma_gemm<3><<<dim3(1, MB), 256, SMEM_GEMM>>>(colh, wconv, proj_b, nullptr, nullptr,
                                                 ln1_w, ln1_b, xt, lnq, CDIM, KCONV);
    // (2) qkv
    mma_gemm<0><<<dim3(3, MB), 256, SMEM_GEMM>>>(lnq, wqkv, qkv_b, nullptr, nullptr,
                                                 nullptr, nullptr, nullptr, qkvh, 3*CDIM, CDIM);
    // (3) attention (HMMA)
    attn_mma<<<NWTOT, 384, SMEM_ATT>>>(qkvh, biasp, aoh);
    // (4) attn-proj + residual + LN2
    mma_gemm<4><<<dim3(1, MB), 256, SMEM_GEMM>>>(aoh, wap, apb, xt, nullptr,
                                                 ln2_w, ln2_b, t1, lnq, CDIM, CDIM);
    // (5) fc1 + GELU   <-- ncu -s 5 lands here
    mma_gemm<2><<<dim3(4, MB), 256, SMEM_GEMM>>>(lnq, wfc1, fc1_b, nullptr, nullptr,
                                                 nullptr, nullptr, nullptr, m1h, 4*CDIM, CDIM);
    // (6) fc2 + residual + shortcut
    mma_gemm<5><<<dim3(1, MB), 256, SMEM_GEMM>>>(m1h, wfc2, fc2_b, t1, xt,
                                                 nullptr, nullptr, t2, nullptr, CDIM, 4*CDIM);
    // (7) transpose
    out_tr<<<dim3(L/32, CDIM/32, BATCH), dim3(32,8)>>>(t2, out);
}

// round 11
// speedup vs baseline: 3.7136x; 1.0853x over previous
#include <cuda_runtime.h>
#include <cuda_fp16.h>
#include <math.h>
#include <stdint.h>

// ---------------- problem constants ----------------
#define BATCH   8
#define CIN     64
#define CDIM    192
#define HDIM    112
#define WDIM    112
#define L       (HDIM*WDIM)          // 12544
#define TKN     (BATCH*L)            // 100352
#define WS      7
#define NWIN    49
#define NH      6
#define HD      32
#define NWTOT   2048
#define KCONV   576

typedef unsigned long long u64;

__device__ __forceinline__ uint32_t smem_u32(const void* p) {
    uint32_t a;
    asm("{ .reg .u64 t; cvta.to.shared.u64 t, %1; cvt.u32.u64 %0, t; }" : "=r"(a) : "l"(p));
    return a;
}
__device__ __forceinline__ uint32_t packh2(float x, float y) {
    __half2 h = __floats2half2_rn(x, y);
    return *(uint32_t*)&h;
}

// ---------------- warp-MMA + cp.async primitives (base ISA) ----------------
#define LDMX4(r, addr) \
    asm volatile("ldmatrix.sync.aligned.m8n8.x4.shared.b16 {%0,%1,%2,%3}, [%4];" \
        : "=r"((r)[0]), "=r"((r)[1]), "=r"((r)[2]), "=r"((r)[3]) : "r"(addr))

#define MMA16816(c, a, b0, b1) \
    asm volatile("mma.sync.aligned.m16n8k16.row.col.f32.f16.f16.f32 " \
        "{%0,%1,%2,%3}, {%4,%5,%6,%7}, {%8,%9}, {%0,%1,%2,%3};" \
        : "+f"((c)[0]), "+f"((c)[1]), "+f"((c)[2]), "+f"((c)[3]) \
        : "r"((a)[0]), "r"((a)[1]), "r"((a)[2]), "r"((a)[3]), "r"(b0), "r"(b1))

#define MMA16816R(c, a0, a1, a2, a3, b0, b1) \
    asm volatile("mma.sync.aligned.m16n8k16.row.col.f32.f16.f16.f32 " \
        "{%0,%1,%2,%3}, {%4,%5,%6,%7}, {%8,%9}, {%0,%1,%2,%3};" \
        : "+f"((c)[0]), "+f"((c)[1]), "+f"((c)[2]), "+f"((c)[3]) \
        : "r"(a0), "r"(a1), "r"(a2), "r"(a3), "r"(b0), "r"(b1))

#define CPA16(dst, src) \
    asm volatile("cp.async.ca.shared.global [%0], [%1], 16;" :: "r"(dst), "l"(src))
#define CPCOMMIT() asm volatile("cp.async.commit_group;" ::: "memory")
#define CPWAIT(n)  asm volatile("cp.async.wait_group %0;" :: "n"(n) : "memory")

// ---------------- scratch (static device) ----------------
__device__ __half g_col[(size_t)TKN*KCONV];
__device__ __half g_ln [(size_t)TKN*CDIM];
__device__ __half g_ao [(size_t)TKN*CDIM];
__device__ __half g_m1 [(size_t)TKN*4*CDIM];
__device__ __half g_qkv[(size_t)TKN*3*CDIM];
__device__ float g_xt [(size_t)TKN*CDIM];
__device__ float g_t1 [(size_t)TKN*CDIM];
__device__ float g_t2 [(size_t)TKN*CDIM];
__device__ float g_bias[NH*64*56];
__device__ __half g_wconv[CDIM*KCONV];
__device__ __half g_wqkv [3*CDIM*CDIM];
__device__ __half g_wap  [CDIM*CDIM];
__device__ __half g_wfc1 [4*CDIM*CDIM];
__device__ __half g_wfc2 [CDIM*4*CDIM];

// ---------------- fp16 HMMA GEMM, BM=128 BN=192 BK=32, 512 thr (16 warps 4x4) ----
// Warp tile 32x48 -> 48 accum regs, ~100 total. 4-stage cp.async.
#define AROWB  80
#define BROWB  80
#define ASTAGE 10240
#define BSTAGE 15360
#define STG    4
#define SMEM_GEMM (STG*(ASTAGE+BSTAGE))   // 102400
template<int EPI>
__global__ __launch_bounds__(512) void mma_gemm(
    const __half* __restrict__ A, const __half* __restrict__ B,
    const float* __restrict__ bias, const float* __restrict__ res,
    const float* __restrict__ res2, const float* __restrict__ lnw,
    const float* __restrict__ lnb,
    float* __restrict__ Cf, __half* __restrict__ Cs,
    int N, int K)
{
    extern __shared__ __align__(16) char dsm[];
    const uint32_t s0 = smem_u32(dsm);
    const int t = threadIdx.x, wid = t >> 5, lane = t & 31;
    const int n0 = blockIdx.x * 192, m0 = blockIdx.y * 128;
    const int wm = (wid >> 2) * 32, wn = (wid & 3) * 48;
    const int mat = lane >> 3, rr = lane & 7;
    const int kc = K >> 5;

    float acc[2][6][4];
    #pragma unroll
    for (int i = 0; i < 2; i++)
        #pragma unroll
        for (int j = 0; j < 6; j++)
            #pragma unroll
            for (int l = 0; l < 4; l++) acc[i][j][l] = 0.f;

    auto issue = [&](int c) {
        const int buf = c % STG;
        const uint32_t aS = s0 + buf*ASTAGE;
        const uint32_t bS = s0 + STG*ASTAGE + buf*BSTAGE;
        const int ac = c << 5;
        {   // A: 128 rows x 4 segs = 512 x 16B, one per thread
            const int row = t >> 2, seg = t & 3;
            CPA16(aS + row*AROWB + seg*16,
                  A + (size_t)(m0 + row)*K + ac + seg*8);
        }
        {   // B: 192 rows x 4 segs = 768 x 16B
            const int row = t >> 2, seg = t & 3;
            CPA16(bS + row*BROWB + seg*16,
                  B + (size_t)(n0 + row)*K + ac + seg*8);
            if (t < 256) {
                const int idx = t + 512, row2 = idx >> 2, seg2 = idx & 3;
                CPA16(bS + row2*BROWB + seg2*16,
                      B + (size_t)(n0 + row2)*K + ac + seg2*8);
            }
        }
    };

    #pragma unroll
    for (int p = 0; p < 3; p++) {
        if (p < kc) issue(p);
        CPCOMMIT();
    }
    for (int c = 0; c < kc; c++) {
        CPWAIT(2);
        __syncthreads();
        if (c + 3 < kc) issue(c + 3);
        CPCOMMIT();
        const int buf = c % STG;
        const uint32_t aB = s0 + buf*ASTAGE;
        const uint32_t bB = s0 + STG*ASTAGE + buf*BSTAGE;
        #pragma unroll
        for (int ks = 0; ks < 2; ks++) {
            const int kb = ks * 32;
            uint32_t afr[2][4];
            #pragma unroll
            for (int am = 0; am < 2; am++)
                LDMX4(afr[am], aB + (uint32_t)((wm + am*16 + (lane & 15))*AROWB)
                             + kb + ((lane >> 4) << 4));
            uint32_t bf[3][4];
            #pragma unroll
            for (int bn = 0; bn < 3; bn++)
                LDMX4(bf[bn], bB + (uint32_t)((wn + bn*16 + ((mat & 2) << 2) + rr)*BROWB)
                            + kb + ((mat & 1) << 4));
            #pragma unroll
            for (int am = 0; am < 2; am++)
                #pragma unroll
                for (int bn = 0; bn < 3; bn++) {
                    MMA16816(acc[am][bn*2],   afr[am], bf[bn][0], bf[bn][1]);
                    MMA16816(acc[am][bn*2+1], afr[am], bf[bn][2], bf[bn][3]);
                }
        }
    }
    __syncthreads();

    // ---- epilogue pass 1 ----
    float lsum[2][2], lsq[2][2];
    #pragma unroll
    for (int am = 0; am < 2; am++)
        #pragma unroll
        for (int h = 0; h < 2; h++) { lsum[am][h] = 0.f; lsq[am][h] = 0.f; }
    #pragma unroll
    for (int am = 0; am < 2; am++) {
        #pragma unroll
        for (int nf = 0; nf < 6; nf++) {
            const int nn = n0 + wn + nf*8 + ((lane & 3) << 1);
            const float b0 = bias[nn], b1 = bias[nn + 1];
            #pragma unroll
            for (int h = 0; h < 2; h++) {
                const int m = m0 + wm + am*16 + (lane >> 2) + h*8;
                float o0 = acc[am][nf][h*2]     + b0;
                float o1 = acc[am][nf][h*2 + 1] + b1;
                if (EPI == 4 || EPI == 5) {
                    float2 rv = *(const float2*)(res + (size_t)m*N + nn);
                    o0 += rv.x; o1 += rv.y;
                }
                if (EPI == 5) {
                    float2 rv = *(const float2*)(res2 + (size_t)m*N + nn);
                    o0 += rv.x; o1 += rv.y;
                }
                if (EPI == 2) {
                    o0 = 0.5f*o0*(1.0f + erff(o0*0.70710678118654752f));
                    o1 = 0.5f*o1*(1.0f + erff(o1*0.70710678118654752f));
                }
                acc[am][nf][h*2]     = o0;
                acc[am][nf][h*2 + 1] = o1;
                if (EPI == 3 || EPI == 4) {
                    lsum[am][h] += o0 + o1;
                    lsq[am][h]  += o0*o0 + o1*o1;
                }
            }
        }
    }

    float mu[2][2], rs[2][2];
    if (EPI == 3 || EPI == 4) {   // row LayerNorm (N==192: full row in CTA)
        float2* red = (float2*)dsm;   // [128][4]
        #pragma unroll
        for (int am = 0; am < 2; am++)
            #pragma unroll
            for (int h = 0; h < 2; h++) {
                #pragma unroll
                for (int ox = 1; ox < 4; ox <<= 1) {
                    lsum[am][h] += __shfl_xor_sync(0xffffffffu, lsum[am][h], ox);
                    lsq[am][h]  += __shfl_xor_sync(0xffffffffu, lsq[am][h], ox);
                }
            }
        if ((lane & 3) == 0) {
            #pragma unroll
            for (int am = 0; am < 2; am++)
                #pragma unroll
                for (int h = 0; h < 2; h++) {
                    int row = wm + am*16 + (lane >> 2) + h*8;
                    red[row*4 + (wid & 3)] = make_float2(lsum[am][h], lsq[am][h]);
                }
        }
        __syncthreads();
        #pragma unroll
        for (int am = 0; am < 2; am++)
            #pragma unroll
            for (int h = 0; h < 2; h++) {
                int row = wm + am*16 + (lane >> 2) + h*8;
                float s = 0.f, q = 0.f;
                #pragma unroll
                for (int w = 0; w < 4; w++) {
                    float2 v = red[row*4 + w];
                    s += v.x; q += v.y;
                }
                float m_ = s * (1.f/192.f);
                float var = q * (1.f/192.f) - m_*m_;
                mu[am][h] = m_;
                rs[am][h] = rsqrtf(var + 1e-5f);
            }
    }

    // ---- epilogue pass 2 ----
    #pragma unroll
    for (int am = 0; am < 2; am++) {
        #pragma unroll
        for (int nf = 0; nf < 6; nf++) {
            const int nn = n0 + wn + nf*8 + ((lane & 3) << 1);
            #pragma unroll
            for (int h = 0; h < 2; h++) {
                const int m = m0 + wm + am*16 + (lane >> 2) + h*8;
                const float o0 = acc[am][nf][h*2], o1 = acc[am][nf][h*2 + 1];
                if (EPI == 5) {
                    *(float2*)(Cf + (size_t)m*N + nn) = make_float2(o0, o1);
                } else if (EPI == 0 || EPI == 2) {
                    *(__half2*)(Cs + (size_t)m*N + nn) =
                        __halves2half2(__float2half_rn(o0), __float2half_rn(o1));
                } else {
                    *(float2*)(Cf + (size_t)m*N + nn) = make_float2(o0, o1);
                    float y0 = (o0 - mu[am][h])*rs[am][h]*lnw[nn]     + lnb[nn];
                    float y1 = (o1 - mu[am][h])*rs[am][h]*lnw[nn + 1] + lnb[nn + 1];
                    *(__half2*)(Cs + (size_t)m*N + nn) =
                        __halves2half2(__float2half_rn(y0), __float2half_rn(y1));
                }
            }
        }
    }
}

// ---------------- fused prep: im2col + 5x weight convert + padded rel-pos bias ----
#define NB_IM 56448
#define W_C1 (CDIM*KCONV)
#define W_C2 (W_C1 + 3*CDIM*CDIM)
#define W_C3 (W_C2 + CDIM*CDIM)
#define W_C4 (W_C3 + 4*CDIM*CDIM)
#define W_C5 (W_C4 + CDIM*4*CDIM)
#define NB_W 2160
#define NB_B 84
__global__ void prep_all(const float* __restrict__ x, __half* __restrict__ col,
                         const float* __restrict__ w0, __half* __restrict__ d0,
                         const float* __restrict__ w1, __half* __restrict__ d1,
                         const float* __restrict__ w2, __half* __restrict__ d2,
                         const float* __restrict__ w3, __half* __restrict__ d3,
                         const float* __restrict__ w4, __half* __restrict__ d4,
                         const float* __restrict__ tab, const int* __restrict__ idx,
                         float* __restrict__ biasout)
{
    const int bid = blockIdx.x;
    if (bid < NB_IM) {
        size_t i4 = (size_t)bid*256 + threadIdx.x;
        int m  = (int)(i4 / 144);
        int k0 = (int)(i4 % 144) * 4;
        int b = m / L, hw = m % L, h = hw / WDIM, w = hw % WDIM;
        __half v[4];
        #pragma unroll
        for (int u = 0; u < 4; u++) {
            int k = k0 + u, ci = k / 9, rq = k - ci*9, kh = rq / 3, kw = rq - kh*3;
            int ih = h + kh - 1, iw = w + kw - 1;
            float f = (ih >= 0 && ih < HDIM && iw >= 0 && iw < WDIM)
                    ? x[((size_t)(b*CIN + ci)*HDIM + ih)*WDIM + iw] : 0.f;
            v[u] = __float2half_rn(f);
        }
        *(uint2*)&col[(size_t)m*KCONV + k0] = *(uint2*)v;
    } else if (bid < NB_IM + NB_W) {
        int i = (bid - NB_IM)*256 + threadIdx.x;
        const float* s; __half* d; int off;
        if      (i < W_C1) { s = w0; d = d0; off = 0; }
        else if (i < W_C2) { s = w1; d = d1; off = W_C1; }
        else if (i < W_C3) { s = w2; d = d2; off = W_C2; }
        else if (i < W_C4) { s = w3; d = d3; off = W_C3; }
        else               { s = w4; d = d4; off = W_C4; }
        d[i - off] = __float2half_rn(s[i - off]);
    } else {
        int i = (bid - NB_IM - NB_W)*256 + threadIdx.x;
        if (i < NH*64*56) {
            int h = i / (64*56), rem = i % (64*56);
            int r = rem / 56, c = rem % 56;
            float v;
            if (c >= NWIN)      v = -1e30f;
            else if (r >= NWIN) v = 0.f;
            else                v = tab[idx[r*NWIN + c]*NH + h];
            biasout[i] = v;
        }
    }
}

// ---------------- HMMA window attention: 1 block/window, 12 warps, 2 CTAs/SM ------
#define QROW 200
#define VROW 72
#define SM_QS  256
#define SM_KS  (SM_QS + 64*400)
#define SM_VT  (SM_KS + 64*400)
#define SMEM_ATT (SM_VT + 192*144)   // 79104
__global__ __launch_bounds__(384, 2) void attn_mma(const __half* __restrict__ qkv,
                                                   const float* __restrict__ biasp,
                                                   __half* __restrict__ o)
{
    extern __shared__ __align__(16) char sm[];
    int* toks = (int*)sm;
    __half* QS = (__half*)(sm + SM_QS);
    __half* KS = (__half*)(sm + SM_KS);
    __half* VT = (__half*)(sm + SM_VT);
    const int t = threadIdx.x, wid = t >> 5, lane = t & 31;
    const int wi = blockIdx.x;
    const int b = wi >> 8, r_ = wi & 255, wh = r_ >> 4, ww = r_ & 15;
    if (t < NWIN) toks[t] = b*L + (wh*WS + t/WS)*WDIM + (ww*WS + t%WS);
    __syncthreads();

    for (int idx = t; idx < NWIN*24; idx += 384) {
        int p = idx / 24, seg = idx % 24;
        const uint4* src = (const uint4*)(qkv + (size_t)toks[p]*576);
        *(uint4*)(QS + p*QROW + seg*8) = src[seg];
        *(uint4*)(KS + p*QROW + seg*8) = src[seg + 24];
    }
    for (int idx = t; idx < NWIN*96; idx += 384) {
        int p = idx / 96, cp = idx % 96;
        __half2 v = *(const __half2*)(qkv + (size_t)toks[p]*576 + 384 + cp*2);
        VT[(cp*2)*VROW + p]     = __low2half(v);
        VT[(cp*2 + 1)*VROW + p] = __high2half(v);
    }
    for (int idx = t; idx < 15*100; idx += 384) {
        int rr2 = idx / 100, c2 = idx % 100;
        *(uint32_t*)(QS + (NWIN + rr2)*QROW + c2*2) = 0;
        *(uint32_t*)(KS + (NWIN + rr2)*QROW + c2*2) = 0;
    }
    for (int idx = t; idx < 192*15; idx += 384) {
        int d = idx / 15, j = NWIN + idx % 15;
        VT[d*VROW + j] = __float2half(0.f);
    }
    __syncthreads();

    const int h = wid >> 1, m0 = (wid & 1)*32;
    const int mat = lane >> 3, rr = lane & 7;
    const uint32_t qsB = smem_u32(QS), ksB = smem_u32(KS), vtB = smem_u32(VT);

    float accS[2][7][4];
    #pragma unroll
    for (int i = 0; i < 2; i++)
        #pragma unroll
        for (int j = 0; j < 7; j++)
            #pragma unroll
            for (int l = 0; l < 4; l++) accS[i][j][l] = 0.f;
    #pragma unroll
    for (int ks = 0; ks < 2; ks++) {
        const int kb = ks*32;
        uint32_t af[2][4];
        #pragma unroll
        for (int mf = 0; mf < 2; mf++)
            LDMX4(af[mf], qsB + (uint32_t)((m0 + mf*16 + (lane & 15))*400)
                        + h*64 + kb + ((lane >> 4) << 4));
        uint32_t bf[4][4];
        #pragma unroll
        for (int bn = 0; bn < 4; bn++)
            LDMX4(bf[bn], ksB + (uint32_t)((bn*16 + ((mat & 2) << 2) + rr)*400)
                        + h*64 + kb + ((mat & 1) << 4));
        #pragma unroll
        for (int mf = 0; mf < 2; mf++)
            #pragma unroll
            for (int nf = 0; nf < 7; nf++)
                MMA16816(accS[mf][nf], af[mf], bf[nf >> 1][(nf & 1)*2], bf[nf >> 1][(nf & 1)*2 + 1]);
    }

    const float scale = 0.17677669529663687f;
    #pragma unroll
    for (int mf = 0; mf < 2; mf++) {
        const int rl = m0 + mf*16 + (lane >> 2);
        const float* b0 = biasp + (h*64 + rl)*56;
        const float* b1 = biasp + (h*64 + rl + 8)*56;
        #pragma unroll
        for (int nf = 0; nf < 7; nf++) {
            const int c0 = nf*8 + (lane & 3)*2;
            float2 blo = *(const float2*)(b0 + c0);
            float2 bhi = *(const float2*)(b1 + c0);
            accS[mf][nf][0] = accS[mf][nf][0]*scale + blo.x;
            accS[mf][nf][1] = accS[mf][nf][1]*scale + blo.y;
            accS[mf][nf][2] = accS[mf][nf][2]*scale + bhi.x;
            accS[mf][nf][3] = accS[mf][nf][3]*scale + bhi.y;
        }
        float mlo = -1e30f, mhi = -1e30f;
        #pragma unroll
        for (int nf = 0; nf < 7; nf++) {
            mlo = fmaxf(mlo, fmaxf(accS[mf][nf][0], accS[mf][nf][1]));
            mhi = fmaxf(mhi, fmaxf(accS[mf][nf][2], accS[mf][nf][3]));
        }
        #pragma unroll
        for (int ox = 1; ox < 4; ox <<= 1) {
            mlo = fmaxf(mlo, __shfl_xor_sync(0xffffffffu, mlo, ox));
            mhi = fmaxf(mhi, __shfl_xor_sync(0xffffffffu, mhi, ox));
        }
        float slo = 0.f, shi = 0.f;
        #pragma unroll
        for (int nf = 0; nf < 7; nf++) {
            accS[mf][nf][0] = __expf(accS[mf][nf][0] - mlo);
            accS[mf][nf][1] = __expf(accS[mf][nf][1] - mlo);
            accS[mf][nf][2] = __expf(accS[mf][nf][2] - mhi);
            accS[mf][nf][3] = __expf(accS[mf][nf][3] - mhi);
            slo += accS[mf][nf][0] + accS[mf][nf][1];
            shi += accS[mf][nf][2] + accS[mf][nf][3];
        }
        #pragma unroll
        for (int ox = 1; ox < 4; ox <<= 1) {
            slo += __shfl_xor_sync(0xffffffffu, slo, ox);
            shi += __shfl_xor_sync(0xffffffffu, shi, ox);
        }
        const float ilo = 1.f/slo, ihi = 1.f/shi;
        #pragma unroll
        for (int nf = 0; nf < 7; nf++) {
            accS[mf][nf][0] *= ilo; accS[mf][nf][1] *= ilo;
            accS[mf][nf][2] *= ihi; accS[mf][nf][3] *= ihi;
        }
    }

    float accO[2][4][4];
    #pragma unroll
    for (int i = 0; i < 2; i++)
        #pragma unroll
        for (int j = 0; j < 4; j++)
            #pragma unroll
            for (int l = 0; l < 4; l++) accO[i][j][l] = 0.f;
    #pragma unroll
    for (int kt = 0; kt < 4; kt++) {
        uint32_t bf[2][4];
        #pragma unroll
        for (int bn = 0; bn < 2; bn++)
            LDMX4(bf[bn], vtB + (uint32_t)((h*32 + bn*16 + ((mat & 2) << 2) + rr)*144)
                        + kt*32 + ((mat & 1) << 4));
        #pragma unroll
        for (int mf = 0; mf < 2; mf++) {
            const int nf0 = 2*kt, nf1 = 2*kt + 1;
            uint32_t a0 = packh2(accS[mf][nf0][0], accS[mf][nf0][1]);
            uint32_t a1 = packh2(accS[mf][nf0][2], accS[mf][nf0][3]);
            uint32_t a2 = 0, a3 = 0;
            if (nf1 < 7) {
                a2 = packh2(accS[mf][nf1][0], accS[mf][nf1][1]);
                a3 = packh2(accS[mf][nf1][2], accS[mf][nf1][3]);
            }
            #pragma unroll
            for (int nf = 0; nf < 4; nf++)
                MMA16816R(accO[mf][nf], a0, a1, a2, a3,
                          bf[nf >> 1][(nf & 1)*2], bf[nf >> 1][(nf & 1)*2 + 1]);
        }
    }

    #pragma unroll
    for (int mf = 0; mf < 2; mf++) {
        const int rl = m0 + mf*16 + (lane >> 2);
        #pragma unroll
        for (int nf = 0; nf < 4; nf++) {
            const int c = nf*8 + (lane & 3)*2;
            if (rl < NWIN)
                *(__half2*)(o + (size_t)toks[rl]*CDIM + h*HD + c) =
                    __halves2half2(__float2half_rn(accO[mf][nf][0]),
                                   __float2half_rn(accO[mf][nf][1]));
            if (rl + 8 < NWIN)
                *(__half2*)(o + (size_t)toks[rl + 8]*CDIM + h*HD + c) =
                    __halves2half2(__float2half_rn(accO[mf][nf][2]),
                                   __float2half_rn(accO[mf][nf][3]));
        }
    }
}

// ---------------- final transpose ----------------
__global__ void out_tr(const float* __restrict__ t2, float* __restrict__ out)
{
    __shared__ float tile[32][33];
    const int b   = blockIdx.z;
    const int hw0 = blockIdx.x * 32;
    const int c0  = blockIdx.y * 32;
    const int tx  = threadIdx.x, ty = threadIdx.y;
    #pragma unroll
    for (int r = 0; r < 4; r++) {
        int i = r*8 + ty;
        tile[i][tx] = t2[(size_t)(b*L + hw0 + i)*CDIM + c0 + tx];
    }
    __syncthreads();
    #pragma unroll
    for (int r = 0; r < 4; r++) {
        int cy = r*8 + ty;
        out[(size_t)(b*CDIM + c0 + cy)*L + hw0 + tx] = tile[tx][cy];
    }
}

// ---------------- launch ----------------
extern "C" void kernel_launch(void* const* d_in, const int* in_sizes, int n_in,
                              void* d_out, int out_size)
{
    const float* x        = (const float*)d_in[0];
    const float* proj_w   = (const float*)d_in[1];
    const float* proj_b   = (const float*)d_in[2];
    const float* ln1_w    = (const float*)d_in[3];
    const float* ln1_b    = (const float*)d_in[4];
    const float* qkv_w    = (const float*)d_in[5];
    const float* qkv_b    = (const float*)d_in[6];
    const float* rel_tab  = (const float*)d_in[7];
    const float* apw      = (const float*)d_in[8];
    const float* apb      = (const float*)d_in[9];
    const float* ln2_w    = (const float*)d_in[10];
    const float* ln2_b    = (const float*)d_in[11];
    const float* fc1_w    = (const float*)d_in[12];
    const float* fc1_b    = (const float*)d_in[13];
    const float* fc2_w    = (const float*)d_in[14];
    const float* fc2_b    = (const float*)d_in[15];
    const int*   rel_idx  = (const int*)d_in[16];
    float* out = (float*)d_out;

    __half *colh, *lnq, *aoh, *m1h, *qkvh, *wconv, *wqkv, *wap, *wfc1, *wfc2;
    float *xt, *t1, *t2, *biasp;
    cudaGetSymbolAddress((void**)&colh,  g_col);
    cudaGetSymbolAddress((void**)&lnq,   g_ln);
    cudaGetSymbolAddress((void**)&aoh,   g_ao);
    cudaGetSymbolAddress((void**)&m1h,   g_m1);
    cudaGetSymbolAddress((void**)&qkvh,  g_qkv);
    cudaGetSymbolAddress((void**)&xt,    g_xt);
    cudaGetSymbolAddress((void**)&t1,    g_t1);
    cudaGetSymbolAddress((void**)&t2,    g_t2);
    cudaGetSymbolAddress((void**)&biasp, g_bias);
    cudaGetSymbolAddress((void**)&wconv, g_wconv);
    cudaGetSymbolAddress((void**)&wqkv,  g_wqkv);
    cudaGetSymbolAddress((void**)&wap,   g_wap);
    cudaGetSymbolAddress((void**)&wfc1,  g_wfc1);
    cudaGetSymbolAddress((void**)&wfc2,  g_wfc2);

    cudaFuncSetAttribute(mma_gemm<0>, cudaFuncAttributeMaxDynamicSharedMemorySize, SMEM_GEMM);
    cudaFuncSetAttribute(mma_gemm<2>, cudaFuncAttributeMaxDynamicSharedMemorySize, SMEM_GEMM);
    cudaFuncSetAttribute(mma_gemm<3>, cudaFuncAttributeMaxDynamicSharedMemorySize, SMEM_GEMM);
    cudaFuncSetAttribute(mma_gemm<4>, cudaFuncAttributeMaxDynamicSharedMemorySize, SMEM_GEMM);
    cudaFuncSetAttribute(mma_gemm<5>, cudaFuncAttributeMaxDynamicSharedMemorySize, SMEM_GEMM);
    cudaFuncSetAttribute(attn_mma,    cudaFuncAttributeMaxDynamicSharedMemorySize, SMEM_ATT);

    const int MB = TKN/128;   // 784

    // (0) prep
    prep_all<<<NB_IM + NB_W + NB_B, 256>>>(x, colh,
                                           proj_w, wconv, qkv_w, wqkv, apw, wap,
                                           fc1_w, wfc1, fc2_w, wfc2,
                                           rel_tab, rel_idx, biasp);
    // (1) conv + fused LN1
    mma_gemm<3><<<dim3(1, MB), 512, SMEM_GEMM>>>(colh, wconv, proj_b, nullptr, nullptr,
                                                 ln1_w, ln1_b, xt, lnq, CDIM, KCONV);
    // (2) qkv
    mma_gemm<0><<<dim3(3, MB), 512, SMEM_GEMM>>>(lnq, wqkv, qkv_b, nullptr, nullptr,
                                                 nullptr, nullptr, nullptr, qkvh, 3*CDIM, CDIM);
    // (3) attention (HMMA)
    attn_mma<<<NWTOT, 384, SMEM_ATT>>>(qkvh, biasp, aoh);
    // (4) attn-proj + residual + LN2
    mma_gemm<4><<<dim3(1, MB), 512, SMEM_GEMM>>>(aoh, wap, apb, xt, nullptr,
                                                 ln2_w, ln2_b, t1, lnq, CDIM, CDIM);
    // (5) fc1 + GELU
    mma_gemm<2><<<dim3(4, MB), 512, SMEM_GEMM>>>(lnq, wfc1, fc1_b, nullptr, nullptr,
                                                 nullptr, nullptr, nullptr, m1h, 4*CDIM, CDIM);
    // (6) fc2 + residual + shortcut
    mma_gemm<5><<<dim3(1, MB), 512, SMEM_GEMM>>>(m1h, wfc2, fc2_b, t1, xt,
                                                 nullptr, nullptr, t2, nullptr, CDIM, 4*CDIM);
    // (7) transpose
    out_tr<<<dim3(L/32, CDIM/32, BATCH), dim3(32,8)>>>(t2, out);
}